// round 2
// baseline (speedup 1.0000x reference)
#include <cuda_runtime.h>
#include <math.h>

#define Bz 32
#define Cc 64
#define Nn 307
#define Tt 24
#define NT 7368            // Nn*Tt
#define O3 64
#define CO 192
#define BCN (Bz*Cc*Nn)     // 628736
#define BCNT (Bz*Cc*NT)    // 15089664

// ---------------- scratch (device globals; no runtime allocation) ----------------
__device__ float d_h[BCNT];
__device__ float d_bufA[BCNT];
__device__ float d_bufB[BCNT];
__device__ float d_tmp[Bz*Cc*Nn];      // also reused as [B,C,T]
__device__ float d_lhs[Bz*Nn*Tt];      // covers [B,C,T] and [B,T,N] too
__device__ float d_rhs[Bz*Nn*Tt];
__device__ float d_att[Bz*Nn*Nn];      // biggest att; reused per branch
__device__ float d_M[Bz*O3*O3];

// flags for k_mix
#define F_PERB 1
#define F_ADD  2
#define F_RELU 4
#define F_BIAS 8

// ---------------- LayerNorm over last dim (T=24), warp per row ----------------
__global__ void k_ln(const float* __restrict__ x, const float* __restrict__ g,
                     const float* __restrict__ be, float* __restrict__ h) {
    int warp = (blockIdx.x * blockDim.x + threadIdx.x) >> 5;
    int lane = threadIdx.x & 31;
    if (warp >= BCN) return;
    const float* row = x + (long)warp * Tt;
    float v = (lane < Tt) ? row[lane] : 0.f;
    float s = v, s2 = v * v;
    #pragma unroll
    for (int o = 16; o; o >>= 1) {
        s  += __shfl_xor_sync(~0u, s,  o);
        s2 += __shfl_xor_sync(~0u, s2, o);
    }
    float mu  = s * (1.f / Tt);
    float var = s2 * (1.f / Tt) - mu * mu;
    float inv = rsqrtf(var + 1e-5f);
    if (lane < Tt)
        h[(long)warp * Tt + lane] = (v - mu) * inv * g[lane] + be[lane];
}

// ---------------- dot over T with weight w[t] -> out[row], warp per row ----------------
__global__ void k_dot_t(const float* __restrict__ w, const float* __restrict__ h,
                        float* __restrict__ out) {
    int warp = (blockIdx.x * blockDim.x + threadIdx.x) >> 5;
    int lane = threadIdx.x & 31;
    if (warp >= BCN) return;
    float v = (lane < Tt) ? h[(long)warp * Tt + lane] * w[lane] : 0.f;
    #pragma unroll
    for (int o = 16; o; o >>= 1) v += __shfl_xor_sync(~0u, v, o);
    if (lane == 0) out[warp] = v;
}

// ---------------- c-branch lhs: out[b,c,t] = sum_n tmp[b,c,n]*W2[n,t] ----------------
__global__ void k_lhs_c(const float* __restrict__ W2, const float* __restrict__ tmp,
                        float* __restrict__ lhs) {
    int idx = blockIdx.x * blockDim.x + threadIdx.x;
    if (idx >= Bz * Cc * Tt) return;
    int t = idx % Tt, bc = idx / Tt;
    float acc = 0.f;
    const float* tp = tmp + bc * Nn;
    for (int n = 0; n < Nn; n++) acc += tp[n] * W2[n * Tt + t];
    lhs[idx] = acc;
}

// ---------------- reduce over n: out[b,c,t] = sum_n w[n]*h[b,c,n,t] ----------------
__global__ void k_reduce_n(const float* __restrict__ w, const float* __restrict__ h,
                           float* __restrict__ out) {
    int idx = blockIdx.x * blockDim.x + threadIdx.x;
    if (idx >= Bz * Cc * Tt) return;
    int t = idx % Tt, bc = idx / Tt;
    float acc = 0.f;
    const float* hp = h + (long)bc * Nn * Tt + t;
    for (int n = 0; n < Nn; n++) acc += w[n] * hp[n * Tt];
    out[idx] = acc;
}

// ---------------- reduce over c: out[b,n,t] = sum_c w[c]*h[b,c,n,t] ----------------
__global__ void k_reduce_c(const float* __restrict__ w, const float* __restrict__ h,
                           float* __restrict__ out) {
    int idx = blockIdx.x * blockDim.x + threadIdx.x;
    if (idx >= Bz * Nn * Tt) return;
    int t = idx % Tt, n = (idx / Tt) % Nn, b = idx / (Nn * Tt);
    float acc = 0.f;
    const float* hp = h + (((long)b * Cc) * Nn + n) * Tt + t;
    for (int c = 0; c < Cc; c++) acc += w[c] * hp[(long)c * Nn * Tt];
    out[idx] = acc;
}

// ---------------- channel attention scores + softmax over d (block per (b,c)) ----------------
__global__ void k_att_c(const float* __restrict__ lhs, const float* __restrict__ rhs,
                        float* __restrict__ att) {
    int bc = blockIdx.x;            // b*Cc + c
    int b  = bc / Cc;
    int d  = threadIdx.x;           // 0..63
    __shared__ float sh[O3];
    float dot = 0.f;
    const float* L = lhs + bc * Tt;
    const float* R = rhs + (b * Cc + d) * Tt;
    #pragma unroll
    for (int t = 0; t < Tt; t++) dot += L[t] * R[t];
    sh[d] = dot;
    __syncthreads();
    float m = -1e38f;
    for (int i = 0; i < O3; i++) m = fmaxf(m, sh[i]);
    float e = expf(dot - m);
    __syncthreads();
    sh[d] = e;
    __syncthreads();
    float s = 0.f;
    for (int i = 0; i < O3; i++) s += sh[i];
    att[bc * O3 + d] = e / s;
}

// ---------------- M[b,o,d] = sum_c cc_W[o,c]*att[b,c,d] ----------------
__global__ void k_M(const float* __restrict__ ccW, const float* __restrict__ att,
                    float* __restrict__ M) {
    int idx = blockIdx.x * blockDim.x + threadIdx.x;
    if (idx >= Bz * O3 * O3) return;
    int dd = idx % O3, o = (idx / O3) % O3, b = idx / (O3 * O3);
    float acc = 0.f;
    for (int c = 0; c < Cc; c++)
        acc += ccW[o * Cc + c] * att[(b * Cc + c) * O3 + dd];
    M[idx] = acc;
}

// ---------------- generic channel-mix: out[b,o,p] = sum_c A[o,c]*X[b,c,p] ----------------
__global__ void k_mix(const float* __restrict__ A, const float* __restrict__ X,
                      const float* __restrict__ bias, float* __restrict__ out,
                      int Ototal, int chOff, int flags) {
    int b = blockIdx.z, oc = blockIdx.y;
    int p = blockIdx.x * 256 + threadIdx.x;
    __shared__ float As[Cc][16];
    const float* Ab = A + ((flags & F_PERB) ? (long)b * Ototal * Cc : 0);
    for (int i = threadIdx.x; i < 16 * Cc; i += 256) {
        int o = i / Cc, c = i % Cc;
        As[c][o] = Ab[(oc * 16 + o) * Cc + c];
    }
    __syncthreads();
    if (p >= NT) return;
    const float* Xb = X + (long)b * Cc * NT + p;
    float acc[16];
    #pragma unroll
    for (int o = 0; o < 16; o++) acc[o] = 0.f;
    for (int c = 0; c < Cc; c++) {
        float xv = Xb[(long)c * NT];
        #pragma unroll
        for (int o = 0; o < 16; o++) acc[o] += As[c][o] * xv;
    }
    #pragma unroll
    for (int o = 0; o < 16; o++) {
        float r = acc[o];
        if (flags & F_BIAS) r += bias[oc * 16 + o];
        long oi = ((long)b * CO + chOff + oc * 16 + o) * NT + p;
        if (flags & F_ADD) r += out[oi];
        if (flags & F_RELU) r = fmaxf(r, 0.f);
        out[oi] = r;
    }
}

// ---------------- temporal lhs: out[b,t,n] = sum_c tmp[b,c,t]*W2[c,n] ----------------
__global__ void k_lhs_t(const float* __restrict__ W2, const float* __restrict__ tmp,
                        float* __restrict__ lhs) {
    int idx = blockIdx.x * blockDim.x + threadIdx.x;
    if (idx >= Bz * Tt * Nn) return;
    int n = idx % Nn, bt = idx / Nn;
    int t = bt % Tt, b = bt / Tt;
    float acc = 0.f;
    for (int c = 0; c < Cc; c++)
        acc += tmp[(b * Cc + c) * Tt + t] * W2[c * Nn + n];
    lhs[idx] = acc;
}

// ---------------- temporal attention: softmax over s of sum_n lhs[b,t,n]*rhs[b,n,s] ----------------
__global__ void k_att_t(const float* __restrict__ lhs, const float* __restrict__ rhs,
                        float* __restrict__ att) {
    int bt = blockIdx.x;            // b*Tt + t
    int b  = bt / Tt;
    int s  = threadIdx.x;           // 0..31, valid < 24
    float dot = -INFINITY;
    if (s < Tt) {
        dot = 0.f;
        const float* L = lhs + bt * Nn;
        const float* R = rhs + (long)b * Nn * Tt + s;
        for (int n = 0; n < Nn; n++) dot += L[n] * R[n * Tt];
    }
    float m = dot;
    #pragma unroll
    for (int o = 16; o; o >>= 1) m = fmaxf(m, __shfl_xor_sync(~0u, m, o));
    float e = (s < Tt) ? expf(dot - m) : 0.f;
    float su = e;
    #pragma unroll
    for (int o = 16; o; o >>= 1) su += __shfl_xor_sync(~0u, su, o);
    if (s < Tt) att[bt * Tt + s] = e / su;
}

// ---------------- apply temporal attention: out[b,c,n,t]=sum_s att[b,t,s]*h[b,c,n,s] ----------------
__global__ void k_apply_t(const float* __restrict__ att, const float* __restrict__ h,
                          float* __restrict__ out) {
    int warp = (blockIdx.x * blockDim.x + threadIdx.x) >> 5;
    int lane = threadIdx.x & 31;
    if (warp >= BCN) return;
    int b = warp / (Cc * Nn);
    long row = (long)warp * Tt;
    float hv = (lane < Tt) ? h[row + lane] : 0.f;
    float acc = 0.f;
    const float* arow = att + (b * Tt + (lane < Tt ? lane : 0)) * Tt;
    #pragma unroll
    for (int s = 0; s < Tt; s++) {
        float hs = __shfl_sync(~0u, hv, s);
        acc += arow[s] * hs;
    }
    if (lane < Tt) out[row + lane] = acc;
}

// ---------------- causal conv [1,2] dilation d, channels 64->64 ----------------
__global__ void k_conv(const float* __restrict__ W, const float* __restrict__ bias,
                       const float* __restrict__ X, float* __restrict__ Y,
                       int dil, int final_add) {
    int b = blockIdx.z, oc = blockIdx.y;
    int p = blockIdx.x * 256 + threadIdx.x;
    __shared__ float W0s[Cc][16], W1s[Cc][16];
    for (int i = threadIdx.x; i < 16 * Cc; i += 256) {
        int o = i / Cc, c = i % Cc;
        W0s[c][o] = W[((oc * 16 + o) * Cc + c) * 2 + 0];
        W1s[c][o] = W[((oc * 16 + o) * Cc + c) * 2 + 1];
    }
    __syncthreads();
    if (p >= NT) return;
    int t = p % Tt;
    bool sh = (t >= dil);
    const float* Xb = X + (long)b * Cc * NT + p;
    float acc[16];
    #pragma unroll
    for (int o = 0; o < 16; o++) acc[o] = 0.f;
    for (int c = 0; c < Cc; c++) {
        float xv = Xb[(long)c * NT];
        float xs = sh ? Xb[(long)c * NT - dil] : 0.f;
        #pragma unroll
        for (int o = 0; o < 16; o++)
            acc[o] += W1s[c][o] * xv + W0s[c][o] * xs;
    }
    #pragma unroll
    for (int o = 0; o < 16; o++) {
        float r = acc[o] + bias[oc * 16 + o];
        if (final_add) {
            long oi = ((long)b * CO + 64 + oc * 16 + o) * NT + p;
            Y[oi] = fmaxf(r + Y[oi], 0.f);
        } else {
            Y[((long)b * Cc + oc * 16 + o) * NT + p] = r;
        }
    }
}

// ---------------- graph lhs: out[b,n,t] = sum_c tmp[b,c,n]*W2[c,t] ----------------
__global__ void k_lhs_g(const float* __restrict__ W2, const float* __restrict__ tmp,
                        float* __restrict__ lhs) {
    int idx = blockIdx.x * blockDim.x + threadIdx.x;
    if (idx >= Bz * Nn * Tt) return;
    int t = idx % Tt, bn = idx / Tt;
    int n = bn % Nn, b = bn / Nn;
    float acc = 0.f;
    for (int c = 0; c < Cc; c++)
        acc += tmp[(b * Cc + c) * Nn + n] * W2[c * Tt + t];
    lhs[idx] = acc;
}

// ---------------- graph attention: masked scores + softmax over m ----------------
__global__ void k_att_g(const int* __restrict__ adj, const float* __restrict__ lhs,
                        const float* __restrict__ rhs, float* __restrict__ att) {
    int bn = blockIdx.x;
    int b = bn / Nn, n = bn % Nn;
    int tid = threadIdx.x;  // 128
    __shared__ float Ls[Tt];
    __shared__ float red[128];
    if (tid < Tt) Ls[tid] = lhs[bn * Tt + tid];
    __syncthreads();
    float sc[3];
    #pragma unroll
    for (int k = 0; k < 3; k++) {
        int m = tid + k * 128;
        sc[k] = -INFINITY;
        if (m < Nn) {
            float dot = 0.f;
            const float* R = rhs + ((long)b * Nn + m) * Tt;
            #pragma unroll
            for (int t = 0; t < Tt; t++) dot += Ls[t] * R[t];
            sc[k] = (adj[n * Nn + m] > 0) ? dot : -1e30f;
        }
    }
    float lm = fmaxf(fmaxf(sc[0], sc[1]), sc[2]);
    red[tid] = lm; __syncthreads();
    for (int st = 64; st; st >>= 1) {
        if (tid < st) red[tid] = fmaxf(red[tid], red[tid + st]);
        __syncthreads();
    }
    float M = red[0]; __syncthreads();
    float ls = 0.f;
    #pragma unroll
    for (int k = 0; k < 3; k++) {
        int m = tid + k * 128;
        if (m < Nn) { sc[k] = expf(sc[k] - M); ls += sc[k]; }
    }
    red[tid] = ls; __syncthreads();
    for (int st = 64; st; st >>= 1) {
        if (tid < st) red[tid] += red[tid + st];
        __syncthreads();
    }
    float S = red[0];
    #pragma unroll
    for (int k = 0; k < 3; k++) {
        int m = tid + k * 128;
        if (m < Nn) att[((long)b * Nn + n) * Nn + m] = sc[k] / S;
    }
}

// ---------------- graph apply: out[b,c,n,t]=sum_m att[b,n,m]*h[b,c,m,t] ----------------
__global__ void k_gapply(const float* __restrict__ att, const float* __restrict__ h,
                         float* __restrict__ out) {
    int b = blockIdx.z, c = blockIdx.y, n0 = blockIdx.x * 64;
    int tid = threadIdx.x;
    int t = tid % Tt, nr = tid / Tt;        // nr in 0..7
    __shared__ float h_s[32 * Tt];
    __shared__ float att_s[32][64];
    float acc[8];
    #pragma unroll
    for (int j = 0; j < 8; j++) acc[j] = 0.f;
    const float* Hbc  = h + ((long)(b * Cc + c) * Nn) * Tt;
    const float* Arow = att + (long)b * Nn * Nn;
    for (int m0 = 0; m0 < Nn; m0 += 32) {
        int mleft = Nn - m0; if (mleft > 32) mleft = 32;
        for (int i = tid; i < 32 * Tt; i += 192)
            h_s[i] = (i < mleft * Tt) ? Hbc[m0 * Tt + i] : 0.f;
        for (int i = tid; i < 2048; i += 192) {
            int nl = i >> 5, m = i & 31;
            int n = n0 + nl;
            att_s[m][nl] = (n < Nn && m < mleft) ? Arow[(long)n * Nn + m0 + m] : 0.f;
        }
        __syncthreads();
        #pragma unroll 4
        for (int m = 0; m < 32; m++) {
            float hv = h_s[m * Tt + t];
            const float4* ap = (const float4*)&att_s[m][nr * 8];
            float4 a0 = ap[0], a1 = ap[1];
            acc[0] += a0.x * hv; acc[1] += a0.y * hv;
            acc[2] += a0.z * hv; acc[3] += a0.w * hv;
            acc[4] += a1.x * hv; acc[5] += a1.y * hv;
            acc[6] += a1.z * hv; acc[7] += a1.w * hv;
        }
        __syncthreads();
    }
    #pragma unroll
    for (int j = 0; j < 8; j++) {
        int n = n0 + nr * 8 + j;
        if (n < Nn)
            out[((long)(b * Cc + c) * Nn + n) * Tt + t] = acc[j];
    }
}

// ================================= launch =================================
extern "C" void kernel_launch(void* const* d_in, const int* in_sizes, int n_in,
                              void* d_out, int out_size) {
    const float* x     = (const float*)d_in[0];
    const int*   adj   = (const int*)  d_in[1];
    const float* ln_g  = (const float*)d_in[2];
    const float* ln_b  = (const float*)d_in[3];
    const float* res_W = (const float*)d_in[4];
    const float* res_b = (const float*)d_in[5];
    const float* ca_W1 = (const float*)d_in[6];
    const float* ca_W2 = (const float*)d_in[7];
    const float* ca_W3 = (const float*)d_in[8];
    const float* cc_W  = (const float*)d_in[9];
    const float* cc_b  = (const float*)d_in[10];
    const float* ta_W1 = (const float*)d_in[11];
    const float* ta_W2 = (const float*)d_in[12];
    const float* ta_W3 = (const float*)d_in[13];
    const float* tc_W0 = (const float*)d_in[14];
    const float* tc_b0 = (const float*)d_in[15];
    const float* tc_W1 = (const float*)d_in[16];
    const float* tc_b1 = (const float*)d_in[17];
    const float* ga_W1 = (const float*)d_in[18];
    const float* ga_W2 = (const float*)d_in[19];
    const float* ga_W3 = (const float*)d_in[20];
    const float* g_W   = (const float*)d_in[21];
    float* out = (float*)d_out;

    // Resolve REAL device addresses of the scratch globals (host-side symbol
    // lookup; not an allocation, not a stream op — graph-capture safe).
    float *p_h, *p_bufA, *p_bufB, *p_tmp, *p_lhs, *p_rhs, *p_att, *p_M;
    cudaGetSymbolAddress((void**)&p_h,    d_h);
    cudaGetSymbolAddress((void**)&p_bufA, d_bufA);
    cudaGetSymbolAddress((void**)&p_bufB, d_bufB);
    cudaGetSymbolAddress((void**)&p_tmp,  d_tmp);
    cudaGetSymbolAddress((void**)&p_lhs,  d_lhs);
    cudaGetSymbolAddress((void**)&p_rhs,  d_rhs);
    cudaGetSymbolAddress((void**)&p_att,  d_att);
    cudaGetSymbolAddress((void**)&p_M,    d_M);

    int warpBlocks = (BCN + 7) / 8;          // 8 warps per 256-thread block
    const int pchunks = (NT + 255) / 256;    // 29

    // LayerNorm
    k_ln<<<warpBlocks, 256>>>(x, ln_g, ln_b, p_h);

    // Residual 1x1 conv -> out (all 192 channels)
    k_mix<<<dim3(pchunks, CO / 16, Bz), 256>>>(res_W, x, res_b, out, CO, 0, F_BIAS);

    // ---- C branch ----
    k_dot_t<<<warpBlocks, 256>>>(ca_W1, p_h, p_tmp);
    k_lhs_c<<<(Bz * Cc * Tt + 255) / 256, 256>>>(ca_W2, p_tmp, p_lhs);
    k_reduce_n<<<(Bz * Cc * Tt + 255) / 256, 256>>>(ca_W3, p_h, p_rhs);
    k_att_c<<<Bz * Cc, O3>>>(p_lhs, p_rhs, p_att);
    k_M<<<(Bz * O3 * O3 + 255) / 256, 256>>>(cc_W, p_att, p_M);
    k_mix<<<dim3(pchunks, O3 / 16, Bz), 256>>>(p_M, p_h, cc_b, out, O3, 0,
                                               F_PERB | F_ADD | F_RELU | F_BIAS);

    // ---- T branch ----
    k_reduce_n<<<(Bz * Cc * Tt + 255) / 256, 256>>>(ta_W1, p_h, p_tmp);  // tmp[b,c,t]
    k_lhs_t<<<(Bz * Tt * Nn + 255) / 256, 256>>>(ta_W2, p_tmp, p_lhs);
    k_reduce_c<<<(Bz * Nn * Tt + 255) / 256, 256>>>(ta_W3, p_h, p_rhs);
    k_att_t<<<Bz * Tt, 32>>>(p_lhs, p_rhs, p_att);
    k_apply_t<<<warpBlocks, 256>>>(p_att, p_h, p_bufA);
    k_conv<<<dim3(pchunks, O3 / 16, Bz), 256>>>(tc_W0, tc_b0, p_bufA, p_bufB, 1, 0);
    k_conv<<<dim3(pchunks, O3 / 16, Bz), 256>>>(tc_W1, tc_b1, p_bufB, out, 2, 1);

    // ---- G branch ----
    k_dot_t<<<warpBlocks, 256>>>(ga_W1, p_h, p_tmp);                     // tmp[b,c,n]
    k_lhs_g<<<(Bz * Nn * Tt + 255) / 256, 256>>>(ga_W2, p_tmp, p_lhs);
    k_reduce_c<<<(Bz * Nn * Tt + 255) / 256, 256>>>(ga_W3, p_h, p_rhs);
    k_att_g<<<Bz * Nn, 128>>>(adj, p_lhs, p_rhs, p_att);
    k_gapply<<<dim3((Nn + 63) / 64, Cc, Bz), 192>>>(p_att, p_h, p_bufA);
    k_mix<<<dim3(pchunks, O3 / 16, Bz), 256>>>(g_W, p_bufA, nullptr, out, O3, 128,
                                               F_ADD | F_RELU);

    (void)in_sizes; (void)n_in; (void)out_size;
}

// round 3
// speedup vs baseline: 1.6924x; 1.6924x over previous
#include <cuda_runtime.h>
#include <math.h>

#define Bz 32
#define Cc 64
#define Nn 307
#define Tt 24
#define NT 7368            // Nn*Tt
#define O3 64
#define CO 192
#define BCN (Bz*Cc*Nn)     // 628736
#define BCNT (Bz*Cc*NT)    // 15089664

typedef unsigned long long u64;

// ---------------- scratch (device globals; no runtime allocation) ----------------
__device__ float d_h[BCNT];
__device__ float d_bufA[BCNT];
__device__ float d_bufB[BCNT];
__device__ float d_tmp[Bz*Cc*Nn];       // reused as [B,C,T] too
__device__ float d_tmp_ca[Bz*Cc*Nn];
__device__ float d_tmp_ga[Bz*Cc*Nn];
__device__ float d_lhs[Bz*Nn*Tt];
__device__ float d_rhs[Bz*Nn*Tt];
__device__ float d_att[Bz*Nn*Nn];
__device__ float d_attT[Bz*Nn*Nn];
__device__ float d_M[Bz*O3*O3];

// flags for k_mix
#define F_PERB    1
#define F_ADD     2
#define F_RELU    4
#define F_BIAS    8
#define F_COMPACT 16

// -------- packed f32x2 helpers (FFMA2 only reachable via PTX) --------
__device__ __forceinline__ void fma2(u64& d, u64 a, u64 b) {
    asm("fma.rn.f32x2 %0, %1, %2, %0;" : "+l"(d) : "l"(a), "l"(b));
}
__device__ __forceinline__ u64 pk2(float x) {
    u64 r; unsigned xi = __float_as_uint(x);
    asm("mov.b64 %0, {%1, %1};" : "=l"(r) : "r"(xi));
    return r;
}
__device__ __forceinline__ float2 unpk(u64 v) {
    unsigned lo, hi;
    asm("mov.b64 {%0, %1}, %2;" : "=r"(lo), "=r"(hi) : "l"(v));
    return make_float2(__uint_as_float(lo), __uint_as_float(hi));
}

// ---------------- LayerNorm (+ fused ca/ga T-dots), warp per row ----------------
__global__ void k_ln(const float* __restrict__ x, const float* __restrict__ g,
                     const float* __restrict__ be,
                     const float* __restrict__ caW1, const float* __restrict__ gaW1,
                     float* __restrict__ h, float* __restrict__ tca,
                     float* __restrict__ tga) {
    int warp = (blockIdx.x * blockDim.x + threadIdx.x) >> 5;
    int lane = threadIdx.x & 31;
    if (warp >= BCN) return;
    const float* row = x + (long)warp * Tt;
    float v = (lane < Tt) ? row[lane] : 0.f;
    float s = v, s2 = v * v;
    #pragma unroll
    for (int o = 16; o; o >>= 1) {
        s  += __shfl_xor_sync(~0u, s,  o);
        s2 += __shfl_xor_sync(~0u, s2, o);
    }
    float mu  = s * (1.f / Tt);
    float var = s2 * (1.f / Tt) - mu * mu;
    float inv = rsqrtf(var + 1e-5f);
    float hv = 0.f;
    if (lane < Tt) {
        hv = (v - mu) * inv * g[lane] + be[lane];
        h[(long)warp * Tt + lane] = hv;
    }
    float dca = (lane < Tt) ? hv * caW1[lane] : 0.f;
    float dga = (lane < Tt) ? hv * gaW1[lane] : 0.f;
    #pragma unroll
    for (int o = 16; o; o >>= 1) {
        dca += __shfl_xor_sync(~0u, dca, o);
        dga += __shfl_xor_sync(~0u, dga, o);
    }
    if (lane == 0) { tca[warp] = dca; tga[warp] = dga; }
}

// ---------------- c-branch lhs: out[b,c,t] = sum_n tmp[b,c,n]*W2[n,t] ----------------
__global__ void k_lhs_c(const float* __restrict__ W2, const float* __restrict__ tmp,
                        float* __restrict__ lhs) {
    int idx = blockIdx.x * blockDim.x + threadIdx.x;
    if (idx >= Bz * Cc * Tt) return;
    int t = idx % Tt, bc = idx / Tt;
    float acc = 0.f;
    const float* tp = tmp + bc * Nn;
    for (int n = 0; n < Nn; n++) acc += tp[n] * W2[n * Tt + t];
    lhs[idx] = acc;
}

// ---------------- reduce over n: out[b,c,t] = sum_n w[n]*h[b,c,n,t] ----------------
__global__ void k_reduce_n(const float* __restrict__ w, const float* __restrict__ h,
                           float* __restrict__ out) {
    int idx = blockIdx.x * blockDim.x + threadIdx.x;
    if (idx >= Bz * Cc * Tt) return;
    int t = idx % Tt, bc = idx / Tt;
    float acc = 0.f;
    const float* hp = h + (long)bc * Nn * Tt + t;
    for (int n = 0; n < Nn; n++) acc += w[n] * hp[n * Tt];
    out[idx] = acc;
}

// ---------------- reduce over c: out[b,n,t] = sum_c w[c]*h[b,c,n,t] ----------------
__global__ void k_reduce_c(const float* __restrict__ w, const float* __restrict__ h,
                           float* __restrict__ out) {
    int idx = blockIdx.x * blockDim.x + threadIdx.x;
    if (idx >= Bz * Nn * Tt) return;
    int t = idx % Tt, n = (idx / Tt) % Nn, b = idx / (Nn * Tt);
    float acc = 0.f;
    const float* hp = h + (((long)b * Cc) * Nn + n) * Tt + t;
    for (int c = 0; c < Cc; c++) acc += w[c] * hp[(long)c * Nn * Tt];
    out[idx] = acc;
}

// ---------------- channel attention softmax (block per (b,c)) ----------------
__global__ void k_att_c(const float* __restrict__ lhs, const float* __restrict__ rhs,
                        float* __restrict__ att) {
    int bc = blockIdx.x;
    int b  = bc / Cc;
    int d  = threadIdx.x;
    __shared__ float sh[O3];
    float dot = 0.f;
    const float* L = lhs + bc * Tt;
    const float* R = rhs + (b * Cc + d) * Tt;
    #pragma unroll
    for (int t = 0; t < Tt; t++) dot += L[t] * R[t];
    sh[d] = dot;
    __syncthreads();
    float m = -1e38f;
    for (int i = 0; i < O3; i++) m = fmaxf(m, sh[i]);
    float e = expf(dot - m);
    __syncthreads();
    sh[d] = e;
    __syncthreads();
    float s = 0.f;
    for (int i = 0; i < O3; i++) s += sh[i];
    att[bc * O3 + d] = e / s;
}

// ---------------- M[b,o,d] = sum_c cc_W[o,c]*att[b,c,d] ----------------
__global__ void k_M(const float* __restrict__ ccW, const float* __restrict__ att,
                    float* __restrict__ M) {
    int idx = blockIdx.x * blockDim.x + threadIdx.x;
    if (idx >= Bz * O3 * O3) return;
    int dd = idx % O3, o = (idx / O3) % O3, b = idx / (O3 * O3);
    float acc = 0.f;
    for (int c = 0; c < Cc; c++)
        acc += ccW[o * Cc + c] * att[(b * Cc + c) * O3 + dd];
    M[idx] = acc;
}

// ---------------- channel-mix: out[b,o,p] = sum_c A[o,c]*X[b,c,p] ----------------
// 256 thr, each thread: 16 o x 4 p with packed f32x2 FMAs.
__global__ void __launch_bounds__(256, 2)
k_mix(const float* __restrict__ A, const float* __restrict__ X,
      const float* __restrict__ bias, float* __restrict__ out,
      int Ototal, int chOff, int flags) {
    int b = blockIdx.z, og = blockIdx.y;
    int p0 = blockIdx.x * 1024 + threadIdx.x * 4;
    __shared__ __align__(16) float As[Cc][16];     // [c][o], o contiguous
    const float* Ab = A + ((flags & F_PERB) ? (long)b * Ototal * Cc : 0);
    for (int i = threadIdx.x; i < 16 * Cc; i += 256) {
        int o = i & 15, c = i >> 4;
        As[c][o] = Ab[(og * 16 + o) * Cc + c];
    }
    __syncthreads();
    if (p0 >= NT) return;
    const float* Xb = X + (long)b * Cc * NT + p0;
    u64 acc2[8][4];
    #pragma unroll
    for (int i = 0; i < 8; i++)
        #pragma unroll
        for (int j = 0; j < 4; j++) acc2[i][j] = 0ull;
    for (int c = 0; c < Cc; c++) {
        float4 xv = *(const float4*)(Xb + (long)c * NT);
        u64 xp0 = pk2(xv.x), xp1 = pk2(xv.y), xp2 = pk2(xv.z), xp3 = pk2(xv.w);
        const u64* Arow = (const u64*)As[c];
        #pragma unroll
        for (int o2 = 0; o2 < 8; o2++) {
            u64 a2 = Arow[o2];
            fma2(acc2[o2][0], a2, xp0);
            fma2(acc2[o2][1], a2, xp1);
            fma2(acc2[o2][2], a2, xp2);
            fma2(acc2[o2][3], a2, xp3);
        }
    }
    #pragma unroll
    for (int o2 = 0; o2 < 8; o2++) {
        float2 v0 = unpk(acc2[o2][0]), v1 = unpk(acc2[o2][1]);
        float2 v2 = unpk(acc2[o2][2]), v3 = unpk(acc2[o2][3]);
        #pragma unroll
        for (int par = 0; par < 2; par++) {
            int o = og * 16 + o2 * 2 + par;
            float4 v = par ? make_float4(v0.y, v1.y, v2.y, v3.y)
                           : make_float4(v0.x, v1.x, v2.x, v3.x);
            if (flags & F_BIAS) {
                float bb = bias[o];
                v.x += bb; v.y += bb; v.z += bb; v.w += bb;
            }
            long oi = (flags & F_COMPACT)
                    ? ((long)b * Ototal + o) * NT + p0
                    : ((long)b * CO + chOff + o) * NT + p0;
            if (flags & F_ADD) {
                float4 r = *(const float4*)(out + oi);
                v.x += r.x; v.y += r.y; v.z += r.z; v.w += r.w;
            }
            if (flags & F_RELU) {
                v.x = fmaxf(v.x, 0.f); v.y = fmaxf(v.y, 0.f);
                v.z = fmaxf(v.z, 0.f); v.w = fmaxf(v.w, 0.f);
            }
            *(float4*)(out + oi) = v;
        }
    }
}

// ---------------- temporal lhs: out[b,t,n] = sum_c tmp[b,c,t]*W2[c,n] ----------------
__global__ void k_lhs_t(const float* __restrict__ W2, const float* __restrict__ tmp,
                        float* __restrict__ lhs) {
    int idx = blockIdx.x * blockDim.x + threadIdx.x;
    if (idx >= Bz * Tt * Nn) return;
    int n = idx % Nn, bt = idx / Nn;
    int t = bt % Tt, b = bt / Tt;
    float acc = 0.f;
    for (int c = 0; c < Cc; c++)
        acc += tmp[(b * Cc + c) * Tt + t] * W2[c * Nn + n];
    lhs[idx] = acc;
}

// ---------------- temporal attention softmax ----------------
__global__ void k_att_t(const float* __restrict__ lhs, const float* __restrict__ rhs,
                        float* __restrict__ att) {
    int bt = blockIdx.x;
    int b  = bt / Tt;
    int s  = threadIdx.x;
    float dot = -INFINITY;
    if (s < Tt) {
        dot = 0.f;
        const float* L = lhs + bt * Nn;
        const float* R = rhs + (long)b * Nn * Tt + s;
        for (int n = 0; n < Nn; n++) dot += L[n] * R[n * Tt];
    }
    float m = dot;
    #pragma unroll
    for (int o = 16; o; o >>= 1) m = fmaxf(m, __shfl_xor_sync(~0u, m, o));
    float e = (s < Tt) ? expf(dot - m) : 0.f;
    float su = e;
    #pragma unroll
    for (int o = 16; o; o >>= 1) su += __shfl_xor_sync(~0u, su, o);
    if (s < Tt) att[bt * Tt + s] = e / su;
}

// ---------------- apply temporal attention ----------------
__global__ void k_apply_t(const float* __restrict__ att, const float* __restrict__ h,
                          float* __restrict__ out) {
    int warp = (blockIdx.x * blockDim.x + threadIdx.x) >> 5;
    int lane = threadIdx.x & 31;
    if (warp >= BCN) return;
    int b = warp / (Cc * Nn);
    long row = (long)warp * Tt;
    float hv = (lane < Tt) ? h[row + lane] : 0.f;
    float acc = 0.f;
    const float* arow = att + (b * Tt + (lane < Tt ? lane : 0)) * Tt;
    #pragma unroll
    for (int s = 0; s < Tt; s++) {
        float hs = __shfl_sync(~0u, hv, s);
        acc += arow[s] * hs;
    }
    if (lane < Tt) out[row + lane] = acc;
}

// ---------------- causal conv [1,2], dilation DIL, 64->64, f32x2 ----------------
template<int DIL>
__global__ void __launch_bounds__(256, 2)
k_conv(const float* __restrict__ W, const float* __restrict__ bias,
       const float* __restrict__ X, float* __restrict__ Y, int final_add) {
    int b = blockIdx.z, og = blockIdx.y;
    int p0 = blockIdx.x * 1024 + threadIdx.x * 4;
    __shared__ __align__(16) float W0s[Cc][16], W1s[Cc][16];
    for (int i = threadIdx.x; i < 16 * Cc; i += 256) {
        int o = i & 15, c = i >> 4;
        W0s[c][o] = W[((og * 16 + o) * Cc + c) * 2 + 0];
        W1s[c][o] = W[((og * 16 + o) * Cc + c) * 2 + 1];
    }
    __syncthreads();
    if (p0 >= NT) return;
    int t0 = p0 % Tt;
    const float* Xb = X + (long)b * Cc * NT + p0;
    u64 acc2[8][4];
    #pragma unroll
    for (int i = 0; i < 8; i++)
        #pragma unroll
        for (int j = 0; j < 4; j++) acc2[i][j] = 0ull;
    for (int c = 0; c < Cc; c++) {
        const float* Xc = Xb + (long)c * NT;
        float4 cur = *(const float4*)Xc;
        float4 prv = make_float4(0.f, 0.f, 0.f, 0.f);
        if (t0 > 0) prv = *(const float4*)(Xc - 4);
        float s0, s1, s2, s3;
        if (DIL == 1) {
            s0 = (t0 > 0) ? prv.w : 0.f; s1 = cur.x; s2 = cur.y; s3 = cur.z;
        } else {
            s0 = (t0 > 0) ? prv.z : 0.f; s1 = (t0 > 0) ? prv.w : 0.f;
            s2 = cur.x; s3 = cur.y;
        }
        u64 xc0 = pk2(cur.x), xc1 = pk2(cur.y), xc2 = pk2(cur.z), xc3 = pk2(cur.w);
        u64 xs0 = pk2(s0), xs1 = pk2(s1), xs2 = pk2(s2), xs3 = pk2(s3);
        const u64* W1r = (const u64*)W1s[c];
        const u64* W0r = (const u64*)W0s[c];
        #pragma unroll
        for (int o2 = 0; o2 < 8; o2++) {
            u64 a1 = W1r[o2], a0 = W0r[o2];
            fma2(acc2[o2][0], a1, xc0); fma2(acc2[o2][0], a0, xs0);
            fma2(acc2[o2][1], a1, xc1); fma2(acc2[o2][1], a0, xs1);
            fma2(acc2[o2][2], a1, xc2); fma2(acc2[o2][2], a0, xs2);
            fma2(acc2[o2][3], a1, xc3); fma2(acc2[o2][3], a0, xs3);
        }
    }
    #pragma unroll
    for (int o2 = 0; o2 < 8; o2++) {
        float2 v0 = unpk(acc2[o2][0]), v1 = unpk(acc2[o2][1]);
        float2 v2 = unpk(acc2[o2][2]), v3 = unpk(acc2[o2][3]);
        #pragma unroll
        for (int par = 0; par < 2; par++) {
            int o = og * 16 + o2 * 2 + par;
            float4 v = par ? make_float4(v0.y, v1.y, v2.y, v3.y)
                           : make_float4(v0.x, v1.x, v2.x, v3.x);
            float bb = bias[o];
            v.x += bb; v.y += bb; v.z += bb; v.w += bb;
            if (final_add) {
                long oi = ((long)b * CO + 64 + o) * NT + p0;
                float4 r = *(const float4*)(Y + oi);
                v.x = fmaxf(v.x + r.x, 0.f); v.y = fmaxf(v.y + r.y, 0.f);
                v.z = fmaxf(v.z + r.z, 0.f); v.w = fmaxf(v.w + r.w, 0.f);
                *(float4*)(Y + oi) = v;
            } else {
                *(float4*)(Y + ((long)b * Cc + o) * NT + p0) = v;
            }
        }
    }
}

// ---------------- graph lhs: out[b,n,t] = sum_c tmp[b,c,n]*W2[c,t] ----------------
__global__ void k_lhs_g(const float* __restrict__ W2, const float* __restrict__ tmp,
                        float* __restrict__ lhs) {
    int idx = blockIdx.x * blockDim.x + threadIdx.x;
    if (idx >= Bz * Nn * Tt) return;
    int t = idx % Tt, bn = idx / Tt;
    int n = bn % Nn, b = bn / Nn;
    float acc = 0.f;
    for (int c = 0; c < Cc; c++)
        acc += tmp[(b * Cc + c) * Nn + n] * W2[c * Tt + t];
    lhs[idx] = acc;
}

// ---------------- graph attention softmax (block per (b,n)) ----------------
__global__ void k_att_g(const int* __restrict__ adj, const float* __restrict__ lhs,
                        const float* __restrict__ rhs, float* __restrict__ att) {
    int bn = blockIdx.x;
    int b = bn / Nn, n = bn % Nn;
    int tid = threadIdx.x;  // 128
    __shared__ float Ls[Tt];
    __shared__ float red[128];
    if (tid < Tt) Ls[tid] = lhs[bn * Tt + tid];
    __syncthreads();
    float sc[3];
    #pragma unroll
    for (int k = 0; k < 3; k++) {
        int m = tid + k * 128;
        sc[k] = -INFINITY;
        if (m < Nn) {
            float dot = 0.f;
            const float* R = rhs + ((long)b * Nn + m) * Tt;
            #pragma unroll
            for (int t = 0; t < Tt; t++) dot += Ls[t] * R[t];
            sc[k] = (adj[n * Nn + m] > 0) ? dot : -1e30f;
        }
    }
    float lm = fmaxf(fmaxf(sc[0], sc[1]), sc[2]);
    red[tid] = lm; __syncthreads();
    for (int st = 64; st; st >>= 1) {
        if (tid < st) red[tid] = fmaxf(red[tid], red[tid + st]);
        __syncthreads();
    }
    float M = red[0]; __syncthreads();
    float ls = 0.f;
    #pragma unroll
    for (int k = 0; k < 3; k++) {
        int m = tid + k * 128;
        if (m < Nn) { sc[k] = expf(sc[k] - M); ls += sc[k]; }
    }
    red[tid] = ls; __syncthreads();
    for (int st = 64; st; st >>= 1) {
        if (tid < st) red[tid] += red[tid + st];
        __syncthreads();
    }
    float S = red[0];
    #pragma unroll
    for (int k = 0; k < 3; k++) {
        int m = tid + k * 128;
        if (m < Nn) att[((long)b * Nn + n) * Nn + m] = sc[k] / S;
    }
}

// ---------------- transpose att per b: attT[b,m,n] = att[b,n,m] ----------------
__global__ void k_transA(const float* __restrict__ att, float* __restrict__ attT) {
    __shared__ float tile[32][33];
    int b = blockIdx.z;
    int x0 = blockIdx.x * 32, y0 = blockIdx.y * 32;
    const float* A = att + (long)b * Nn * Nn;
    float* AT = attT + (long)b * Nn * Nn;
    int tx = threadIdx.x, ty = threadIdx.y;  // 32 x 8
    #pragma unroll
    for (int i = 0; i < 4; i++) {
        int y = y0 + ty + i * 8, x = x0 + tx;
        if (y < Nn && x < Nn) tile[ty + i * 8][tx] = A[(long)y * Nn + x];
    }
    __syncthreads();
    #pragma unroll
    for (int i = 0; i < 4; i++) {
        int y = x0 + ty + i * 8, x = y0 + tx;     // transposed coords
        if (y < Nn && x < Nn) AT[(long)y * Nn + x] = tile[tx][ty + i * 8];
    }
}

// ---------------- graph apply GEMM + fused residual/relu epilogue ----------------
// out[b,128+c,n,t] = relu( sum_m attT[b,m,n]*gh[b,c,m,t] + out[b,128+c,n,t] )
// block: b, n-tile 64, c-group of 4. 256 thr: tx=cols (c_local,t0), ty=rows.
#define GH_MS 26              // mk stride (floats)
#define GH_CS (16*GH_MS + 8)  // 424, c_local stride

__global__ void k_gapply(const float* __restrict__ attT, const float* __restrict__ gh,
                         float* __restrict__ out) {
    int b = blockIdx.z;
    int n0 = blockIdx.x * 64;
    int cbase = blockIdx.y * 4;
    int tid = threadIdx.x;
    int tx = tid & 15, ty = tid >> 4;
    int cl_t = tx >> 2;
    int t0 = (tx & 3) * 6;
    __shared__ __align__(16) float att_s[16][64];
    __shared__ __align__(16) float gh_s[4 * GH_CS];
    u64 acc2[4][3];
    #pragma unroll
    for (int i = 0; i < 4; i++)
        #pragma unroll
        for (int j = 0; j < 3; j++) acc2[i][j] = 0ull;

    const float* ATb = attT + (long)b * Nn * Nn;
    const float* GHb = gh + ((long)b * Cc + cbase) * (long)Nn * Tt;

    for (int m0 = 0; m0 < Nn; m0 += 16) {
        #pragma unroll
        for (int i = tid; i < 1024; i += 256) {
            int mk = i >> 6, nl = i & 63;
            float v = 0.f;
            if (m0 + mk < Nn && n0 + nl < Nn) v = ATb[(long)(m0 + mk) * Nn + n0 + nl];
            att_s[mk][((nl & 15) << 2) | (nl >> 4)] = v;
        }
        #pragma unroll
        for (int i = tid; i < 1536; i += 256) {
            int cl = i / 384, r = i % 384, mk = r / 24, t = r % 24;
            float v = 0.f;
            if (m0 + mk < Nn) v = GHb[((long)cl * Nn + m0 + mk) * Tt + t];
            gh_s[cl * GH_CS + mk * GH_MS + t] = v;
        }
        __syncthreads();
        #pragma unroll
        for (int mk = 0; mk < 16; mk++) {
            float4 av = *(const float4*)&att_s[mk][ty << 2];
            u64 a0 = pk2(av.x), a1 = pk2(av.y), a2 = pk2(av.z), a3 = pk2(av.w);
            const u64* gp = (const u64*)&gh_s[cl_t * GH_CS + mk * GH_MS + t0];
            u64 g0 = gp[0], g1 = gp[1], g2 = gp[2];
            fma2(acc2[0][0], a0, g0); fma2(acc2[0][1], a0, g1); fma2(acc2[0][2], a0, g2);
            fma2(acc2[1][0], a1, g0); fma2(acc2[1][1], a1, g1); fma2(acc2[1][2], a1, g2);
            fma2(acc2[2][0], a2, g0); fma2(acc2[2][1], a2, g1); fma2(acc2[2][2], a2, g2);
            fma2(acc2[3][0], a3, g0); fma2(acc2[3][1], a3, g1); fma2(acc2[3][2], a3, g2);
        }
        __syncthreads();
    }
    int ch = 128 + cbase + cl_t;
    #pragma unroll
    for (int i = 0; i < 4; i++) {
        int n = n0 + ty + 16 * i;
        if (n >= Nn) continue;
        long base = ((long)b * CO + ch) * NT + n * Tt + t0;
        #pragma unroll
        for (int j = 0; j < 3; j++) {
            float2 v = unpk(acc2[i][j]);
            float2 r = *(const float2*)(out + base + j * 2);
            v.x = fmaxf(v.x + r.x, 0.f);
            v.y = fmaxf(v.y + r.y, 0.f);
            *(float2*)(out + base + j * 2) = v;
        }
    }
}

// ================================= launch =================================
extern "C" void kernel_launch(void* const* d_in, const int* in_sizes, int n_in,
                              void* d_out, int out_size) {
    const float* x     = (const float*)d_in[0];
    const int*   adj   = (const int*)  d_in[1];
    const float* ln_g  = (const float*)d_in[2];
    const float* ln_b  = (const float*)d_in[3];
    const float* res_W = (const float*)d_in[4];
    const float* res_b = (const float*)d_in[5];
    const float* ca_W1 = (const float*)d_in[6];
    const float* ca_W2 = (const float*)d_in[7];
    const float* ca_W3 = (const float*)d_in[8];
    const float* cc_W  = (const float*)d_in[9];
    const float* cc_b  = (const float*)d_in[10];
    const float* ta_W1 = (const float*)d_in[11];
    const float* ta_W2 = (const float*)d_in[12];
    const float* ta_W3 = (const float*)d_in[13];
    const float* tc_W0 = (const float*)d_in[14];
    const float* tc_b0 = (const float*)d_in[15];
    const float* tc_W1 = (const float*)d_in[16];
    const float* tc_b1 = (const float*)d_in[17];
    const float* ga_W1 = (const float*)d_in[18];
    const float* ga_W2 = (const float*)d_in[19];
    const float* ga_W3 = (const float*)d_in[20];
    const float* g_W   = (const float*)d_in[21];
    float* out = (float*)d_out;

    float *p_h, *p_bufA, *p_bufB, *p_tmp, *p_tca, *p_tga, *p_lhs, *p_rhs,
          *p_att, *p_attT, *p_M;
    cudaGetSymbolAddress((void**)&p_h,    d_h);
    cudaGetSymbolAddress((void**)&p_bufA, d_bufA);
    cudaGetSymbolAddress((void**)&p_bufB, d_bufB);
    cudaGetSymbolAddress((void**)&p_tmp,  d_tmp);
    cudaGetSymbolAddress((void**)&p_tca,  d_tmp_ca);
    cudaGetSymbolAddress((void**)&p_tga,  d_tmp_ga);
    cudaGetSymbolAddress((void**)&p_lhs,  d_lhs);
    cudaGetSymbolAddress((void**)&p_rhs,  d_rhs);
    cudaGetSymbolAddress((void**)&p_att,  d_att);
    cudaGetSymbolAddress((void**)&p_attT, d_attT);
    cudaGetSymbolAddress((void**)&p_M,    d_M);

    int warpBlocks = (BCN + 7) / 8;
    const int PX = 8;   // 8*1024 >= NT

    // LayerNorm + fused ca/ga T-dots
    k_ln<<<warpBlocks, 256>>>(x, ln_g, ln_b, ca_W1, ga_W1, p_h, p_tca, p_tga);

    // Residual 1x1 conv -> out (all 192 channels)
    k_mix<<<dim3(PX, CO / 16, Bz), 256>>>(res_W, x, res_b, out, CO, 0, F_BIAS);

    // ---- C branch ----
    k_lhs_c<<<(Bz * Cc * Tt + 255) / 256, 256>>>(ca_W2, p_tca, p_lhs);
    k_reduce_n<<<(Bz * Cc * Tt + 255) / 256, 256>>>(ca_W3, p_h, p_rhs);
    k_att_c<<<Bz * Cc, O3>>>(p_lhs, p_rhs, p_att);
    k_M<<<(Bz * O3 * O3 + 255) / 256, 256>>>(cc_W, p_att, p_M);
    k_mix<<<dim3(PX, O3 / 16, Bz), 256>>>(p_M, p_h, cc_b, out, O3, 0,
                                          F_PERB | F_ADD | F_RELU | F_BIAS);

    // ---- T branch ----
    k_reduce_n<<<(Bz * Cc * Tt + 255) / 256, 256>>>(ta_W1, p_h, p_tmp);
    k_lhs_t<<<(Bz * Tt * Nn + 255) / 256, 256>>>(ta_W2, p_tmp, p_lhs);
    k_reduce_c<<<(Bz * Nn * Tt + 255) / 256, 256>>>(ta_W3, p_h, p_rhs);
    k_att_t<<<Bz * Tt, 32>>>(p_lhs, p_rhs, p_att);
    k_apply_t<<<warpBlocks, 256>>>(p_att, p_h, p_bufA);
    k_conv<1><<<dim3(PX, O3 / 16, Bz), 256>>>(tc_W0, tc_b0, p_bufA, p_bufB, 0);
    k_conv<2><<<dim3(PX, O3 / 16, Bz), 256>>>(tc_W1, tc_b1, p_bufB, out, 1);

    // ---- G branch ----
    k_lhs_g<<<(Bz * Nn * Tt + 255) / 256, 256>>>(ga_W2, p_tga, p_lhs);
    k_reduce_c<<<(Bz * Nn * Tt + 255) / 256, 256>>>(ga_W3, p_h, p_rhs);
    k_att_g<<<Bz * Nn, 128>>>(adj, p_lhs, p_rhs, p_att);
    k_transA<<<dim3(10, 10, Bz), dim3(32, 8)>>>(p_att, p_attT);
    // gh = g_W @ h  (compact [b,64,N,T] into bufB; bufB free after conv chain)
    k_mix<<<dim3(PX, O3 / 16, Bz), 256>>>(g_W, p_h, nullptr, p_bufB, O3, 0, F_COMPACT);
    k_gapply<<<dim3((Nn + 63) / 64, 16, Bz), 256>>>(p_attT, p_bufB, out);

    (void)in_sizes; (void)n_in; (void)out_size;
}

// round 4
// speedup vs baseline: 2.0092x; 1.1872x over previous
#include <cuda_runtime.h>
#include <math.h>

#define Bz 32
#define Cc 64
#define Nn 307
#define Tt 24
#define NT 7368            // Nn*Tt
#define O3 64
#define CO 192
#define BCN (Bz*Cc*Nn)     // 628736
#define BCNT (Bz*Cc*NT)    // 15089664

typedef unsigned long long u64;

// ---------------- scratch (device globals; referenced directly in device code) ----------------
__device__ float d_h[BCNT];
__device__ float d_bufA[BCNT];
__device__ float d_bufB[BCNT];
__device__ float d_tca[Bz*Cc*Nn];
__device__ float d_tga[Bz*Cc*Nn];
__device__ float d_lhs_c[Bz*Cc*Tt];
__device__ float d_rhs_c[Bz*Cc*Tt];
__device__ float d_tmp_t[Bz*Cc*Tt];
__device__ float d_lhs_t[Bz*Tt*Nn];
__device__ float d_rhs_t[Bz*Nn*Tt];
__device__ float d_lhs_g[Bz*Nn*Tt];
__device__ float d_rhs_g[Bz*Nn*Tt];
__device__ float d_att_c[Bz*Cc*Cc];
__device__ float d_att_t[Bz*Tt*Tt];
__device__ float d_att_g[Bz*Nn*Nn];
__device__ float d_attT[Bz*Nn*Nn];
__device__ float d_M[Bz*O3*O3];

// flags for generic k_mix
#define F_ADD     2
#define F_RELU    4
#define F_BIAS    8
#define F_COMPACT 16

// -------- packed f32x2 helpers --------
__device__ __forceinline__ void fma2(u64& d, u64 a, u64 b) {
    asm("fma.rn.f32x2 %0, %1, %2, %0;" : "+l"(d) : "l"(a), "l"(b));
}
__device__ __forceinline__ u64 pk2(float x) {
    u64 r; unsigned xi = __float_as_uint(x);
    asm("mov.b64 %0, {%1, %1};" : "=l"(r) : "r"(xi));
    return r;
}
__device__ __forceinline__ float2 unpk(u64 v) {
    unsigned lo, hi;
    asm("mov.b64 {%0, %1}, %2;" : "=r"(lo), "=r"(hi) : "l"(v));
    return make_float2(__uint_as_float(lo), __uint_as_float(hi));
}

// ---------------- LayerNorm (+ fused ca/ga T-dots), warp per row ----------------
__global__ void k_ln(const float* __restrict__ x, const float* __restrict__ g,
                     const float* __restrict__ be,
                     const float* __restrict__ caW1, const float* __restrict__ gaW1) {
    int warp = (blockIdx.x * blockDim.x + threadIdx.x) >> 5;
    int lane = threadIdx.x & 31;
    if (warp >= BCN) return;
    const float* row = x + (long)warp * Tt;
    float v = (lane < Tt) ? row[lane] : 0.f;
    float s = v, s2 = v * v;
    #pragma unroll
    for (int o = 16; o; o >>= 1) {
        s  += __shfl_xor_sync(~0u, s,  o);
        s2 += __shfl_xor_sync(~0u, s2, o);
    }
    float mu  = s * (1.f / Tt);
    float var = s2 * (1.f / Tt) - mu * mu;
    float inv = rsqrtf(var + 1e-5f);
    float hv = 0.f;
    if (lane < Tt) {
        hv = (v - mu) * inv * g[lane] + be[lane];
        d_h[(long)warp * Tt + lane] = hv;
    }
    float dca = (lane < Tt) ? hv * caW1[lane] : 0.f;
    float dga = (lane < Tt) ? hv * gaW1[lane] : 0.f;
    #pragma unroll
    for (int o = 16; o; o >>= 1) {
        dca += __shfl_xor_sync(~0u, dca, o);
        dga += __shfl_xor_sync(~0u, dga, o);
    }
    if (lane == 0) { d_tca[warp] = dca; d_tga[warp] = dga; }
}

// ---------------- stage1: 6 independent glue reductions, one launch ----------------
__global__ void k_stage1(const float* __restrict__ caW3, const float* __restrict__ taW1,
                         const float* __restrict__ taW3, const float* __restrict__ gaW3,
                         const float* __restrict__ caW2, const float* __restrict__ gaW2) {
    int task = blockIdx.y;
    int idx = blockIdx.x * 256 + threadIdx.x;
    if (task <= 1) {            // reduce over n: out[b,c,t] = sum_n w[n]*h[bc,n,t]
        if (idx >= Bz * Cc * Tt) return;
        const float* w = task ? taW1 : caW3;
        int t = idx % Tt, bc = idx / Tt;
        const float* hp = d_h + (long)bc * Nn * Tt + t;
        float a0 = 0.f, a1 = 0.f, a2 = 0.f, a3 = 0.f;
        int n = 0;
        for (; n < 304; n += 4) {
            a0 += w[n]     * hp[(n)     * Tt];
            a1 += w[n + 1] * hp[(n + 1) * Tt];
            a2 += w[n + 2] * hp[(n + 2) * Tt];
            a3 += w[n + 3] * hp[(n + 3) * Tt];
        }
        for (; n < Nn; n++) a0 += w[n] * hp[n * Tt];
        float r = (a0 + a1) + (a2 + a3);
        if (task) d_tmp_t[idx] = r; else d_rhs_c[idx] = r;
    } else if (task <= 3) {     // reduce over c: out[b,n,t] = sum_c w[c]*h[b,c,n,t]
        if (idx >= Bz * Nn * Tt) return;
        const float* w = (task == 2) ? taW3 : gaW3;
        int t = idx % Tt, n = (idx / Tt) % Nn, b = idx / (Nn * Tt);
        const float* hp = d_h + (((long)b * Cc) * Nn + n) * Tt + t;
        float a0 = 0.f, a1 = 0.f, a2 = 0.f, a3 = 0.f;
        #pragma unroll 4
        for (int c = 0; c < Cc; c += 4) {
            a0 += w[c]     * hp[(long)(c)     * Nn * Tt];
            a1 += w[c + 1] * hp[(long)(c + 1) * Nn * Tt];
            a2 += w[c + 2] * hp[(long)(c + 2) * Nn * Tt];
            a3 += w[c + 3] * hp[(long)(c + 3) * Nn * Tt];
        }
        float r = (a0 + a1) + (a2 + a3);
        if (task == 2) d_rhs_t[idx] = r; else d_rhs_g[idx] = r;
    } else if (task == 4) {     // lhs_c[b,c,t] = sum_n tca[bc,n]*caW2[n,t]
        if (idx >= Bz * Cc * Tt) return;
        int t = idx % Tt, bc = idx / Tt;
        const float* tp = d_tca + (long)bc * Nn;
        float a0 = 0.f, a1 = 0.f, a2 = 0.f, a3 = 0.f;
        int n = 0;
        for (; n < 304; n += 4) {
            a0 += tp[n]     * caW2[(n)     * Tt + t];
            a1 += tp[n + 1] * caW2[(n + 1) * Tt + t];
            a2 += tp[n + 2] * caW2[(n + 2) * Tt + t];
            a3 += tp[n + 3] * caW2[(n + 3) * Tt + t];
        }
        for (; n < Nn; n++) a0 += tp[n] * caW2[n * Tt + t];
        d_lhs_c[idx] = (a0 + a1) + (a2 + a3);
    } else {                    // lhs_g[b,n,t] = sum_c tga[b,c,n]*gaW2[c,t]
        if (idx >= Bz * Nn * Tt) return;
        int t = idx % Tt, bn = idx / Tt;
        int n = bn % Nn, b = bn / Nn;
        const float* tp = d_tga + (long)b * Cc * Nn + n;
        float a0 = 0.f, a1 = 0.f, a2 = 0.f, a3 = 0.f;
        #pragma unroll 4
        for (int c = 0; c < Cc; c += 4) {
            a0 += tp[(c)     * Nn] * gaW2[(c)     * Tt + t];
            a1 += tp[(c + 1) * Nn] * gaW2[(c + 1) * Tt + t];
            a2 += tp[(c + 2) * Nn] * gaW2[(c + 2) * Tt + t];
            a3 += tp[(c + 3) * Nn] * gaW2[(c + 3) * Tt + t];
        }
        d_lhs_g[idx] = (a0 + a1) + (a2 + a3);
    }
}

// ---------------- stage2: att_g softmax | lhs_t | att_c softmax ----------------
__global__ void k_small2(const int* __restrict__ adj, const float* __restrict__ taW2) {
    __shared__ float smem_s[160];   // att_g: Ls[24]+red[128]; att_c: sh[2][64]
    int task = blockIdx.y;
    int tid = threadIdx.x;          // 128
    if (task == 0) {                // graph attention, block per (b,n)
        int bn = blockIdx.x;
        if (bn >= Bz * Nn) return;
        int b = bn / Nn, n = bn % Nn;
        float* Ls  = smem_s;        // [24]
        float* red = smem_s + 32;   // [128]
        if (tid < Tt) Ls[tid] = d_lhs_g[bn * Tt + tid];
        __syncthreads();
        float sc[3];
        #pragma unroll
        for (int k = 0; k < 3; k++) {
            int m = tid + k * 128;
            sc[k] = -INFINITY;
            if (m < Nn) {
                float dot = 0.f;
                const float* R = d_rhs_g + ((long)b * Nn + m) * Tt;
                #pragma unroll
                for (int t = 0; t < Tt; t++) dot += Ls[t] * R[t];
                sc[k] = (adj[n * Nn + m] > 0) ? dot : -1e30f;
            }
        }
        float lm = fmaxf(fmaxf(sc[0], sc[1]), sc[2]);
        red[tid] = lm; __syncthreads();
        for (int st = 64; st; st >>= 1) {
            if (tid < st) red[tid] = fmaxf(red[tid], red[tid + st]);
            __syncthreads();
        }
        float M = red[0]; __syncthreads();
        float ls = 0.f;
        #pragma unroll
        for (int k = 0; k < 3; k++) {
            int m = tid + k * 128;
            if (m < Nn) { sc[k] = expf(sc[k] - M); ls += sc[k]; }
        }
        red[tid] = ls; __syncthreads();
        for (int st = 64; st; st >>= 1) {
            if (tid < st) red[tid] += red[tid + st];
            __syncthreads();
        }
        float S = red[0];
        #pragma unroll
        for (int k = 0; k < 3; k++) {
            int m = tid + k * 128;
            if (m < Nn) d_att_g[((long)b * Nn + n) * Nn + m] = sc[k] / S;
        }
    } else if (task == 1) {         // lhs_t[b,t,n] = sum_c tmp_t[b,c,t]*taW2[c,n]
        int idx = blockIdx.x * 128 + tid;
        if (idx >= Bz * Tt * Nn) return;
        int n = idx % Nn, bt = idx / Nn;
        int t = bt % Tt, b = bt / Tt;
        const float* tp = d_tmp_t + ((long)b * Cc) * Tt + t;
        float a0 = 0.f, a1 = 0.f, a2 = 0.f, a3 = 0.f;
        #pragma unroll 4
        for (int c = 0; c < Cc; c += 4) {
            a0 += tp[(c)     * Tt] * taW2[(c)     * Nn + n];
            a1 += tp[(c + 1) * Tt] * taW2[(c + 1) * Nn + n];
            a2 += tp[(c + 2) * Tt] * taW2[(c + 2) * Nn + n];
            a3 += tp[(c + 3) * Tt] * taW2[(c + 3) * Nn + n];
        }
        d_lhs_t[idx] = (a0 + a1) + (a2 + a3);
    } else {                        // channel attention, 2 (b,c) units per block
        int bc2 = blockIdx.x;
        if (bc2 >= (Bz * Cc) / 2) return;
        int unit = tid >> 6, d = tid & 63;
        int bc = bc2 * 2 + unit;
        int b = bc / Cc;
        float* sh = smem_s + unit * 64;
        float dot = 0.f;
        const float* L = d_lhs_c + bc * Tt;
        const float* R = d_rhs_c + (b * Cc + d) * Tt;
        #pragma unroll
        for (int t = 0; t < Tt; t++) dot += L[t] * R[t];
        sh[d] = dot;
        __syncthreads();
        float m = -1e38f;
        for (int i = 0; i < O3; i++) m = fmaxf(m, sh[i]);
        float e = expf(dot - m);
        __syncthreads();
        sh[d] = e;
        __syncthreads();
        float s = 0.f;
        for (int i = 0; i < O3; i++) s += sh[i];
        d_att_c[bc * O3 + d] = e / s;
    }
}

// ---------------- stage3: k_M | att_t | transpose att_g ----------------
__global__ void k_small3(const float* __restrict__ ccW) {
    int task = blockIdx.y;
    int tid = threadIdx.x;          // 256
    if (task == 0) {                // M[b,o,d] = sum_c ccW[o,c]*att_c[b,c,d]
        int idx = blockIdx.x * 256 + tid;
        if (idx >= Bz * O3 * O3) return;
        int dd = idx % O3, o = (idx / O3) % O3, b = idx / (O3 * O3);
        const float* ap = d_att_c + ((long)b * Cc) * O3 + dd;
        float a0 = 0.f, a1 = 0.f, a2 = 0.f, a3 = 0.f;
        #pragma unroll 4
        for (int c = 0; c < Cc; c += 4) {
            a0 += ccW[o * Cc + c]     * ap[(c)     * O3];
            a1 += ccW[o * Cc + c + 1] * ap[(c + 1) * O3];
            a2 += ccW[o * Cc + c + 2] * ap[(c + 2) * O3];
            a3 += ccW[o * Cc + c + 3] * ap[(c + 3) * O3];
        }
        d_M[idx] = (a0 + a1) + (a2 + a3);
    } else if (task == 1) {         // temporal attention softmax, warp per (b,t)
        int w = blockIdx.x * 8 + (tid >> 5);
        if (w >= Bz * Tt) return;
        int lane = tid & 31;
        int b = w / Tt;
        float dot = -INFINITY;
        if (lane < Tt) {
            dot = 0.f;
            const float* L = d_lhs_t + (long)w * Nn;
            const float* R = d_rhs_t + (long)b * Nn * Tt + lane;
            for (int n = 0; n < Nn; n++) dot += L[n] * R[n * Tt];
        }
        float m = dot;
        #pragma unroll
        for (int o = 16; o; o >>= 1) m = fmaxf(m, __shfl_xor_sync(~0u, m, o));
        float e = (lane < Tt) ? expf(dot - m) : 0.f;
        float su = e;
        #pragma unroll
        for (int o = 16; o; o >>= 1) su += __shfl_xor_sync(~0u, su, o);
        if (lane < Tt) d_att_t[w * Tt + lane] = e / su;
    } else {                        // attT[b,m,n] = att_g[b,n,m]
        int blk = blockIdx.x;
        if (blk >= 3200) return;
        __shared__ float tile[32][33];
        int bx = blk % 10, by = (blk / 10) % 10, b = blk / 100;
        int x0 = bx * 32, y0 = by * 32;
        const float* A = d_att_g + (long)b * Nn * Nn;
        float* AT = d_attT + (long)b * Nn * Nn;
        int tx = tid & 31, ty = tid >> 5;
        #pragma unroll
        for (int i = 0; i < 4; i++) {
            int y = y0 + ty + i * 8, xx = x0 + tx;
            if (y < Nn && xx < Nn) tile[ty + i * 8][tx] = A[(long)y * Nn + xx];
        }
        __syncthreads();
        #pragma unroll
        for (int i = 0; i < 4; i++) {
            int y = x0 + ty + i * 8, xx = y0 + tx;
            if (y < Nn && xx < Nn) AT[(long)y * Nn + xx] = tile[tx][ty + i * 8];
        }
    }
}

// ---------------- apply temporal attention: bufA = att_t applied to h ----------------
__global__ void k_apply_t() {
    int warp = (blockIdx.x * blockDim.x + threadIdx.x) >> 5;
    int lane = threadIdx.x & 31;
    if (warp >= BCN) return;
    int b = warp / (Cc * Nn);
    long row = (long)warp * Tt;
    float hv = (lane < Tt) ? d_h[row + lane] : 0.f;
    float acc = 0.f;
    const float* arow = d_att_t + (b * Tt + (lane < Tt ? lane : 0)) * Tt;
    #pragma unroll
    for (int s = 0; s < Tt; s++) {
        float hs = __shfl_sync(~0u, hv, s);
        acc += arow[s] * hs;
    }
    if (lane < Tt) d_bufA[row + lane] = acc;
}

// ---------------- conv1: dil=1, bufA -> bufB (+bias) ----------------
__global__ void __launch_bounds__(256, 2)
k_conv1(const float* __restrict__ W, const float* __restrict__ bias) {
    int b = blockIdx.z, og = blockIdx.y;
    int p0 = blockIdx.x * 1024 + threadIdx.x * 4;
    __shared__ __align__(16) float W0s[Cc][16], W1s[Cc][16];
    for (int i = threadIdx.x; i < 16 * Cc; i += 256) {
        int o = i & 15, c = i >> 4;
        W0s[c][o] = W[((og * 16 + o) * Cc + c) * 2 + 0];
        W1s[c][o] = W[((og * 16 + o) * Cc + c) * 2 + 1];
    }
    __syncthreads();
    if (p0 >= NT) return;
    int t0 = p0 % Tt;
    const float* Xb = d_bufA + (long)b * Cc * NT + p0;
    u64 acc2[8][4] = {};
    for (int c = 0; c < Cc; c++) {
        const float* Xc = Xb + (long)c * NT;
        float4 cur = *(const float4*)Xc;
        float pw = (t0 > 0) ? Xc[-1] : 0.f;
        float s0 = pw, s1 = cur.x, s2 = cur.y, s3 = cur.z;
        u64 xc0 = pk2(cur.x), xc1 = pk2(cur.y), xc2 = pk2(cur.z), xc3 = pk2(cur.w);
        u64 xs0 = pk2(s0), xs1 = pk2(s1), xs2 = pk2(s2), xs3 = pk2(s3);
        const u64* W1r = (const u64*)W1s[c];
        const u64* W0r = (const u64*)W0s[c];
        #pragma unroll
        for (int o2 = 0; o2 < 8; o2++) {
            u64 a1 = W1r[o2], a0 = W0r[o2];
            fma2(acc2[o2][0], a1, xc0); fma2(acc2[o2][0], a0, xs0);
            fma2(acc2[o2][1], a1, xc1); fma2(acc2[o2][1], a0, xs1);
            fma2(acc2[o2][2], a1, xc2); fma2(acc2[o2][2], a0, xs2);
            fma2(acc2[o2][3], a1, xc3); fma2(acc2[o2][3], a0, xs3);
        }
    }
    #pragma unroll
    for (int o2 = 0; o2 < 8; o2++) {
        float2 v0 = unpk(acc2[o2][0]), v1 = unpk(acc2[o2][1]);
        float2 v2 = unpk(acc2[o2][2]), v3 = unpk(acc2[o2][3]);
        #pragma unroll
        for (int par = 0; par < 2; par++) {
            int o = og * 16 + o2 * 2 + par;
            float4 v = par ? make_float4(v0.y, v1.y, v2.y, v3.y)
                           : make_float4(v0.x, v1.x, v2.x, v3.x);
            float bb = bias[o];
            v.x += bb; v.y += bb; v.z += bb; v.w += bb;
            *(float4*)(d_bufB + ((long)b * Cc + o) * NT + p0) = v;
        }
    }
}

// ---------------- conv2 (dil=2) + fused residual slice [64:128] + relu ----------------
__global__ void __launch_bounds__(256, 2)
k_conv2res(const float* __restrict__ W, const float* __restrict__ tcb,
           const float* __restrict__ resW, const float* __restrict__ resb,
           const float* __restrict__ x, float* __restrict__ out) {
    int b = blockIdx.z, og = blockIdx.y;
    int p0 = blockIdx.x * 1024 + threadIdx.x * 4;
    __shared__ __align__(16) float W0s[Cc][16], W1s[Cc][16], Rs[Cc][16];
    for (int i = threadIdx.x; i < 16 * Cc; i += 256) {
        int o = i & 15, c = i >> 4;
        W0s[c][o] = W[((og * 16 + o) * Cc + c) * 2 + 0];
        W1s[c][o] = W[((og * 16 + o) * Cc + c) * 2 + 1];
        Rs[c][o]  = resW[(64 + og * 16 + o) * Cc + c];
    }
    __syncthreads();
    if (p0 >= NT) return;
    int t0 = p0 % Tt;
    const float* Xb = d_bufB + (long)b * Cc * NT + p0;
    const float* xb = x + (long)b * Cc * NT + p0;
    u64 acc2[8][4] = {};
    for (int c = 0; c < Cc; c++) {
        const float* Xc = Xb + (long)c * NT;
        float4 cur = *(const float4*)Xc;
        float2 pv = make_float2(0.f, 0.f);
        if (t0 > 0) pv = *(const float2*)(Xc - 2);
        float4 xv = *(const float4*)(xb + (long)c * NT);
        float s0 = pv.x, s1 = pv.y, s2 = cur.x, s3 = cur.y;
        u64 xc0 = pk2(cur.x), xc1 = pk2(cur.y), xc2 = pk2(cur.z), xc3 = pk2(cur.w);
        u64 xs0 = pk2(s0), xs1 = pk2(s1), xs2 = pk2(s2), xs3 = pk2(s3);
        u64 xr0 = pk2(xv.x), xr1 = pk2(xv.y), xr2 = pk2(xv.z), xr3 = pk2(xv.w);
        const u64* W1r = (const u64*)W1s[c];
        const u64* W0r = (const u64*)W0s[c];
        const u64* Rr  = (const u64*)Rs[c];
        #pragma unroll
        for (int o2 = 0; o2 < 8; o2++) {
            u64 a1 = W1r[o2], a0 = W0r[o2], ar = Rr[o2];
            fma2(acc2[o2][0], a1, xc0); fma2(acc2[o2][0], a0, xs0); fma2(acc2[o2][0], ar, xr0);
            fma2(acc2[o2][1], a1, xc1); fma2(acc2[o2][1], a0, xs1); fma2(acc2[o2][1], ar, xr1);
            fma2(acc2[o2][2], a1, xc2); fma2(acc2[o2][2], a0, xs2); fma2(acc2[o2][2], ar, xr2);
            fma2(acc2[o2][3], a1, xc3); fma2(acc2[o2][3], a0, xs3); fma2(acc2[o2][3], ar, xr3);
        }
    }
    #pragma unroll
    for (int o2 = 0; o2 < 8; o2++) {
        float2 v0 = unpk(acc2[o2][0]), v1 = unpk(acc2[o2][1]);
        float2 v2 = unpk(acc2[o2][2]), v3 = unpk(acc2[o2][3]);
        #pragma unroll
        for (int par = 0; par < 2; par++) {
            int o = og * 16 + o2 * 2 + par;
            float4 v = par ? make_float4(v0.y, v1.y, v2.y, v3.y)
                           : make_float4(v0.x, v1.x, v2.x, v3.x);
            float bb = tcb[o] + resb[64 + o];
            v.x = fmaxf(v.x + bb, 0.f); v.y = fmaxf(v.y + bb, 0.f);
            v.z = fmaxf(v.z + bb, 0.f); v.w = fmaxf(v.w + bb, 0.f);
            *(float4*)(out + ((long)b * CO + 64 + o) * NT + p0) = v;
        }
    }
}

// ---------------- C-branch: out[0:64] = relu(M_b@h + resW0@x + cc_b + res_b) ----------------
__global__ void __launch_bounds__(256, 2)
k_cmix(const float* __restrict__ resW, const float* __restrict__ resb,
       const float* __restrict__ ccb, const float* __restrict__ x,
       float* __restrict__ out) {
    int b = blockIdx.z, og = blockIdx.y;
    int p0 = blockIdx.x * 1024 + threadIdx.x * 4;
    __shared__ __align__(16) float Ms[Cc][16], Rs[Cc][16];
    const float* Mb = d_M + (long)b * O3 * Cc;
    for (int i = threadIdx.x; i < 16 * Cc; i += 256) {
        int o = i & 15, c = i >> 4;
        Ms[c][o] = Mb[(og * 16 + o) * Cc + c];
        Rs[c][o] = resW[(og * 16 + o) * Cc + c];
    }
    __syncthreads();
    if (p0 >= NT) return;
    const float* Hb = d_h + (long)b * Cc * NT + p0;
    const float* xb = x + (long)b * Cc * NT + p0;
    u64 acc2[8][4] = {};
    for (int c = 0; c < Cc; c++) {
        float4 hv = *(const float4*)(Hb + (long)c * NT);
        float4 xv = *(const float4*)(xb + (long)c * NT);
        u64 hp0 = pk2(hv.x), hp1 = pk2(hv.y), hp2 = pk2(hv.z), hp3 = pk2(hv.w);
        u64 xp0 = pk2(xv.x), xp1 = pk2(xv.y), xp2 = pk2(xv.z), xp3 = pk2(xv.w);
        const u64* Mr = (const u64*)Ms[c];
        const u64* Rr = (const u64*)Rs[c];
        #pragma unroll
        for (int o2 = 0; o2 < 8; o2++) {
            u64 am = Mr[o2], ar = Rr[o2];
            fma2(acc2[o2][0], am, hp0); fma2(acc2[o2][0], ar, xp0);
            fma2(acc2[o2][1], am, hp1); fma2(acc2[o2][1], ar, xp1);
            fma2(acc2[o2][2], am, hp2); fma2(acc2[o2][2], ar, xp2);
            fma2(acc2[o2][3], am, hp3); fma2(acc2[o2][3], ar, xp3);
        }
    }
    #pragma unroll
    for (int o2 = 0; o2 < 8; o2++) {
        float2 v0 = unpk(acc2[o2][0]), v1 = unpk(acc2[o2][1]);
        float2 v2 = unpk(acc2[o2][2]), v3 = unpk(acc2[o2][3]);
        #pragma unroll
        for (int par = 0; par < 2; par++) {
            int o = og * 16 + o2 * 2 + par;
            float4 v = par ? make_float4(v0.y, v1.y, v2.y, v3.y)
                           : make_float4(v0.x, v1.x, v2.x, v3.x);
            float bb = ccb[o] + resb[o];
            v.x = fmaxf(v.x + bb, 0.f); v.y = fmaxf(v.y + bb, 0.f);
            v.z = fmaxf(v.z + bb, 0.f); v.w = fmaxf(v.w + bb, 0.f);
            *(float4*)(out + ((long)b * CO + o) * NT + p0) = v;
        }
    }
}

// ---------------- generic channel-mix (gh compact + residual-G) ----------------
__global__ void __launch_bounds__(256, 2)
k_mix(const float* __restrict__ A, const float* __restrict__ X,
      const float* __restrict__ bias, float* __restrict__ out,
      int Ototal, int chOff, int flags) {
    int b = blockIdx.z, og = blockIdx.y;
    int p0 = blockIdx.x * 1024 + threadIdx.x * 4;
    __shared__ __align__(16) float As[Cc][16];
    for (int i = threadIdx.x; i < 16 * Cc; i += 256) {
        int o = i & 15, c = i >> 4;
        As[c][o] = A[(og * 16 + o) * Cc + c];
    }
    __syncthreads();
    if (p0 >= NT) return;
    const float* Xb = X + (long)b * Cc * NT + p0;
    u64 acc2[8][4] = {};
    for (int c = 0; c < Cc; c++) {
        float4 xv = *(const float4*)(Xb + (long)c * NT);
        u64 xp0 = pk2(xv.x), xp1 = pk2(xv.y), xp2 = pk2(xv.z), xp3 = pk2(xv.w);
        const u64* Arow = (const u64*)As[c];
        #pragma unroll
        for (int o2 = 0; o2 < 8; o2++) {
            u64 a2 = Arow[o2];
            fma2(acc2[o2][0], a2, xp0);
            fma2(acc2[o2][1], a2, xp1);
            fma2(acc2[o2][2], a2, xp2);
            fma2(acc2[o2][3], a2, xp3);
        }
    }
    #pragma unroll
    for (int o2 = 0; o2 < 8; o2++) {
        float2 v0 = unpk(acc2[o2][0]), v1 = unpk(acc2[o2][1]);
        float2 v2 = unpk(acc2[o2][2]), v3 = unpk(acc2[o2][3]);
        #pragma unroll
        for (int par = 0; par < 2; par++) {
            int o = og * 16 + o2 * 2 + par;
            float4 v = par ? make_float4(v0.y, v1.y, v2.y, v3.y)
                           : make_float4(v0.x, v1.x, v2.x, v3.x);
            if (flags & F_BIAS) {
                float bb = bias[o];
                v.x += bb; v.y += bb; v.z += bb; v.w += bb;
            }
            long oi = (flags & F_COMPACT)
                    ? ((long)b * Ototal + o) * NT + p0
                    : ((long)b * CO + chOff + o) * NT + p0;
            if (flags & F_ADD) {
                float4 r = *(const float4*)(out + oi);
                v.x += r.x; v.y += r.y; v.z += r.z; v.w += r.w;
            }
            if (flags & F_RELU) {
                v.x = fmaxf(v.x, 0.f); v.y = fmaxf(v.y, 0.f);
                v.z = fmaxf(v.z, 0.f); v.w = fmaxf(v.w, 0.f);
            }
            *(float4*)(out + oi) = v;
        }
    }
}

// ---------------- graph apply GEMM + residual add + relu ----------------
// out[b,128+c,n,t] = relu(sum_m attT[b,m,n]*gh[b,c,m,t] + out[...])
// block: (n-tile 64, c-group 8, b). thread: cl=tid&7, tq=(tid>>3)&3, ty=tid>>5.
#define GCS 428   // per-channel smem stride: 16*26 + 12 pad (conflict-free bank-pair cover)

__global__ void __launch_bounds__(256, 2) k_gapply(float* __restrict__ out) {
    int b = blockIdx.z;
    int n0 = blockIdx.x * 64;
    int cbase = blockIdx.y * 8;
    int tid = threadIdx.x;
    int cl = tid & 7, tq = (tid >> 3) & 3, ty = tid >> 5;
    int t0 = tq * 6;
    __shared__ __align__(16) u64 att2_s[16][64];
    __shared__ __align__(16) float gh_s[8 * GCS];
    u64 acc2[8][3] = {};
    const float* ATb = d_attT + (long)b * Nn * Nn;
    const float* GHb = d_bufA + ((long)b * Cc + cbase) * (long)Nn * Tt;
    for (int m0 = 0; m0 < Nn; m0 += 16) {
        #pragma unroll
        for (int i = tid; i < 1024; i += 256) {
            int mk = i >> 6, nl = i & 63;
            float v = 0.f;
            if (m0 + mk < Nn && n0 + nl < Nn) v = ATb[(long)(m0 + mk) * Nn + n0 + nl];
            att2_s[mk][nl] = pk2(v);
        }
        #pragma unroll
        for (int i = tid; i < 3072; i += 256) {
            int c2 = i / 384, r = i - c2 * 384;
            int mk = r / 24, t = r - mk * 24;
            float v = 0.f;
            if (m0 + mk < Nn) v = GHb[((long)c2 * Nn + m0 + mk) * Tt + t];
            gh_s[c2 * GCS + mk * 26 + t] = v;
        }
        __syncthreads();
        #pragma unroll
        for (int mk = 0; mk < 16; mk++) {
            const u64* ar = &att2_s[mk][ty * 8];
            const u64* gp = (const u64*)&gh_s[cl * GCS + mk * 26 + t0];
            u64 g0 = gp[0], g1 = gp[1], g2 = gp[2];
            #pragma unroll
            for (int j = 0; j < 8; j++) {
                u64 a = ar[j];
                fma2(acc2[j][0], a, g0);
                fma2(acc2[j][1], a, g1);
                fma2(acc2[j][2], a, g2);
            }
        }
        __syncthreads();
    }
    int ch = 128 + cbase + cl;
    #pragma unroll
    for (int j = 0; j < 8; j++) {
        int n = n0 + ty * 8 + j;
        if (n >= Nn) continue;
        long base = ((long)b * CO + ch) * NT + (long)n * Tt + t0;
        #pragma unroll
        for (int k = 0; k < 3; k++) {
            float2 v = unpk(acc2[j][k]);
            float2 r = *(const float2*)(out + base + k * 2);
            v.x = fmaxf(v.x + r.x, 0.f);
            v.y = fmaxf(v.y + r.y, 0.f);
            *(float2*)(out + base + k * 2) = v;
        }
    }
}

// ================================= launch =================================
extern "C" void kernel_launch(void* const* d_in, const int* in_sizes, int n_in,
                              void* d_out, int out_size) {
    const float* x     = (const float*)d_in[0];
    const int*   adj   = (const int*)  d_in[1];
    const float* ln_g  = (const float*)d_in[2];
    const float* ln_b  = (const float*)d_in[3];
    const float* res_W = (const float*)d_in[4];
    const float* res_b = (const float*)d_in[5];
    const float* ca_W1 = (const float*)d_in[6];
    const float* ca_W2 = (const float*)d_in[7];
    const float* ca_W3 = (const float*)d_in[8];
    const float* cc_W  = (const float*)d_in[9];
    const float* cc_b  = (const float*)d_in[10];
    const float* ta_W1 = (const float*)d_in[11];
    const float* ta_W2 = (const float*)d_in[12];
    const float* ta_W3 = (const float*)d_in[13];
    const float* tc_W0 = (const float*)d_in[14];
    const float* tc_b0 = (const float*)d_in[15];
    const float* tc_W1 = (const float*)d_in[16];
    const float* tc_b1 = (const float*)d_in[17];
    const float* ga_W1 = (const float*)d_in[18];
    const float* ga_W2 = (const float*)d_in[19];
    const float* ga_W3 = (const float*)d_in[20];
    const float* g_W   = (const float*)d_in[21];
    float* out = (float*)d_out;

    float *p_h, *p_bufA;
    cudaGetSymbolAddress((void**)&p_h,    d_h);
    cudaGetSymbolAddress((void**)&p_bufA, d_bufA);

    int warpBlocks = (BCN + 7) / 8;

    // 1) LayerNorm + fused ca/ga T-dots
    k_ln<<<warpBlocks, 256>>>(x, ln_g, ln_b, ca_W1, ga_W1);
    // 2) all independent glue reductions in one launch
    k_stage1<<<dim3(921, 6), 256>>>(ca_W3, ta_W1, ta_W3, ga_W3, ca_W2, ga_W2);
    // 3) att_g | lhs_t | att_c
    k_small2<<<dim3(Bz * Nn, 3), 128>>>(adj, ta_W2);
    // 4) k_M | att_t | transpose(att_g)
    k_small3<<<dim3(3200, 3), 256>>>(cc_W);
    // 5) temporal attention apply -> bufA
    k_apply_t<<<warpBlocks, 256>>>();
    // 6) conv1: bufA -> bufB
    k_conv1<<<dim3(8, 4, Bz), 256>>>(tc_W0, tc_b0);
    // 7) gh = g_W @ h -> bufA (bufA free after conv1)
    k_mix<<<dim3(8, 4, Bz), 256>>>(g_W, p_h, nullptr, p_bufA, O3, 0, F_COMPACT);
    // 8) conv2 + residual[64:128] + relu -> out
    k_conv2res<<<dim3(8, 4, Bz), 256>>>(tc_W1, tc_b1, res_W, res_b, x, out);
    // 9) C branch: M@h + residual[0:64] + relu -> out
    k_cmix<<<dim3(8, 4, Bz), 256>>>(res_W, res_b, cc_b, x, out);
    // 10) residual base for G channels [128:192]
    k_mix<<<dim3(8, 4, Bz), 256>>>(res_W + (long)128 * Cc, x, res_b + 128, out,
                                   CO, 128, F_BIAS);
    // 11) graph apply GEMM + add + relu
    k_gapply<<<dim3(5, 8, Bz), 256>>>(out);

    (void)in_sizes; (void)n_in; (void)out_size;
}

// round 5
// speedup vs baseline: 2.0506x; 1.0206x over previous
#include <cuda_runtime.h>
#include <math.h>

#define Bz 32
#define Cc 64
#define Nn 307
#define Tt 24
#define NT 7368            // Nn*Tt
#define O3 64
#define CO 192
#define BCN (Bz*Cc*Nn)     // 628736
#define BCNT (Bz*Cc*NT)    // 15089664

typedef unsigned long long u64;

// ---------------- scratch (device globals) ----------------
__device__ float d_h[BCNT];
__device__ float d_bufA[BCNT];
__device__ float d_bufB[BCNT];
__device__ float d_tca[Bz*Cc*Nn];
__device__ float d_tga[Bz*Cc*Nn];
__device__ float d_lhs_c[Bz*Cc*Tt];
__device__ float d_rhs_c[Bz*Cc*Tt];
__device__ float d_tmp_t[Bz*Cc*Tt];
__device__ float d_lhs_t[Bz*Tt*Nn];
__device__ float d_rhs_t[Bz*Nn*Tt];
__device__ float d_lhs_g[Bz*Nn*Tt];
__device__ float d_rhs_g[Bz*Nn*Tt];
__device__ float d_att_c[Bz*Cc*Cc];
__device__ float d_att_t[Bz*Tt*Tt];
__device__ float d_att_g[Bz*Nn*Nn];
__device__ float d_attT[Bz*Nn*Nn];
__device__ float d_M[Bz*O3*O3];
__device__ float d_Wc[4*O3*Cc];     // combined conv taps: [k][o][c]
__device__ float d_bhi[O3];         // combined bias for t>=2
__device__ float d_blo[O3];         // combined bias for t<2

#define F_ADD     2
#define F_RELU    4
#define F_BIAS    8
#define F_COMPACT 16

// -------- packed f32x2 helpers --------
__device__ __forceinline__ void fma2(u64& d, u64 a, u64 b) {
    asm("fma.rn.f32x2 %0, %1, %2, %0;" : "+l"(d) : "l"(a), "l"(b));
}
__device__ __forceinline__ u64 pk2(float x) {
    u64 r; unsigned xi = __float_as_uint(x);
    asm("mov.b64 %0, {%1, %1};" : "=l"(r) : "r"(xi));
    return r;
}
__device__ __forceinline__ float2 unpk(u64 v) {
    unsigned lo, hi;
    asm("mov.b64 {%0, %1}, %2;" : "=r"(lo), "=r"(hi) : "l"(v));
    return make_float2(__uint_as_float(lo), __uint_as_float(hi));
}

// ---------------- LayerNorm (+ fused ca/ga T-dots), warp per row ----------------
__global__ void k_ln(const float* __restrict__ x, const float* __restrict__ g,
                     const float* __restrict__ be,
                     const float* __restrict__ caW1, const float* __restrict__ gaW1) {
    int warp = (blockIdx.x * blockDim.x + threadIdx.x) >> 5;
    int lane = threadIdx.x & 31;
    if (warp >= BCN) return;
    const float* row = x + (long)warp * Tt;
    float v = (lane < Tt) ? row[lane] : 0.f;
    float s = v, s2 = v * v;
    #pragma unroll
    for (int o = 16; o; o >>= 1) {
        s  += __shfl_xor_sync(~0u, s,  o);
        s2 += __shfl_xor_sync(~0u, s2, o);
    }
    float mu  = s * (1.f / Tt);
    float var = s2 * (1.f / Tt) - mu * mu;
    float inv = rsqrtf(var + 1e-5f);
    float hv = 0.f;
    if (lane < Tt) {
        hv = (v - mu) * inv * g[lane] + be[lane];
        d_h[(long)warp * Tt + lane] = hv;
    }
    float dca = (lane < Tt) ? hv * caW1[lane] : 0.f;
    float dga = (lane < Tt) ? hv * gaW1[lane] : 0.f;
    #pragma unroll
    for (int o = 16; o; o >>= 1) {
        dca += __shfl_xor_sync(~0u, dca, o);
        dga += __shfl_xor_sync(~0u, dga, o);
    }
    if (lane == 0) { d_tca[warp] = dca; d_tga[warp] = dga; }
}

// ---------------- combined conv weights: Wc[k] in {W1'W1, W1'W0, W0'W1, W0'W0} ----------------
__global__ void k_wcomb(const float* __restrict__ tcW0, const float* __restrict__ tcb0,
                        const float* __restrict__ tcW1, const float* __restrict__ tcb1) {
    int idx = blockIdx.x * 256 + threadIdx.x;
    if (idx < 4 * O3 * Cc) {
        int c = idx & 63, o = (idx >> 6) & 63, k = idx >> 12;
        int a = (k < 2) ? 1 : 0;                 // conv2 tap: 1=current, 0=t-2
        int bsel = (k == 0 || k == 2) ? 1 : 0;   // conv1 tap: 1=current, 0=t-1
        float s = 0.f;
        for (int j = 0; j < O3; j++)
            s += tcW1[(o * O3 + j) * 2 + a] * tcW0[(j * Cc + c) * 2 + bsel];
        d_Wc[idx] = s;
    } else if (idx < 4 * O3 * Cc + O3) {
        int o = idx - 4 * O3 * Cc;
        float s1 = 0.f, s0 = 0.f;
        for (int j = 0; j < O3; j++) {
            s1 += tcW1[(o * O3 + j) * 2 + 1] * tcb0[j];
            s0 += tcW1[(o * O3 + j) * 2 + 0] * tcb0[j];
        }
        d_blo[o] = s1 + tcb1[o];
        d_bhi[o] = s1 + s0 + tcb1[o];
    }
}

// ---------------- stage1: 4 tasks, paired h passes ----------------
__global__ void k_stage1(const float* __restrict__ caW3, const float* __restrict__ taW1,
                         const float* __restrict__ taW3, const float* __restrict__ gaW3,
                         const float* __restrict__ caW2, const float* __restrict__ gaW2) {
    int task = blockIdx.y;
    int idx = blockIdx.x * 256 + threadIdx.x;
    if (task == 0) {            // reduce over n (BOTH caW3->rhs_c and taW1->tmp_t)
        if (idx >= Bz * Cc * Tt) return;
        int t = idx % Tt, bc = idx / Tt;
        const float* hp = d_h + (long)bc * Nn * Tt + t;
        float a0 = 0.f, a1 = 0.f, b0 = 0.f, b1 = 0.f;
        int n = 0;
        for (; n < 306; n += 2) {
            float h0 = hp[(n)     * Tt];
            float h1 = hp[(n + 1) * Tt];
            a0 += caW3[n] * h0;  b0 += taW1[n] * h0;
            a1 += caW3[n + 1] * h1;  b1 += taW1[n + 1] * h1;
        }
        { float h0 = hp[n * Tt]; a0 += caW3[n] * h0; b0 += taW1[n] * h0; }
        d_rhs_c[idx] = a0 + a1;
        d_tmp_t[idx] = b0 + b1;
    } else if (task == 1) {     // reduce over c (BOTH taW3->rhs_t and gaW3->rhs_g)
        if (idx >= Bz * Nn * Tt) return;
        int t = idx % Tt, n = (idx / Tt) % Nn, b = idx / (Nn * Tt);
        const float* hp = d_h + (((long)b * Cc) * Nn + n) * Tt + t;
        float a0 = 0.f, a1 = 0.f, b0 = 0.f, b1 = 0.f;
        #pragma unroll 4
        for (int c = 0; c < Cc; c += 2) {
            float h0 = hp[(long)(c)     * Nn * Tt];
            float h1 = hp[(long)(c + 1) * Nn * Tt];
            a0 += taW3[c] * h0;  b0 += gaW3[c] * h0;
            a1 += taW3[c + 1] * h1;  b1 += gaW3[c + 1] * h1;
        }
        d_rhs_t[idx] = a0 + a1;
        d_rhs_g[idx] = b0 + b1;
    } else if (task == 2) {     // lhs_c[b,c,t] = sum_n tca[bc,n]*caW2[n,t]
        if (idx >= Bz * Cc * Tt) return;
        int t = idx % Tt, bc = idx / Tt;
        const float* tp = d_tca + (long)bc * Nn;
        float a0 = 0.f, a1 = 0.f, a2 = 0.f, a3 = 0.f;
        int n = 0;
        for (; n < 304; n += 4) {
            a0 += tp[n]     * caW2[(n)     * Tt + t];
            a1 += tp[n + 1] * caW2[(n + 1) * Tt + t];
            a2 += tp[n + 2] * caW2[(n + 2) * Tt + t];
            a3 += tp[n + 3] * caW2[(n + 3) * Tt + t];
        }
        for (; n < Nn; n++) a0 += tp[n] * caW2[n * Tt + t];
        d_lhs_c[idx] = (a0 + a1) + (a2 + a3);
    } else {                    // lhs_g[b,n,t] = sum_c tga[b,c,n]*gaW2[c,t]
        if (idx >= Bz * Nn * Tt) return;
        int t = idx % Tt, bn = idx / Tt;
        int n = bn % Nn, b = bn / Nn;
        const float* tp = d_tga + (long)b * Cc * Nn + n;
        float a0 = 0.f, a1 = 0.f, a2 = 0.f, a3 = 0.f;
        #pragma unroll 4
        for (int c = 0; c < Cc; c += 4) {
            a0 += tp[(c)     * Nn] * gaW2[(c)     * Tt + t];
            a1 += tp[(c + 1) * Nn] * gaW2[(c + 1) * Tt + t];
            a2 += tp[(c + 2) * Nn] * gaW2[(c + 2) * Tt + t];
            a3 += tp[(c + 3) * Nn] * gaW2[(c + 3) * Tt + t];
        }
        d_lhs_g[idx] = (a0 + a1) + (a2 + a3);
    }
}

// ---------------- stage2: att_g softmax | lhs_t | att_c softmax ----------------
__global__ void k_small2(const int* __restrict__ adj, const float* __restrict__ taW2) {
    __shared__ float smem_s[160];
    int task = blockIdx.y;
    int tid = threadIdx.x;          // 128
    if (task == 0) {                // graph attention, block per (b,n)
        int bn = blockIdx.x;
        if (bn >= Bz * Nn) return;
        int b = bn / Nn, n = bn % Nn;
        float* Ls  = smem_s;
        float* red = smem_s + 32;
        if (tid < Tt) Ls[tid] = d_lhs_g[bn * Tt + tid];
        __syncthreads();
        float sc[3];
        #pragma unroll
        for (int k = 0; k < 3; k++) {
            int m = tid + k * 128;
            sc[k] = -INFINITY;
            if (m < Nn) {
                float dot = 0.f;
                const float* R = d_rhs_g + ((long)b * Nn + m) * Tt;
                #pragma unroll
                for (int t = 0; t < Tt; t++) dot += Ls[t] * R[t];
                sc[k] = (adj[n * Nn + m] > 0) ? dot : -1e30f;
            }
        }
        float lm = fmaxf(fmaxf(sc[0], sc[1]), sc[2]);
        red[tid] = lm; __syncthreads();
        for (int st = 64; st; st >>= 1) {
            if (tid < st) red[tid] = fmaxf(red[tid], red[tid + st]);
            __syncthreads();
        }
        float M = red[0]; __syncthreads();
        float ls = 0.f;
        #pragma unroll
        for (int k = 0; k < 3; k++) {
            int m = tid + k * 128;
            if (m < Nn) { sc[k] = expf(sc[k] - M); ls += sc[k]; }
        }
        red[tid] = ls; __syncthreads();
        for (int st = 64; st; st >>= 1) {
            if (tid < st) red[tid] += red[tid + st];
            __syncthreads();
        }
        float S = red[0];
        #pragma unroll
        for (int k = 0; k < 3; k++) {
            int m = tid + k * 128;
            if (m < Nn) d_att_g[((long)b * Nn + n) * Nn + m] = sc[k] / S;
        }
    } else if (task == 1) {         // lhs_t[b,t,n] = sum_c tmp_t[b,c,t]*taW2[c,n]
        int idx = blockIdx.x * 128 + tid;
        if (idx >= Bz * Tt * Nn) return;
        int n = idx % Nn, bt = idx / Nn;
        int t = bt % Tt, b = bt / Tt;
        const float* tp = d_tmp_t + ((long)b * Cc) * Tt + t;
        float a0 = 0.f, a1 = 0.f, a2 = 0.f, a3 = 0.f;
        #pragma unroll 4
        for (int c = 0; c < Cc; c += 4) {
            a0 += tp[(c)     * Tt] * taW2[(c)     * Nn + n];
            a1 += tp[(c + 1) * Tt] * taW2[(c + 1) * Nn + n];
            a2 += tp[(c + 2) * Tt] * taW2[(c + 2) * Nn + n];
            a3 += tp[(c + 3) * Tt] * taW2[(c + 3) * Nn + n];
        }
        d_lhs_t[idx] = (a0 + a1) + (a2 + a3);
    } else {                        // channel attention, 2 (b,c) units per block
        int bc2 = blockIdx.x;
        if (bc2 >= (Bz * Cc) / 2) return;
        int unit = tid >> 6, d = tid & 63;
        int bc = bc2 * 2 + unit;
        int b = bc / Cc;
        float* sh = smem_s + unit * 64;
        float dot = 0.f;
        const float* L = d_lhs_c + bc * Tt;
        const float* R = d_rhs_c + (b * Cc + d) * Tt;
        #pragma unroll
        for (int t = 0; t < Tt; t++) dot += L[t] * R[t];
        sh[d] = dot;
        __syncthreads();
        float m = -1e38f;
        for (int i = 0; i < O3; i++) m = fmaxf(m, sh[i]);
        float e = expf(dot - m);
        __syncthreads();
        sh[d] = e;
        __syncthreads();
        float s = 0.f;
        for (int i = 0; i < O3; i++) s += sh[i];
        d_att_c[bc * O3 + d] = e / s;
    }
}

// ---------------- stage3: k_M | att_t | transpose att_g ----------------
__global__ void k_small3(const float* __restrict__ ccW) {
    int task = blockIdx.y;
    int tid = threadIdx.x;          // 256
    if (task == 0) {
        int idx = blockIdx.x * 256 + tid;
        if (idx >= Bz * O3 * O3) return;
        int dd = idx % O3, o = (idx / O3) % O3, b = idx / (O3 * O3);
        const float* ap = d_att_c + ((long)b * Cc) * O3 + dd;
        float a0 = 0.f, a1 = 0.f, a2 = 0.f, a3 = 0.f;
        #pragma unroll 4
        for (int c = 0; c < Cc; c += 4) {
            a0 += ccW[o * Cc + c]     * ap[(c)     * O3];
            a1 += ccW[o * Cc + c + 1] * ap[(c + 1) * O3];
            a2 += ccW[o * Cc + c + 2] * ap[(c + 2) * O3];
            a3 += ccW[o * Cc + c + 3] * ap[(c + 3) * O3];
        }
        d_M[idx] = (a0 + a1) + (a2 + a3);
    } else if (task == 1) {
        int w = blockIdx.x * 8 + (tid >> 5);
        if (w >= Bz * Tt) return;
        int lane = tid & 31;
        int b = w / Tt;
        float dot = -INFINITY;
        if (lane < Tt) {
            dot = 0.f;
            const float* L = d_lhs_t + (long)w * Nn;
            const float* R = d_rhs_t + (long)b * Nn * Tt + lane;
            for (int n = 0; n < Nn; n++) dot += L[n] * R[n * Tt];
        }
        float m = dot;
        #pragma unroll
        for (int o = 16; o; o >>= 1) m = fmaxf(m, __shfl_xor_sync(~0u, m, o));
        float e = (lane < Tt) ? expf(dot - m) : 0.f;
        float su = e;
        #pragma unroll
        for (int o = 16; o; o >>= 1) su += __shfl_xor_sync(~0u, su, o);
        if (lane < Tt) d_att_t[w * Tt + lane] = e / su;
    } else {
        int blk = blockIdx.x;
        if (blk >= 3200) return;
        __shared__ float tile[32][33];
        int bx = blk % 10, by = (blk / 10) % 10, b = blk / 100;
        int x0 = bx * 32, y0 = by * 32;
        const float* A = d_att_g + (long)b * Nn * Nn;
        float* AT = d_attT + (long)b * Nn * Nn;
        int tx = tid & 31, ty = tid >> 5;
        #pragma unroll
        for (int i = 0; i < 4; i++) {
            int y = y0 + ty + i * 8, xx = x0 + tx;
            if (y < Nn && xx < Nn) tile[ty + i * 8][tx] = A[(long)y * Nn + xx];
        }
        __syncthreads();
        #pragma unroll
        for (int i = 0; i < 4; i++) {
            int y = x0 + ty + i * 8, xx = y0 + tx;
            if (y < Nn && xx < Nn) AT[(long)y * Nn + xx] = tile[tx][ty + i * 8];
        }
    }
}

// ---------------- apply temporal attention -> bufA ----------------
__global__ void k_apply_t() {
    int warp = (blockIdx.x * blockDim.x + threadIdx.x) >> 5;
    int lane = threadIdx.x & 31;
    if (warp >= BCN) return;
    int b = warp / (Cc * Nn);
    long row = (long)warp * Tt;
    float hv = (lane < Tt) ? d_h[row + lane] : 0.f;
    float acc = 0.f;
    const float* arow = d_att_t + (b * Tt + (lane < Tt ? lane : 0)) * Tt;
    #pragma unroll
    for (int s = 0; s < Tt; s++) {
        float hs = __shfl_sync(~0u, hv, s);
        acc += arow[s] * hs;
    }
    if (lane < Tt) d_bufA[row + lane] = acc;
}

// ---------------- 4-tap combined causal conv + residual[64:128] + relu ----------------
__global__ void __launch_bounds__(256, 2)
k_conv4res(const float* __restrict__ resW, const float* __restrict__ resb,
           const float* __restrict__ x, float* __restrict__ out) {
    int b = blockIdx.z, og = blockIdx.y;
    int p0 = blockIdx.x * 1024 + threadIdx.x * 4;
    __shared__ __align__(16) float Ws[4][Cc][16], Rs[Cc][16];
    for (int i = threadIdx.x; i < 16 * Cc; i += 256) {
        int o = i & 15, c = i >> 4;
        #pragma unroll
        for (int k = 0; k < 4; k++)
            Ws[k][c][o] = d_Wc[k * O3 * Cc + (og * 16 + o) * Cc + c];
        Rs[c][o] = resW[(64 + og * 16 + o) * Cc + c];
    }
    __syncthreads();
    if (p0 >= NT) return;
    int t0 = p0 % Tt;
    const float* Zb = d_bufA + (long)b * Cc * NT + p0;
    const float* xb = x + (long)b * Cc * NT + p0;
    u64 acc2[8][4] = {};
    for (int c = 0; c < Cc; c++) {
        const float* Zc = Zb + (long)c * NT;
        float4 cur = *(const float4*)Zc;
        float4 prv = make_float4(0.f, 0.f, 0.f, 0.f);
        if (t0 > 0) prv = *(const float4*)(Zc - 4);
        float4 xv = *(const float4*)(xb + (long)c * NT);
        u64 z0 = pk2(prv.y), z1 = pk2(prv.z), z2 = pk2(prv.w);
        u64 z3 = pk2(cur.x), z4 = pk2(cur.y), z5 = pk2(cur.z), z6 = pk2(cur.w);
        u64 xr0 = pk2(xv.x), xr1 = pk2(xv.y), xr2 = pk2(xv.z), xr3 = pk2(xv.w);
        const u64* W0r = (const u64*)Ws[0][c];
        const u64* W1r = (const u64*)Ws[1][c];
        const u64* W2r = (const u64*)Ws[2][c];
        const u64* W3r = (const u64*)Ws[3][c];
        const u64* Rr  = (const u64*)Rs[c];
        #pragma unroll
        for (int o2 = 0; o2 < 8; o2++) {
            u64 w0 = W0r[o2], w1 = W1r[o2], w2 = W2r[o2], w3 = W3r[o2], ar = Rr[o2];
            fma2(acc2[o2][0], w0, z3); fma2(acc2[o2][0], w1, z2);
            fma2(acc2[o2][0], w2, z1); fma2(acc2[o2][0], w3, z0);
            fma2(acc2[o2][0], ar, xr0);
            fma2(acc2[o2][1], w0, z4); fma2(acc2[o2][1], w1, z3);
            fma2(acc2[o2][1], w2, z2); fma2(acc2[o2][1], w3, z1);
            fma2(acc2[o2][1], ar, xr1);
            fma2(acc2[o2][2], w0, z5); fma2(acc2[o2][2], w1, z4);
            fma2(acc2[o2][2], w2, z3); fma2(acc2[o2][2], w3, z2);
            fma2(acc2[o2][2], ar, xr2);
            fma2(acc2[o2][3], w0, z6); fma2(acc2[o2][3], w1, z5);
            fma2(acc2[o2][3], w2, z4); fma2(acc2[o2][3], w3, z3);
            fma2(acc2[o2][3], ar, xr3);
        }
    }
    #pragma unroll
    for (int o2 = 0; o2 < 8; o2++) {
        float2 v0 = unpk(acc2[o2][0]), v1 = unpk(acc2[o2][1]);
        float2 v2 = unpk(acc2[o2][2]), v3 = unpk(acc2[o2][3]);
        #pragma unroll
        for (int par = 0; par < 2; par++) {
            int o = og * 16 + o2 * 2 + par;
            float4 v = par ? make_float4(v0.y, v1.y, v2.y, v3.y)
                           : make_float4(v0.x, v1.x, v2.x, v3.x);
            float rb  = resb[64 + o];
            float bhi = d_bhi[o] + rb;
            float blo = d_blo[o] + rb;
            float ba = (t0 == 0) ? blo : bhi;   // t0, t0+1
            v.x = fmaxf(v.x + ba,  0.f); v.y = fmaxf(v.y + ba,  0.f);
            v.z = fmaxf(v.z + bhi, 0.f); v.w = fmaxf(v.w + bhi, 0.f);
            *(float4*)(out + ((long)b * CO + 64 + o) * NT + p0) = v;
        }
    }
}

// ---------------- C-branch: out[0:64] = relu(M_b@h + resW0@x + biases) ----------------
__global__ void __launch_bounds__(256, 2)
k_cmix(const float* __restrict__ resW, const float* __restrict__ resb,
       const float* __restrict__ ccb, const float* __restrict__ x,
       float* __restrict__ out) {
    int b = blockIdx.z, og = blockIdx.y;
    int p0 = blockIdx.x * 1024 + threadIdx.x * 4;
    __shared__ __align__(16) float Ms[Cc][16], Rs[Cc][16];
    const float* Mb = d_M + (long)b * O3 * Cc;
    for (int i = threadIdx.x; i < 16 * Cc; i += 256) {
        int o = i & 15, c = i >> 4;
        Ms[c][o] = Mb[(og * 16 + o) * Cc + c];
        Rs[c][o] = resW[(og * 16 + o) * Cc + c];
    }
    __syncthreads();
    if (p0 >= NT) return;
    const float* Hb = d_h + (long)b * Cc * NT + p0;
    const float* xb = x + (long)b * Cc * NT + p0;
    u64 acc2[8][4] = {};
    for (int c = 0; c < Cc; c++) {
        float4 hv = *(const float4*)(Hb + (long)c * NT);
        float4 xv = *(const float4*)(xb + (long)c * NT);
        u64 hp0 = pk2(hv.x), hp1 = pk2(hv.y), hp2 = pk2(hv.z), hp3 = pk2(hv.w);
        u64 xp0 = pk2(xv.x), xp1 = pk2(xv.y), xp2 = pk2(xv.z), xp3 = pk2(xv.w);
        const u64* Mr = (const u64*)Ms[c];
        const u64* Rr = (const u64*)Rs[c];
        #pragma unroll
        for (int o2 = 0; o2 < 8; o2++) {
            u64 am = Mr[o2], ar = Rr[o2];
            fma2(acc2[o2][0], am, hp0); fma2(acc2[o2][0], ar, xp0);
            fma2(acc2[o2][1], am, hp1); fma2(acc2[o2][1], ar, xp1);
            fma2(acc2[o2][2], am, hp2); fma2(acc2[o2][2], ar, xp2);
            fma2(acc2[o2][3], am, hp3); fma2(acc2[o2][3], ar, xp3);
        }
    }
    #pragma unroll
    for (int o2 = 0; o2 < 8; o2++) {
        float2 v0 = unpk(acc2[o2][0]), v1 = unpk(acc2[o2][1]);
        float2 v2 = unpk(acc2[o2][2]), v3 = unpk(acc2[o2][3]);
        #pragma unroll
        for (int par = 0; par < 2; par++) {
            int o = og * 16 + o2 * 2 + par;
            float4 v = par ? make_float4(v0.y, v1.y, v2.y, v3.y)
                           : make_float4(v0.x, v1.x, v2.x, v3.x);
            float bb = ccb[o] + resb[o];
            v.x = fmaxf(v.x + bb, 0.f); v.y = fmaxf(v.y + bb, 0.f);
            v.z = fmaxf(v.z + bb, 0.f); v.w = fmaxf(v.w + bb, 0.f);
            *(float4*)(out + ((long)b * CO + o) * NT + p0) = v;
        }
    }
}

// ---------------- generic channel-mix ----------------
__global__ void __launch_bounds__(256, 2)
k_mix(const float* __restrict__ A, const float* __restrict__ X,
      const float* __restrict__ bias, float* __restrict__ out,
      int Ototal, int chOff, int flags) {
    int b = blockIdx.z, og = blockIdx.y;
    int p0 = blockIdx.x * 1024 + threadIdx.x * 4;
    __shared__ __align__(16) float As[Cc][16];
    for (int i = threadIdx.x; i < 16 * Cc; i += 256) {
        int o = i & 15, c = i >> 4;
        As[c][o] = A[(og * 16 + o) * Cc + c];
    }
    __syncthreads();
    if (p0 >= NT) return;
    const float* Xb = X + (long)b * Cc * NT + p0;
    u64 acc2[8][4] = {};
    for (int c = 0; c < Cc; c++) {
        float4 xv = *(const float4*)(Xb + (long)c * NT);
        u64 xp0 = pk2(xv.x), xp1 = pk2(xv.y), xp2 = pk2(xv.z), xp3 = pk2(xv.w);
        const u64* Arow = (const u64*)As[c];
        #pragma unroll
        for (int o2 = 0; o2 < 8; o2++) {
            u64 a2 = Arow[o2];
            fma2(acc2[o2][0], a2, xp0);
            fma2(acc2[o2][1], a2, xp1);
            fma2(acc2[o2][2], a2, xp2);
            fma2(acc2[o2][3], a2, xp3);
        }
    }
    #pragma unroll
    for (int o2 = 0; o2 < 8; o2++) {
        float2 v0 = unpk(acc2[o2][0]), v1 = unpk(acc2[o2][1]);
        float2 v2 = unpk(acc2[o2][2]), v3 = unpk(acc2[o2][3]);
        #pragma unroll
        for (int par = 0; par < 2; par++) {
            int o = og * 16 + o2 * 2 + par;
            float4 v = par ? make_float4(v0.y, v1.y, v2.y, v3.y)
                           : make_float4(v0.x, v1.x, v2.x, v3.x);
            if (flags & F_BIAS) {
                float bb = bias[o];
                v.x += bb; v.y += bb; v.z += bb; v.w += bb;
            }
            long oi = (flags & F_COMPACT)
                    ? ((long)b * Ototal + o) * NT + p0
                    : ((long)b * CO + chOff + o) * NT + p0;
            if (flags & F_ADD) {
                float4 r = *(const float4*)(out + oi);
                v.x += r.x; v.y += r.y; v.z += r.z; v.w += r.w;
            }
            if (flags & F_RELU) {
                v.x = fmaxf(v.x, 0.f); v.y = fmaxf(v.y, 0.f);
                v.z = fmaxf(v.z, 0.f); v.w = fmaxf(v.w, 0.f);
            }
            *(float4*)(out + oi) = v;
        }
    }
}

// ---------------- graph apply GEMM + residual add + relu (reads bufB) ----------------
#define GCS 428

__global__ void __launch_bounds__(256, 2) k_gapply(float* __restrict__ out) {
    int b = blockIdx.z;
    int n0 = blockIdx.x * 64;
    int cbase = blockIdx.y * 8;
    int tid = threadIdx.x;
    int cl = tid & 7, tq = (tid >> 3) & 3, ty = tid >> 5;
    int t0 = tq * 6;
    __shared__ __align__(16) u64 att2_s[16][64];
    __shared__ __align__(16) float gh_s[8 * GCS];
    u64 acc2[8][3] = {};
    const float* ATb = d_attT + (long)b * Nn * Nn;
    const float* GHb = d_bufB + ((long)b * Cc + cbase) * (long)Nn * Tt;
    for (int m0 = 0; m0 < Nn; m0 += 16) {
        #pragma unroll
        for (int i = tid; i < 1024; i += 256) {
            int mk = i >> 6, nl = i & 63;
            float v = 0.f;
            if (m0 + mk < Nn && n0 + nl < Nn) v = ATb[(long)(m0 + mk) * Nn + n0 + nl];
            att2_s[mk][nl] = pk2(v);
        }
        #pragma unroll
        for (int i = tid; i < 3072; i += 256) {
            int c2 = i / 384, r = i - c2 * 384;
            int mk = r / 24, t = r - mk * 24;
            float v = 0.f;
            if (m0 + mk < Nn) v = GHb[((long)c2 * Nn + m0 + mk) * Tt + t];
            gh_s[c2 * GCS + mk * 26 + t] = v;
        }
        __syncthreads();
        #pragma unroll
        for (int mk = 0; mk < 16; mk++) {
            const u64* ar = &att2_s[mk][ty * 8];
            const u64* gp = (const u64*)&gh_s[cl * GCS + mk * 26 + t0];
            u64 g0 = gp[0], g1 = gp[1], g2 = gp[2];
            #pragma unroll
            for (int j = 0; j < 8; j++) {
                u64 a = ar[j];
                fma2(acc2[j][0], a, g0);
                fma2(acc2[j][1], a, g1);
                fma2(acc2[j][2], a, g2);
            }
        }
        __syncthreads();
    }
    int ch = 128 + cbase + cl;
    #pragma unroll
    for (int j = 0; j < 8; j++) {
        int n = n0 + ty * 8 + j;
        if (n >= Nn) continue;
        long base = ((long)b * CO + ch) * NT + (long)n * Tt + t0;
        #pragma unroll
        for (int k = 0; k < 3; k++) {
            float2 v = unpk(acc2[j][k]);
            float2 r = *(const float2*)(out + base + k * 2);
            v.x = fmaxf(v.x + r.x, 0.f);
            v.y = fmaxf(v.y + r.y, 0.f);
            *(float2*)(out + base + k * 2) = v;
        }
    }
}

// ================================= launch =================================
extern "C" void kernel_launch(void* const* d_in, const int* in_sizes, int n_in,
                              void* d_out, int out_size) {
    const float* x     = (const float*)d_in[0];
    const int*   adj   = (const int*)  d_in[1];
    const float* ln_g  = (const float*)d_in[2];
    const float* ln_b  = (const float*)d_in[3];
    const float* res_W = (const float*)d_in[4];
    const float* res_b = (const float*)d_in[5];
    const float* ca_W1 = (const float*)d_in[6];
    const float* ca_W2 = (const float*)d_in[7];
    const float* ca_W3 = (const float*)d_in[8];
    const float* cc_W  = (const float*)d_in[9];
    const float* cc_b  = (const float*)d_in[10];
    const float* ta_W1 = (const float*)d_in[11];
    const float* ta_W2 = (const float*)d_in[12];
    const float* ta_W3 = (const float*)d_in[13];
    const float* tc_W0 = (const float*)d_in[14];
    const float* tc_b0 = (const float*)d_in[15];
    const float* tc_W1 = (const float*)d_in[16];
    const float* tc_b1 = (const float*)d_in[17];
    const float* ga_W1 = (const float*)d_in[18];
    const float* ga_W2 = (const float*)d_in[19];
    const float* ga_W3 = (const float*)d_in[20];
    const float* g_W   = (const float*)d_in[21];
    float* out = (float*)d_out;

    float *p_h, *p_bufB;
    cudaGetSymbolAddress((void**)&p_h,    d_h);
    cudaGetSymbolAddress((void**)&p_bufB, d_bufB);

    int warpBlocks = (BCN + 7) / 8;

    // 1) combined conv weights (independent, tiny)
    k_wcomb<<<65, 256>>>(tc_W0, tc_b0, tc_W1, tc_b1);
    // 2) LayerNorm + fused ca/ga T-dots
    k_ln<<<warpBlocks, 256>>>(x, ln_g, ln_b, ca_W1, ga_W1);
    // 3) glue reductions (paired h passes)
    k_stage1<<<dim3(921, 4), 256>>>(ca_W3, ta_W1, ta_W3, ga_W3, ca_W2, ga_W2);
    // 4) att_g | lhs_t | att_c
    k_small2<<<dim3(Bz * Nn, 3), 128>>>(adj, ta_W2);
    // 5) k_M | att_t | transpose(att_g)
    k_small3<<<dim3(3200, 3), 256>>>(cc_W);
    // 6) temporal attention apply -> bufA
    k_apply_t<<<warpBlocks, 256>>>();
    // 7) gh = g_W @ h -> bufB (compact)
    k_mix<<<dim3(8, 4, Bz), 256>>>(g_W, p_h, nullptr, p_bufB, O3, 0, F_COMPACT);
    // 8) 4-tap combined conv + residual[64:128] + relu -> out
    k_conv4res<<<dim3(8, 4, Bz), 256>>>(res_W, res_b, x, out);
    // 9) C branch: M@h + residual[0:64] + relu -> out
    k_cmix<<<dim3(8, 4, Bz), 256>>>(res_W, res_b, cc_b, x, out);
    // 10) residual base for G channels [128:192]
    k_mix<<<dim3(8, 4, Bz), 256>>>(res_W + (long)128 * Cc, x, res_b + 128, out,
                                   CO, 128, F_BIAS);
    // 11) graph apply GEMM + add + relu
    k_gapply<<<dim3(5, 8, Bz), 256>>>(out);

    (void)in_sizes; (void)n_in; (void)out_size;
}

// round 7
// speedup vs baseline: 2.0683x; 1.0086x over previous
#include <cuda_runtime.h>
#include <math.h>

#define Bz 32
#define Cc 64
#define Nn 307
#define Tt 24
#define NT 7368            // Nn*Tt
#define O3 64
#define CO 192
#define QW (O3*Tt)         // 1536 flattened (ch,t)
#define BCN (Bz*Cc*Nn)     // 628736
#define BCNT (Bz*Cc*NT)

typedef unsigned long long u64;

// ---------------- scratch ----------------
__device__ float d_h[BCNT];
__device__ float d_bufA[BCNT];          // apply_t output [b][c][n][t]
__device__ float d_gh[BCNT];            // g_W@h in [b][m][ch][t] layout
__device__ float d_tca[Bz*Cc*Nn];
__device__ float d_tga[Bz*Cc*Nn];
__device__ float d_lhs_c[Bz*Cc*Tt];
__device__ float d_rhs_c[Bz*Cc*Tt];
__device__ float d_tmp_t[Bz*Cc*Tt];
__device__ float d_lhs_t[Bz*Tt*Nn];
__device__ float d_rhs_t[Bz*Nn*Tt];
__device__ float d_lhs_g[Bz*Nn*Tt];
__device__ float d_rhs_g[Bz*Nn*Tt];
__device__ float d_att_c[Bz*Cc*Cc];
__device__ float d_att_t[Bz*Tt*Tt];
__device__ float d_att_g[Bz*Nn*Nn];     // scores -> softmaxed in place
__device__ float d_M[Bz*O3*O3];
__device__ float d_Wc[4*O3*Cc];
__device__ float d_bhi[O3];
__device__ float d_blo[O3];

// -------- packed f32x2 helpers --------
__device__ __forceinline__ void fma2(u64& d, u64 a, u64 b) {
    asm("fma.rn.f32x2 %0, %1, %2, %0;" : "+l"(d) : "l"(a), "l"(b));
}
__device__ __forceinline__ u64 pk2(float x) {
    u64 r; unsigned xi = __float_as_uint(x);
    asm("mov.b64 %0, {%1, %1};" : "=l"(r) : "r"(xi));
    return r;
}
__device__ __forceinline__ float2 unpk(u64 v) {
    unsigned lo, hi;
    asm("mov.b64 {%0, %1}, %2;" : "=r"(lo), "=r"(hi) : "l"(v));
    return make_float2(__uint_as_float(lo), __uint_as_float(hi));
}

// ---------------- LayerNorm + fused ca/ga T-dots ----------------
__global__ void k_ln(const float* __restrict__ x, const float* __restrict__ g,
                     const float* __restrict__ be,
                     const float* __restrict__ caW1, const float* __restrict__ gaW1) {
    int warp = (blockIdx.x * blockDim.x + threadIdx.x) >> 5;
    int lane = threadIdx.x & 31;
    if (warp >= BCN) return;
    const float* row = x + (long)warp * Tt;
    float v = (lane < Tt) ? row[lane] : 0.f;
    float s = v, s2 = v * v;
    #pragma unroll
    for (int o = 16; o; o >>= 1) {
        s  += __shfl_xor_sync(~0u, s,  o);
        s2 += __shfl_xor_sync(~0u, s2, o);
    }
    float mu  = s * (1.f / Tt);
    float var = s2 * (1.f / Tt) - mu * mu;
    float inv = rsqrtf(var + 1e-5f);
    float hv = 0.f;
    if (lane < Tt) {
        hv = (v - mu) * inv * g[lane] + be[lane];
        d_h[(long)warp * Tt + lane] = hv;
    }
    float dca = (lane < Tt) ? hv * caW1[lane] : 0.f;
    float dga = (lane < Tt) ? hv * gaW1[lane] : 0.f;
    #pragma unroll
    for (int o = 16; o; o >>= 1) {
        dca += __shfl_xor_sync(~0u, dca, o);
        dga += __shfl_xor_sync(~0u, dga, o);
    }
    if (lane == 0) { d_tca[warp] = dca; d_tga[warp] = dga; }
}

// ---------------- combined conv weights ----------------
__global__ void k_wcomb(const float* __restrict__ tcW0, const float* __restrict__ tcb0,
                        const float* __restrict__ tcW1, const float* __restrict__ tcb1) {
    int idx = blockIdx.x * 256 + threadIdx.x;
    if (idx < 4 * O3 * Cc) {
        int c = idx & 63, o = (idx >> 6) & 63, k = idx >> 12;
        int a = (k < 2) ? 1 : 0;
        int bsel = (k == 0 || k == 2) ? 1 : 0;
        float s = 0.f;
        for (int j = 0; j < O3; j++)
            s += tcW1[(o * O3 + j) * 2 + a] * tcW0[(j * Cc + c) * 2 + bsel];
        d_Wc[idx] = s;
    } else if (idx < 4 * O3 * Cc + O3) {
        int o = idx - 4 * O3 * Cc;
        float s1 = 0.f, s0 = 0.f;
        for (int j = 0; j < O3; j++) {
            s1 += tcW1[(o * O3 + j) * 2 + 1] * tcb0[j];
            s0 += tcW1[(o * O3 + j) * 2 + 0] * tcb0[j];
        }
        d_blo[o] = s1 + tcb1[o];
        d_bhi[o] = s1 + s0 + tcb1[o];
    }
}

// ---------------- stage1: glue reductions ----------------
__global__ void k_stage1(const float* __restrict__ caW3, const float* __restrict__ taW1,
                         const float* __restrict__ taW3, const float* __restrict__ gaW3,
                         const float* __restrict__ caW2, const float* __restrict__ gaW2) {
    int task = blockIdx.y;
    int idx = blockIdx.x * 256 + threadIdx.x;
    if (task == 0) {
        if (idx >= Bz * Cc * Tt) return;
        int t = idx % Tt, bc = idx / Tt;
        const float* hp = d_h + (long)bc * Nn * Tt + t;
        float a0 = 0.f, a1 = 0.f, b0 = 0.f, b1 = 0.f;
        int n = 0;
        for (; n < 306; n += 2) {
            float h0 = hp[(n)     * Tt];
            float h1 = hp[(n + 1) * Tt];
            a0 += caW3[n] * h0;  b0 += taW1[n] * h0;
            a1 += caW3[n + 1] * h1;  b1 += taW1[n + 1] * h1;
        }
        { float h0 = hp[n * Tt]; a0 += caW3[n] * h0; b0 += taW1[n] * h0; }
        d_rhs_c[idx] = a0 + a1;
        d_tmp_t[idx] = b0 + b1;
    } else if (task == 1) {
        if (idx >= Bz * Nn * Tt) return;
        int t = idx % Tt, n = (idx / Tt) % Nn, b = idx / (Nn * Tt);
        const float* hp = d_h + (((long)b * Cc) * Nn + n) * Tt + t;
        float a0 = 0.f, a1 = 0.f, b0 = 0.f, b1 = 0.f;
        #pragma unroll 4
        for (int c = 0; c < Cc; c += 2) {
            float h0 = hp[(long)(c)     * Nn * Tt];
            float h1 = hp[(long)(c + 1) * Nn * Tt];
            a0 += taW3[c] * h0;  b0 += gaW3[c] * h0;
            a1 += taW3[c + 1] * h1;  b1 += gaW3[c + 1] * h1;
        }
        d_rhs_t[idx] = a0 + a1;
        d_rhs_g[idx] = b0 + b1;
    } else if (task == 2) {
        if (idx >= Bz * Cc * Tt) return;
        int t = idx % Tt, bc = idx / Tt;
        const float* tp = d_tca + (long)bc * Nn;
        float a0 = 0.f, a1 = 0.f, a2 = 0.f, a3 = 0.f;
        int n = 0;
        for (; n < 304; n += 4) {
            a0 += tp[n]     * caW2[(n)     * Tt + t];
            a1 += tp[n + 1] * caW2[(n + 1) * Tt + t];
            a2 += tp[n + 2] * caW2[(n + 2) * Tt + t];
            a3 += tp[n + 3] * caW2[(n + 3) * Tt + t];
        }
        for (; n < Nn; n++) a0 += tp[n] * caW2[n * Tt + t];
        d_lhs_c[idx] = (a0 + a1) + (a2 + a3);
    } else {
        if (idx >= Bz * Nn * Tt) return;
        int t = idx % Tt, bn = idx / Tt;
        int n = bn % Nn, b = bn / Nn;
        const float* tp = d_tga + (long)b * Cc * Nn + n;
        float a0 = 0.f, a1 = 0.f, a2 = 0.f, a3 = 0.f;
        #pragma unroll 4
        for (int c = 0; c < Cc; c += 4) {
            a0 += tp[(c)     * Nn] * gaW2[(c)     * Tt + t];
            a1 += tp[(c + 1) * Nn] * gaW2[(c + 1) * Tt + t];
            a2 += tp[(c + 2) * Nn] * gaW2[(c + 2) * Tt + t];
            a3 += tp[(c + 3) * Nn] * gaW2[(c + 3) * Tt + t];
        }
        d_lhs_g[idx] = (a0 + a1) + (a2 + a3);
    }
}

// ---------------- gh = g_W @ h, stored [b][n][o][t] ----------------
__global__ void __launch_bounds__(256, 2)
k_mixgh(const float* __restrict__ A) {
    int b = blockIdx.z, og = blockIdx.y;
    int p0 = blockIdx.x * 1024 + threadIdx.x * 4;
    __shared__ __align__(16) float As[Cc][16];
    for (int i = threadIdx.x; i < 16 * Cc; i += 256) {
        int o = i & 15, c = i >> 4;
        As[c][o] = A[(og * 16 + o) * Cc + c];
    }
    __syncthreads();
    if (p0 >= NT) return;
    int n = p0 / Tt, t0 = p0 % Tt;
    const float* Xb = d_h + (long)b * Cc * NT + p0;
    u64 acc2[8][4] = {};
    for (int c = 0; c < Cc; c++) {
        float4 xv = *(const float4*)(Xb + (long)c * NT);
        u64 xp0 = pk2(xv.x), xp1 = pk2(xv.y), xp2 = pk2(xv.z), xp3 = pk2(xv.w);
        const u64* Arow = (const u64*)As[c];
        #pragma unroll
        for (int o2 = 0; o2 < 8; o2++) {
            u64 a2 = Arow[o2];
            fma2(acc2[o2][0], a2, xp0);
            fma2(acc2[o2][1], a2, xp1);
            fma2(acc2[o2][2], a2, xp2);
            fma2(acc2[o2][3], a2, xp3);
        }
    }
    long nbase = ((long)b * Nn + n) * QW;
    #pragma unroll
    for (int o2 = 0; o2 < 8; o2++) {
        float2 v0 = unpk(acc2[o2][0]), v1 = unpk(acc2[o2][1]);
        float2 v2 = unpk(acc2[o2][2]), v3 = unpk(acc2[o2][3]);
        #pragma unroll
        for (int par = 0; par < 2; par++) {
            int o = og * 16 + o2 * 2 + par;
            float4 v = par ? make_float4(v0.y, v1.y, v2.y, v3.y)
                           : make_float4(v0.x, v1.x, v2.x, v3.x);
            *(float4*)(d_gh + nbase + o * Tt + t0) = v;
        }
    }
}

// ---------------- graph attention scores: S[b,n,m] = lhs_g[b,n,:]·rhs_g[b,m,:] ----------------
// block (n-tile 64, b); thread: mq=tid&15 (4 m), ny=tid>>4 (4 n)
__global__ void k_scoreG() {
    int b = blockIdx.y;
    int n0 = blockIdx.x * 64;
    int tid = threadIdx.x;
    int mq = tid & 15, ny = tid >> 4;
    __shared__ __align__(16) u64 lhs2[64][Tt];
    __shared__ __align__(16) float rhsT[Tt][64];
    for (int i = tid; i < 64 * Tt; i += 256) {
        int nl = i / Tt, k = i % Tt;
        float v = (n0 + nl < Nn) ? d_lhs_g[((long)b * Nn + n0 + nl) * Tt + k] : 0.f;
        lhs2[nl][k] = pk2(v);
    }
    for (int m0 = 0; m0 < Nn; m0 += 64) {
        __syncthreads();
        for (int i = tid; i < 64 * Tt; i += 256) {
            int ml = i / Tt, k = i % Tt;
            float v = (m0 + ml < Nn) ? d_rhs_g[((long)b * Nn + m0 + ml) * Tt + k] : 0.f;
            rhsT[k][ml] = v;
        }
        __syncthreads();
        u64 acc2[4][2] = {};
        #pragma unroll
        for (int k = 0; k < Tt; k++) {
            const u64* rp = (const u64*)&rhsT[k][mq * 4];
            u64 r0 = rp[0], r1 = rp[1];
            #pragma unroll
            for (int nl = 0; nl < 4; nl++) {
                u64 l = lhs2[ny * 4 + nl][k];
                fma2(acc2[nl][0], l, r0);
                fma2(acc2[nl][1], l, r1);
            }
        }
        #pragma unroll
        for (int nl = 0; nl < 4; nl++) {
            int n = n0 + ny * 4 + nl;
            if (n >= Nn) continue;
            long row = ((long)b * Nn + n) * Nn;
            #pragma unroll
            for (int mp = 0; mp < 2; mp++) {
                float2 v = unpk(acc2[nl][mp]);
                int m = m0 + mq * 4 + mp * 2;
                if (m < Nn) d_att_g[row + m] = v.x;
                if (m + 1 < Nn) d_att_g[row + m + 1] = v.y;
            }
        }
    }
}

// ---------------- masked softmax over m (block per (b,n)) ----------------
__global__ void k_softg(const int* __restrict__ adj) {
    int bn = blockIdx.x;
    int b = bn / Nn, n = bn % Nn;
    int tid = threadIdx.x;  // 128
    __shared__ float red[128];
    long row = ((long)b * Nn + n) * Nn;
    float sc[3];
    #pragma unroll
    for (int k = 0; k < 3; k++) {
        int m = tid + k * 128;
        sc[k] = -INFINITY;
        if (m < Nn)
            sc[k] = (adj[n * Nn + m] > 0) ? d_att_g[row + m] : -1e30f;
    }
    float lm = fmaxf(fmaxf(sc[0], sc[1]), sc[2]);
    red[tid] = lm; __syncthreads();
    for (int st = 64; st; st >>= 1) {
        if (tid < st) red[tid] = fmaxf(red[tid], red[tid + st]);
        __syncthreads();
    }
    float M = red[0]; __syncthreads();
    float ls = 0.f;
    #pragma unroll
    for (int k = 0; k < 3; k++) {
        int m = tid + k * 128;
        if (m < Nn) { sc[k] = expf(sc[k] - M); ls += sc[k]; }
    }
    red[tid] = ls; __syncthreads();
    for (int st = 64; st; st >>= 1) {
        if (tid < st) red[tid] += red[tid + st];
        __syncthreads();
    }
    float S = red[0];
    #pragma unroll
    for (int k = 0; k < 3; k++) {
        int m = tid + k * 128;
        if (m < Nn) d_att_g[row + m] = sc[k] / S;
    }
}

// ---------------- small2b: lhs_t | att_c ----------------
__global__ void k_small2b(const float* __restrict__ taW2) {
    __shared__ float smem_s[128];
    int task = blockIdx.y;
    int tid = threadIdx.x;  // 128
    if (task == 0) {
        int idx = blockIdx.x * 128 + tid;
        if (idx >= Bz * Tt * Nn) return;
        int n = idx % Nn, bt = idx / Nn;
        int t = bt % Tt, b = bt / Tt;
        const float* tp = d_tmp_t + ((long)b * Cc) * Tt + t;
        float a0 = 0.f, a1 = 0.f, a2 = 0.f, a3 = 0.f;
        #pragma unroll 4
        for (int c = 0; c < Cc; c += 4) {
            a0 += tp[(c)     * Tt] * taW2[(c)     * Nn + n];
            a1 += tp[(c + 1) * Tt] * taW2[(c + 1) * Nn + n];
            a2 += tp[(c + 2) * Tt] * taW2[(c + 2) * Nn + n];
            a3 += tp[(c + 3) * Tt] * taW2[(c + 3) * Nn + n];
        }
        d_lhs_t[idx] = (a0 + a1) + (a2 + a3);
    } else {
        int bc2 = blockIdx.x;
        if (bc2 >= (Bz * Cc) / 2) return;
        int unit = tid >> 6, d = tid & 63;
        int bc = bc2 * 2 + unit;
        int b = bc / Cc;
        float* sh = smem_s + unit * 64;
        float dot = 0.f;
        const float* L = d_lhs_c + bc * Tt;
        const float* R = d_rhs_c + (b * Cc + d) * Tt;
        #pragma unroll
        for (int t = 0; t < Tt; t++) dot += L[t] * R[t];
        sh[d] = dot;
        __syncthreads();
        float m = -1e38f;
        for (int i = 0; i < O3; i++) m = fmaxf(m, sh[i]);
        float e = expf(dot - m);
        __syncthreads();
        sh[d] = e;
        __syncthreads();
        float s = 0.f;
        for (int i = 0; i < O3; i++) s += sh[i];
        d_att_c[bc * O3 + d] = e / s;
    }
}

// ---------------- small3b: k_M | att_t ----------------
__global__ void k_small3b(const float* __restrict__ ccW) {
    int task = blockIdx.y;
    int tid = threadIdx.x;          // 256
    if (task == 0) {
        int idx = blockIdx.x * 256 + tid;
        if (idx >= Bz * O3 * O3) return;
        int dd = idx % O3, o = (idx / O3) % O3, b = idx / (O3 * O3);
        const float* ap = d_att_c + ((long)b * Cc) * O3 + dd;
        float a0 = 0.f, a1 = 0.f, a2 = 0.f, a3 = 0.f;
        #pragma unroll 4
        for (int c = 0; c < Cc; c += 4) {
            a0 += ccW[o * Cc + c]     * ap[(c)     * O3];
            a1 += ccW[o * Cc + c + 1] * ap[(c + 1) * O3];
            a2 += ccW[o * Cc + c + 2] * ap[(c + 2) * O3];
            a3 += ccW[o * Cc + c + 3] * ap[(c + 3) * O3];
        }
        d_M[idx] = (a0 + a1) + (a2 + a3);
    } else if (task == 1) {
        int w = blockIdx.x * 8 + (tid >> 5);
        if (w >= Bz * Tt) return;
        int lane = tid & 31;
        int b = w / Tt;
        float dot = -INFINITY;
        if (lane < Tt) {
            dot = 0.f;
            const float* L = d_lhs_t + (long)w * Nn;
            const float* R = d_rhs_t + (long)b * Nn * Tt + lane;
            for (int n = 0; n < Nn; n++) dot += L[n] * R[n * Tt];
        }
        float m = dot;
        #pragma unroll
        for (int o = 16; o; o >>= 1) m = fmaxf(m, __shfl_xor_sync(~0u, m, o));
        float e = (lane < Tt) ? expf(dot - m) : 0.f;
        float su = e;
        #pragma unroll
        for (int o = 16; o; o >>= 1) su += __shfl_xor_sync(~0u, su, o);
        if (lane < Tt) d_att_t[w * Tt + lane] = e / su;
    }
}

// ---------------- apply temporal attention -> bufA ----------------
__global__ void k_apply_t() {
    int warp = (blockIdx.x * blockDim.x + threadIdx.x) >> 5;
    int lane = threadIdx.x & 31;
    if (warp >= BCN) return;
    int b = warp / (Cc * Nn);
    long row = (long)warp * Tt;
    float hv = (lane < Tt) ? d_h[row + lane] : 0.f;
    float acc = 0.f;
    const float* arow = d_att_t + (b * Tt + (lane < Tt ? lane : 0)) * Tt;
    #pragma unroll
    for (int s = 0; s < Tt; s++) {
        float hs = __shfl_sync(~0u, hv, s);
        acc += arow[s] * hs;
    }
    if (lane < Tt) d_bufA[row + lane] = acc;
}

// ---------------- big fused kernel: conv4res | cmix | gres via blockIdx.y ----------------
__global__ void __launch_bounds__(256, 2)
k_big(const float* __restrict__ resW, const float* __restrict__ resb,
      const float* __restrict__ ccb, const float* __restrict__ x,
      float* __restrict__ out) {
    int b = blockIdx.z;
    int yy = blockIdx.y;
    int p0 = blockIdx.x * 1024 + threadIdx.x * 4;
    __shared__ __align__(16) float sm[5 * Cc * 16];

    if (yy < 4) {
        // ---- conv4res, og = yy ----
        int og = yy;
        float (*Ws)[Cc][16] = (float(*)[Cc][16])sm;           // [4][Cc][16]
        float (*Rs)[16] = (float(*)[16])(sm + 4 * Cc * 16);   // [Cc][16]
        for (int i = threadIdx.x; i < 16 * Cc; i += 256) {
            int o = i & 15, c = i >> 4;
            #pragma unroll
            for (int k = 0; k < 4; k++)
                Ws[k][c][o] = d_Wc[k * O3 * Cc + (og * 16 + o) * Cc + c];
            Rs[c][o] = resW[(64 + og * 16 + o) * Cc + c];
        }
        __syncthreads();
        if (p0 >= NT) return;
        int t0 = p0 % Tt;
        const float* Zb = d_bufA + (long)b * Cc * NT + p0;
        const float* xb = x + (long)b * Cc * NT + p0;
        u64 acc2[8][4] = {};
        for (int c = 0; c < Cc; c++) {
            const float* Zc = Zb + (long)c * NT;
            float4 cur = *(const float4*)Zc;
            float4 prv = make_float4(0.f, 0.f, 0.f, 0.f);
            if (t0 > 0) prv = *(const float4*)(Zc - 4);
            float4 xv = *(const float4*)(xb + (long)c * NT);
            u64 z0 = pk2(prv.y), z1 = pk2(prv.z), z2 = pk2(prv.w);
            u64 z3 = pk2(cur.x), z4 = pk2(cur.y), z5 = pk2(cur.z), z6 = pk2(cur.w);
            u64 xr0 = pk2(xv.x), xr1 = pk2(xv.y), xr2 = pk2(xv.z), xr3 = pk2(xv.w);
            const u64* W0r = (const u64*)Ws[0][c];
            const u64* W1r = (const u64*)Ws[1][c];
            const u64* W2r = (const u64*)Ws[2][c];
            const u64* W3r = (const u64*)Ws[3][c];
            const u64* Rr  = (const u64*)Rs[c];
            #pragma unroll
            for (int o2 = 0; o2 < 8; o2++) {
                u64 w0 = W0r[o2], w1 = W1r[o2], w2 = W2r[o2], w3 = W3r[o2], ar = Rr[o2];
                fma2(acc2[o2][0], w0, z3); fma2(acc2[o2][0], w1, z2);
                fma2(acc2[o2][0], w2, z1); fma2(acc2[o2][0], w3, z0);
                fma2(acc2[o2][0], ar, xr0);
                fma2(acc2[o2][1], w0, z4); fma2(acc2[o2][1], w1, z3);
                fma2(acc2[o2][1], w2, z2); fma2(acc2[o2][1], w3, z1);
                fma2(acc2[o2][1], ar, xr1);
                fma2(acc2[o2][2], w0, z5); fma2(acc2[o2][2], w1, z4);
                fma2(acc2[o2][2], w2, z3); fma2(acc2[o2][2], w3, z2);
                fma2(acc2[o2][2], ar, xr2);
                fma2(acc2[o2][3], w0, z6); fma2(acc2[o2][3], w1, z5);
                fma2(acc2[o2][3], w2, z4); fma2(acc2[o2][3], w3, z3);
                fma2(acc2[o2][3], ar, xr3);
            }
        }
        #pragma unroll
        for (int o2 = 0; o2 < 8; o2++) {
            float2 v0 = unpk(acc2[o2][0]), v1 = unpk(acc2[o2][1]);
            float2 v2 = unpk(acc2[o2][2]), v3 = unpk(acc2[o2][3]);
            #pragma unroll
            for (int par = 0; par < 2; par++) {
                int o = og * 16 + o2 * 2 + par;
                float4 v = par ? make_float4(v0.y, v1.y, v2.y, v3.y)
                               : make_float4(v0.x, v1.x, v2.x, v3.x);
                float rb  = resb[64 + o];
                float bhi = d_bhi[o] + rb;
                float blo = d_blo[o] + rb;
                float ba = (t0 == 0) ? blo : bhi;
                v.x = fmaxf(v.x + ba,  0.f); v.y = fmaxf(v.y + ba,  0.f);
                v.z = fmaxf(v.z + bhi, 0.f); v.w = fmaxf(v.w + bhi, 0.f);
                *(float4*)(out + ((long)b * CO + 64 + o) * NT + p0) = v;
            }
        }
    } else {
        // ---- cmix (yy 4..7) or gres (yy 8..11) ----
        int og = yy & 3;
        bool isC = yy < 8;
        float (*As)[16] = (float(*)[16])sm;                   // [Cc][16]
        float (*Rs)[16] = (float(*)[16])(sm + Cc * 16);       // [Cc][16] (cmix only)
        const float* Mb = d_M + (long)b * O3 * Cc;
        for (int i = threadIdx.x; i < 16 * Cc; i += 256) {
            int o = i & 15, c = i >> 4;
            if (isC) {
                As[c][o] = Mb[(og * 16 + o) * Cc + c];
                Rs[c][o] = resW[(og * 16 + o) * Cc + c];
            } else {
                As[c][o] = resW[(128 + og * 16 + o) * Cc + c];
            }
        }
        __syncthreads();
        if (p0 >= NT) return;
        const float* Hb = d_h + (long)b * Cc * NT + p0;
        const float* xb = x + (long)b * Cc * NT + p0;
        u64 acc2[8][4] = {};
        if (isC) {
            for (int c = 0; c < Cc; c++) {
                float4 hv = *(const float4*)(Hb + (long)c * NT);
                float4 xv = *(const float4*)(xb + (long)c * NT);
                u64 hp0 = pk2(hv.x), hp1 = pk2(hv.y), hp2 = pk2(hv.z), hp3 = pk2(hv.w);
                u64 xp0 = pk2(xv.x), xp1 = pk2(xv.y), xp2 = pk2(xv.z), xp3 = pk2(xv.w);
                const u64* Mr = (const u64*)As[c];
                const u64* Rr = (const u64*)Rs[c];
                #pragma unroll
                for (int o2 = 0; o2 < 8; o2++) {
                    u64 am = Mr[o2], ar = Rr[o2];
                    fma2(acc2[o2][0], am, hp0); fma2(acc2[o2][0], ar, xp0);
                    fma2(acc2[o2][1], am, hp1); fma2(acc2[o2][1], ar, xp1);
                    fma2(acc2[o2][2], am, hp2); fma2(acc2[o2][2], ar, xp2);
                    fma2(acc2[o2][3], am, hp3); fma2(acc2[o2][3], ar, xp3);
                }
            }
        } else {
            for (int c = 0; c < Cc; c++) {
                float4 xv = *(const float4*)(xb + (long)c * NT);
                u64 xp0 = pk2(xv.x), xp1 = pk2(xv.y), xp2 = pk2(xv.z), xp3 = pk2(xv.w);
                const u64* Ar = (const u64*)As[c];
                #pragma unroll
                for (int o2 = 0; o2 < 8; o2++) {
                    u64 a2 = Ar[o2];
                    fma2(acc2[o2][0], a2, xp0);
                    fma2(acc2[o2][1], a2, xp1);
                    fma2(acc2[o2][2], a2, xp2);
                    fma2(acc2[o2][3], a2, xp3);
                }
            }
        }
        #pragma unroll
        for (int o2 = 0; o2 < 8; o2++) {
            float2 v0 = unpk(acc2[o2][0]), v1 = unpk(acc2[o2][1]);
            float2 v2 = unpk(acc2[o2][2]), v3 = unpk(acc2[o2][3]);
            #pragma unroll
            for (int par = 0; par < 2; par++) {
                int o = og * 16 + o2 * 2 + par;
                float4 v = par ? make_float4(v0.y, v1.y, v2.y, v3.y)
                               : make_float4(v0.x, v1.x, v2.x, v3.x);
                if (isC) {
                    float bb = ccb[o] + resb[o];
                    v.x = fmaxf(v.x + bb, 0.f); v.y = fmaxf(v.y + bb, 0.f);
                    v.z = fmaxf(v.z + bb, 0.f); v.w = fmaxf(v.w + bb, 0.f);
                    *(float4*)(out + ((long)b * CO + o) * NT + p0) = v;
                } else {
                    float bb = resb[128 + o];
                    v.x += bb; v.y += bb; v.z += bb; v.w += bb;
                    *(float4*)(out + ((long)b * CO + 128 + o) * NT + p0) = v;
                }
            }
        }
    }
}

// ---------------- graph apply: C[n,q] = sum_m att[n,m]*gh[m,q], q=(ch,t) ----------------
// grid (q-tile 6x256, n-tile 5x64, b); thread: tx=tid&31 (8 q), ty=tid>>5 (8 n)
__global__ void __launch_bounds__(256, 2) k_gapply(float* __restrict__ out) {
    int b = blockIdx.z;
    int q0 = blockIdx.x * 256;
    int n0 = blockIdx.y * 64;
    int tid = threadIdx.x;
    int tx = tid & 31, ty = tid >> 5;
    __shared__ __align__(16) u64 att2[64][16];
    __shared__ __align__(16) float Gs[16][256];
    u64 acc2[8][4] = {};
    const float* Ab = d_att_g + (long)b * Nn * Nn;
    const float* Gb = d_gh + (long)b * Nn * QW;
    for (int m0 = 0; m0 < Nn; m0 += 16) {
        {   // fill att2: 1024 u64, 4 per thread
            int i = tid * 4;
            int row = i >> 4, k0 = i & 15;
            int n = n0 + row;
            #pragma unroll
            for (int j = 0; j < 4; j++) {
                float v = 0.f;
                int m = m0 + k0 + j;
                if (n < Nn && m < Nn) v = Ab[(long)n * Nn + m];
                att2[row][k0 + j] = pk2(v);
            }
        }
        // fill Gs: 4096 floats, 16 per thread (4x float4)
        #pragma unroll
        for (int i = tid; i < 1024; i += 256) {
            int k = i >> 6, qq = (i & 63) * 4;
            float4 v = make_float4(0.f, 0.f, 0.f, 0.f);
            if (m0 + k < Nn)
                v = *(const float4*)(Gb + (long)(m0 + k) * QW + q0 + qq);
            *(float4*)&Gs[k][qq] = v;
        }
        __syncthreads();
        #pragma unroll
        for (int k = 0; k < 16; k++) {
            const u64* gp = (const u64*)&Gs[k][tx * 8];
            u64 g0 = gp[0], g1 = gp[1], g2 = gp[2], g3 = gp[3];
            #pragma unroll
            for (int j = 0; j < 8; j++) {
                u64 a = att2[ty * 8 + j][k];
                fma2(acc2[j][0], a, g0);
                fma2(acc2[j][1], a, g1);
                fma2(acc2[j][2], a, g2);
                fma2(acc2[j][3], a, g3);
            }
        }
        __syncthreads();
    }
    int q = q0 + tx * 8;
    int ch = q / Tt, t0 = q % Tt;       // 8 q stay within one ch (24%8==0)
    #pragma unroll
    for (int j = 0; j < 8; j++) {
        int n = n0 + ty * 8 + j;
        if (n >= Nn) continue;
        long base = ((long)b * CO + 128 + ch) * NT + (long)n * Tt + t0;
        float2 a0 = unpk(acc2[j][0]), a1 = unpk(acc2[j][1]);
        float2 a2 = unpk(acc2[j][2]), a3 = unpk(acc2[j][3]);
        float4 r0 = *(const float4*)(out + base);
        float4 r1 = *(const float4*)(out + base + 4);
        float4 w0, w1;
        w0.x = fmaxf(a0.x + r0.x, 0.f); w0.y = fmaxf(a0.y + r0.y, 0.f);
        w0.z = fmaxf(a1.x + r0.z, 0.f); w0.w = fmaxf(a1.y + r0.w, 0.f);
        w1.x = fmaxf(a2.x + r1.x, 0.f); w1.y = fmaxf(a2.y + r1.y, 0.f);
        w1.z = fmaxf(a3.x + r1.z, 0.f); w1.w = fmaxf(a3.y + r1.w, 0.f);
        *(float4*)(out + base) = w0;
        *(float4*)(out + base + 4) = w1;
    }
}

// ================================= launch =================================
extern "C" void kernel_launch(void* const* d_in, const int* in_sizes, int n_in,
                              void* d_out, int out_size) {
    const float* x     = (const float*)d_in[0];
    const int*   adj   = (const int*)  d_in[1];
    const float* ln_g  = (const float*)d_in[2];
    const float* ln_b  = (const float*)d_in[3];
    const float* res_W = (const float*)d_in[4];
    const float* res_b = (const float*)d_in[5];
    const float* ca_W1 = (const float*)d_in[6];
    const float* ca_W2 = (const float*)d_in[7];
    const float* ca_W3 = (const float*)d_in[8];
    const float* cc_W  = (const float*)d_in[9];
    const float* cc_b  = (const float*)d_in[10];
    const float* ta_W1 = (const float*)d_in[11];
    const float* ta_W2 = (const float*)d_in[12];
    const float* ta_W3 = (const float*)d_in[13];
    const float* tc_W0 = (const float*)d_in[14];
    const float* tc_b0 = (const float*)d_in[15];
    const float* tc_W1 = (const float*)d_in[16];
    const float* tc_b1 = (const float*)d_in[17];
    const float* ga_W1 = (const float*)d_in[18];
    const float* ga_W2 = (const float*)d_in[19];
    const float* ga_W3 = (const float*)d_in[20];
    const float* g_W   = (const float*)d_in[21];
    float* out = (float*)d_out;

    int warpBlocks = (BCN + 7) / 8;

    // 1) combined conv weights
    k_wcomb<<<65, 256>>>(tc_W0, tc_b0, tc_W1, tc_b1);
    // 2) LayerNorm + fused ca/ga T-dots
    k_ln<<<warpBlocks, 256>>>(x, ln_g, ln_b, ca_W1, ga_W1);
    // 3) glue reductions
    k_stage1<<<dim3(921, 4), 256>>>(ca_W3, ta_W1, ta_W3, ga_W3, ca_W2, ga_W2);
    // 4) gh = g_W @ h in [b][m][ch][t] layout   (ncu-profiled slot)
    k_mixgh<<<dim3(8, 4, Bz), 256>>>(g_W);
    // 5) graph attention scores (tiled GEMM)
    k_scoreG<<<dim3(5, Bz), 256>>>();
    // 6) masked softmax over scores
    k_softg<<<Bz * Nn, 128>>>(adj);
    // 7) lhs_t | att_c
    k_small2b<<<dim3(1842, 2), 128>>>(ta_W2);
    // 8) k_M | att_t
    k_small3b<<<dim3(512, 2), 256>>>(cc_W);
    // 9) temporal attention apply -> bufA
    k_apply_t<<<warpBlocks, 256>>>();
    // 10) fused: conv4res | cmix | G-residual
    k_big<<<dim3(8, 12, Bz), 256>>>(res_W, res_b, cc_b, x, out);
    // 11) graph apply GEMM + add + relu
    k_gapply<<<dim3(6, 5, Bz), 256>>>(out);

    (void)in_sizes; (void)n_in; (void)out_size;
}

// round 8
// speedup vs baseline: 2.0848x; 1.0080x over previous
#include <cuda_runtime.h>
#include <math.h>

#define Bz 32
#define Cc 64
#define Nn 307
#define Tt 24
#define NT 7368            // Nn*Tt
#define O3 64
#define CO 192
#define QW (O3*Tt)         // 1536 flattened (ch,t)
#define BCN (Bz*Cc*Nn)     // 628736
#define BCNT (Bz*Cc*NT)

typedef unsigned long long u64;

// ---------------- scratch ----------------
__device__ float d_h[BCNT];
__device__ float d_bufA[BCNT];          // apply_t output [b][c][n][t]
__device__ float d_gh[BCNT];            // g_W@h in [b][m][ch][t] layout
__device__ float d_tca[Bz*Cc*Nn];
__device__ float d_tga[Bz*Cc*Nn];
__device__ float d_lhs_c[Bz*Cc*Tt];
__device__ float d_rhs_c[Bz*Cc*Tt];
__device__ float d_tmp_t[Bz*Cc*Tt];
__device__ float d_lhs_t[Bz*Tt*Nn];
__device__ float d_rhs_t[Bz*Nn*Tt];
__device__ float d_lhs_g[Bz*Nn*Tt];
__device__ float d_rhs_g[Bz*Nn*Tt];
__device__ float d_att_c[Bz*Cc*Cc];
__device__ float d_att_t[Bz*Tt*Tt];
__device__ float d_att_g[Bz*Nn*Nn];     // scores -> softmaxed in place
__device__ float d_M[Bz*O3*O3];
__device__ float d_Wc[4*O3*Cc];
__device__ float d_bhi[O3];
__device__ float d_blo[O3];

// -------- packed f32x2 helpers --------
__device__ __forceinline__ void fma2(u64& d, u64 a, u64 b) {
    asm("fma.rn.f32x2 %0, %1, %2, %0;" : "+l"(d) : "l"(a), "l"(b));
}
__device__ __forceinline__ u64 pk2(float x) {
    u64 r; unsigned xi = __float_as_uint(x);
    asm("mov.b64 %0, {%1, %1};" : "=l"(r) : "r"(xi));
    return r;
}
__device__ __forceinline__ float2 unpk(u64 v) {
    unsigned lo, hi;
    asm("mov.b64 {%0, %1}, %2;" : "=r"(lo), "=r"(hi) : "l"(v));
    return make_float2(__uint_as_float(lo), __uint_as_float(hi));
}

// ---------------- LayerNorm + ca/ga T-dots + (tail blocks) conv-weight combine ----------------
__global__ void k_lnw(const float* __restrict__ x, const float* __restrict__ g,
                      const float* __restrict__ be,
                      const float* __restrict__ caW1, const float* __restrict__ gaW1,
                      const float* __restrict__ tcW0, const float* __restrict__ tcb0,
                      const float* __restrict__ tcW1, const float* __restrict__ tcb1,
                      int warpBlocks) {
    if ((int)blockIdx.x >= warpBlocks) {
        // ---- conv weight combine ----
        int idx = (blockIdx.x - warpBlocks) * 256 + threadIdx.x;
        if (idx < 4 * O3 * Cc) {
            int c = idx & 63, o = (idx >> 6) & 63, k = idx >> 12;
            int a = (k < 2) ? 1 : 0;
            int bsel = (k == 0 || k == 2) ? 1 : 0;
            float s = 0.f;
            for (int j = 0; j < O3; j++)
                s += tcW1[(o * O3 + j) * 2 + a] * tcW0[(j * Cc + c) * 2 + bsel];
            d_Wc[idx] = s;
        } else if (idx < 4 * O3 * Cc + O3) {
            int o = idx - 4 * O3 * Cc;
            float s1 = 0.f, s0 = 0.f;
            for (int j = 0; j < O3; j++) {
                s1 += tcW1[(o * O3 + j) * 2 + 1] * tcb0[j];
                s0 += tcW1[(o * O3 + j) * 2 + 0] * tcb0[j];
            }
            d_blo[o] = s1 + tcb1[o];
            d_bhi[o] = s1 + s0 + tcb1[o];
        }
        return;
    }
    int warp = (blockIdx.x * blockDim.x + threadIdx.x) >> 5;
    int lane = threadIdx.x & 31;
    if (warp >= BCN) return;
    const float* row = x + (long)warp * Tt;
    float v = (lane < Tt) ? row[lane] : 0.f;
    float s = v, s2 = v * v;
    #pragma unroll
    for (int o = 16; o; o >>= 1) {
        s  += __shfl_xor_sync(~0u, s,  o);
        s2 += __shfl_xor_sync(~0u, s2, o);
    }
    float mu  = s * (1.f / Tt);
    float var = s2 * (1.f / Tt) - mu * mu;
    float inv = rsqrtf(var + 1e-5f);
    float hv = 0.f;
    if (lane < Tt) {
        hv = (v - mu) * inv * g[lane] + be[lane];
        d_h[(long)warp * Tt + lane] = hv;
    }
    float dca = (lane < Tt) ? hv * caW1[lane] : 0.f;
    float dga = (lane < Tt) ? hv * gaW1[lane] : 0.f;
    #pragma unroll
    for (int o = 16; o; o >>= 1) {
        dca += __shfl_xor_sync(~0u, dca, o);
        dga += __shfl_xor_sync(~0u, dga, o);
    }
    if (lane == 0) { d_tca[warp] = dca; d_tga[warp] = dga; }
}

// ---------------- gh = g_W @ h, stored [b][n][o][t]; MLP-4 c-loop ----------------
__global__ void __launch_bounds__(256, 2)
k_mixgh(const float* __restrict__ A) {
    int b = blockIdx.z, og = blockIdx.y;
    int p0 = blockIdx.x * 1024 + threadIdx.x * 4;
    __shared__ __align__(16) float As[Cc][16];
    for (int i = threadIdx.x; i < 16 * Cc; i += 256) {
        int o = i & 15, c = i >> 4;
        As[c][o] = A[(og * 16 + o) * Cc + c];
    }
    __syncthreads();
    if (p0 >= NT) return;
    int n = p0 / Tt, t0 = p0 % Tt;
    const float* Xb = d_h + (long)b * Cc * NT + p0;
    u64 acc2[8][4] = {};
    auto step = [&](float4 xv, int c) {
        u64 xp0 = pk2(xv.x), xp1 = pk2(xv.y), xp2 = pk2(xv.z), xp3 = pk2(xv.w);
        const u64* Arow = (const u64*)As[c];
        #pragma unroll
        for (int o2 = 0; o2 < 8; o2++) {
            u64 a2 = Arow[o2];
            fma2(acc2[o2][0], a2, xp0);
            fma2(acc2[o2][1], a2, xp1);
            fma2(acc2[o2][2], a2, xp2);
            fma2(acc2[o2][3], a2, xp3);
        }
    };
    for (int c = 0; c < Cc; c += 4) {
        float4 x0 = *(const float4*)(Xb + (long)(c)     * NT);
        float4 x1 = *(const float4*)(Xb + (long)(c + 1) * NT);
        float4 x2 = *(const float4*)(Xb + (long)(c + 2) * NT);
        float4 x3 = *(const float4*)(Xb + (long)(c + 3) * NT);
        step(x0, c); step(x1, c + 1); step(x2, c + 2); step(x3, c + 3);
    }
    long nbase = ((long)b * Nn + n) * QW;
    #pragma unroll
    for (int o2 = 0; o2 < 8; o2++) {
        float2 v0 = unpk(acc2[o2][0]), v1 = unpk(acc2[o2][1]);
        float2 v2 = unpk(acc2[o2][2]), v3 = unpk(acc2[o2][3]);
        #pragma unroll
        for (int par = 0; par < 2; par++) {
            int o = og * 16 + o2 * 2 + par;
            float4 v = par ? make_float4(v0.y, v1.y, v2.y, v3.y)
                           : make_float4(v0.x, v1.x, v2.x, v3.x);
            *(float4*)(d_gh + nbase + o * Tt + t0) = v;
        }
    }
}

// ---------------- stage1: glue reductions ----------------
__global__ void k_stage1(const float* __restrict__ caW3, const float* __restrict__ taW1,
                         const float* __restrict__ taW3, const float* __restrict__ gaW3,
                         const float* __restrict__ caW2, const float* __restrict__ gaW2) {
    int task = blockIdx.y;
    int idx = blockIdx.x * 256 + threadIdx.x;
    if (task == 0) {
        if (idx >= Bz * Cc * Tt) return;
        int t = idx % Tt, bc = idx / Tt;
        const float* hp = d_h + (long)bc * Nn * Tt + t;
        float a0 = 0.f, a1 = 0.f, b0 = 0.f, b1 = 0.f;
        int n = 0;
        for (; n < 306; n += 2) {
            float h0 = hp[(n)     * Tt];
            float h1 = hp[(n + 1) * Tt];
            a0 += caW3[n] * h0;  b0 += taW1[n] * h0;
            a1 += caW3[n + 1] * h1;  b1 += taW1[n + 1] * h1;
        }
        { float h0 = hp[n * Tt]; a0 += caW3[n] * h0; b0 += taW1[n] * h0; }
        d_rhs_c[idx] = a0 + a1;
        d_tmp_t[idx] = b0 + b1;
    } else if (task == 1) {
        if (idx >= Bz * Nn * Tt) return;
        int t = idx % Tt, n = (idx / Tt) % Nn, b = idx / (Nn * Tt);
        const float* hp = d_h + (((long)b * Cc) * Nn + n) * Tt + t;
        float a0 = 0.f, a1 = 0.f, b0 = 0.f, b1 = 0.f;
        #pragma unroll 4
        for (int c = 0; c < Cc; c += 2) {
            float h0 = hp[(long)(c)     * Nn * Tt];
            float h1 = hp[(long)(c + 1) * Nn * Tt];
            a0 += taW3[c] * h0;  b0 += gaW3[c] * h0;
            a1 += taW3[c + 1] * h1;  b1 += gaW3[c + 1] * h1;
        }
        d_rhs_t[idx] = a0 + a1;
        d_rhs_g[idx] = b0 + b1;
    } else if (task == 2) {
        if (idx >= Bz * Cc * Tt) return;
        int t = idx % Tt, bc = idx / Tt;
        const float* tp = d_tca + (long)bc * Nn;
        float a0 = 0.f, a1 = 0.f, a2 = 0.f, a3 = 0.f;
        int n = 0;
        for (; n < 304; n += 4) {
            a0 += tp[n]     * caW2[(n)     * Tt + t];
            a1 += tp[n + 1] * caW2[(n + 1) * Tt + t];
            a2 += tp[n + 2] * caW2[(n + 2) * Tt + t];
            a3 += tp[n + 3] * caW2[(n + 3) * Tt + t];
        }
        for (; n < Nn; n++) a0 += tp[n] * caW2[n * Tt + t];
        d_lhs_c[idx] = (a0 + a1) + (a2 + a3);
    } else {
        if (idx >= Bz * Nn * Tt) return;
        int t = idx % Tt, bn = idx / Tt;
        int n = bn % Nn, b = bn / Nn;
        const float* tp = d_tga + (long)b * Cc * Nn + n;
        float a0 = 0.f, a1 = 0.f, a2 = 0.f, a3 = 0.f;
        #pragma unroll 4
        for (int c = 0; c < Cc; c += 4) {
            a0 += tp[(c)     * Nn] * gaW2[(c)     * Tt + t];
            a1 += tp[(c + 1) * Nn] * gaW2[(c + 1) * Tt + t];
            a2 += tp[(c + 2) * Nn] * gaW2[(c + 2) * Tt + t];
            a3 += tp[(c + 3) * Nn] * gaW2[(c + 3) * Tt + t];
        }
        d_lhs_g[idx] = (a0 + a1) + (a2 + a3);
    }
}

// ---------------- merged2: y=0 scoreG | y=1 lhs_t | y=2 att_c   (256 thr) ----------------
__global__ void k_merged2(const float* __restrict__ taW2) {
    __shared__ __align__(16) char smem_raw[64 * Tt * 8 + Tt * 64 * 4];
    int task = blockIdx.y;
    int tid = threadIdx.x;
    if (task == 0) {
        // scoreG: S[b,n,m] = lhs_g[b,n,:]·rhs_g[b,m,:], block n-tile 64
        if (blockIdx.x >= 5 * Bz) return;
        int b = blockIdx.x / 5;
        int n0 = (blockIdx.x % 5) * 64;
        int mq = tid & 15, ny = tid >> 4;
        u64 (*lhs2)[Tt] = (u64(*)[Tt])smem_raw;
        float (*rhsT)[64] = (float(*)[64])(smem_raw + 64 * Tt * 8);
        for (int i = tid; i < 64 * Tt; i += 256) {
            int nl = i / Tt, k = i % Tt;
            float v = (n0 + nl < Nn) ? d_lhs_g[((long)b * Nn + n0 + nl) * Tt + k] : 0.f;
            lhs2[nl][k] = pk2(v);
        }
        for (int m0 = 0; m0 < Nn; m0 += 64) {
            __syncthreads();
            for (int i = tid; i < 64 * Tt; i += 256) {
                int ml = i / Tt, k = i % Tt;
                float v = (m0 + ml < Nn) ? d_rhs_g[((long)b * Nn + m0 + ml) * Tt + k] : 0.f;
                rhsT[k][ml] = v;
            }
            __syncthreads();
            u64 acc2[4][2] = {};
            #pragma unroll
            for (int k = 0; k < Tt; k++) {
                const u64* rp = (const u64*)&rhsT[k][mq * 4];
                u64 r0 = rp[0], r1 = rp[1];
                #pragma unroll
                for (int nl = 0; nl < 4; nl++) {
                    u64 l = lhs2[ny * 4 + nl][k];
                    fma2(acc2[nl][0], l, r0);
                    fma2(acc2[nl][1], l, r1);
                }
            }
            #pragma unroll
            for (int nl = 0; nl < 4; nl++) {
                int n = n0 + ny * 4 + nl;
                if (n >= Nn) continue;
                long row = ((long)b * Nn + n) * Nn;
                #pragma unroll
                for (int mp = 0; mp < 2; mp++) {
                    float2 v = unpk(acc2[nl][mp]);
                    int m = m0 + mq * 4 + mp * 2;
                    if (m < Nn) d_att_g[row + m] = v.x;
                    if (m + 1 < Nn) d_att_g[row + m + 1] = v.y;
                }
            }
        }
    } else if (task == 1) {
        int idx = blockIdx.x * 256 + tid;
        if (idx >= Bz * Tt * Nn) return;
        int n = idx % Nn, bt = idx / Nn;
        int t = bt % Tt, b = bt / Tt;
        const float* tp = d_tmp_t + ((long)b * Cc) * Tt + t;
        float a0 = 0.f, a1 = 0.f, a2 = 0.f, a3 = 0.f;
        #pragma unroll 4
        for (int c = 0; c < Cc; c += 4) {
            a0 += tp[(c)     * Tt] * taW2[(c)     * Nn + n];
            a1 += tp[(c + 1) * Tt] * taW2[(c + 1) * Nn + n];
            a2 += tp[(c + 2) * Tt] * taW2[(c + 2) * Nn + n];
            a3 += tp[(c + 3) * Tt] * taW2[(c + 3) * Nn + n];
        }
        d_lhs_t[idx] = (a0 + a1) + (a2 + a3);
    } else {
        // att_c: 4 (b,c) units per block
        if (blockIdx.x >= (Bz * Cc) / 4) return;
        int unit = tid >> 6, d = tid & 63;
        int bc = blockIdx.x * 4 + unit;
        int b = bc / Cc;
        float* sh = (float*)smem_raw + unit * 64;
        float dot = 0.f;
        const float* L = d_lhs_c + bc * Tt;
        const float* R = d_rhs_c + (b * Cc + d) * Tt;
        #pragma unroll
        for (int t = 0; t < Tt; t++) dot += L[t] * R[t];
        sh[d] = dot;
        __syncthreads();
        float m = -1e38f;
        for (int i = 0; i < O3; i++) m = fmaxf(m, sh[i]);
        float e = expf(dot - m);
        __syncthreads();
        sh[d] = e;
        __syncthreads();
        float s = 0.f;
        for (int i = 0; i < O3; i++) s += sh[i];
        d_att_c[bc * O3 + d] = e / s;
    }
}

// ---------------- merged3: y=0 softg | y=1 k_M | y=2 att_t   (256 thr) ----------------
__global__ void k_merged3(const int* __restrict__ adj, const float* __restrict__ ccW) {
    __shared__ float red[256];
    int task = blockIdx.y;
    int tid = threadIdx.x;
    if (task == 0) {
        int bn = blockIdx.x;
        if (bn >= Bz * Nn) return;
        int b = bn / Nn, n = bn % Nn;
        long row = ((long)b * Nn + n) * Nn;
        float sc[2];
        #pragma unroll
        for (int k = 0; k < 2; k++) {
            int m = tid + k * 256;
            sc[k] = -INFINITY;
            if (m < Nn)
                sc[k] = (adj[n * Nn + m] > 0) ? d_att_g[row + m] : -1e30f;
        }
        float lm = fmaxf(sc[0], sc[1]);
        red[tid] = lm; __syncthreads();
        for (int st = 128; st; st >>= 1) {
            if (tid < st) red[tid] = fmaxf(red[tid], red[tid + st]);
            __syncthreads();
        }
        float M = red[0]; __syncthreads();
        float ls = 0.f;
        #pragma unroll
        for (int k = 0; k < 2; k++) {
            int m = tid + k * 256;
            if (m < Nn) { sc[k] = expf(sc[k] - M); ls += sc[k]; }
        }
        red[tid] = ls; __syncthreads();
        for (int st = 128; st; st >>= 1) {
            if (tid < st) red[tid] += red[tid + st];
            __syncthreads();
        }
        float S = red[0];
        #pragma unroll
        for (int k = 0; k < 2; k++) {
            int m = tid + k * 256;
            if (m < Nn) d_att_g[row + m] = sc[k] / S;
        }
    } else if (task == 1) {
        int idx = blockIdx.x * 256 + tid;
        if (idx >= Bz * O3 * O3) return;
        int dd = idx % O3, o = (idx / O3) % O3, b = idx / (O3 * O3);
        const float* ap = d_att_c + ((long)b * Cc) * O3 + dd;
        float a0 = 0.f, a1 = 0.f, a2 = 0.f, a3 = 0.f;
        #pragma unroll 4
        for (int c = 0; c < Cc; c += 4) {
            a0 += ccW[o * Cc + c]     * ap[(c)     * O3];
            a1 += ccW[o * Cc + c + 1] * ap[(c + 1) * O3];
            a2 += ccW[o * Cc + c + 2] * ap[(c + 2) * O3];
            a3 += ccW[o * Cc + c + 3] * ap[(c + 3) * O3];
        }
        d_M[idx] = (a0 + a1) + (a2 + a3);
    } else {
        int w = blockIdx.x * 8 + (tid >> 5);
        if (w >= Bz * Tt) return;
        int lane = tid & 31;
        int b = w / Tt;
        float dot = -INFINITY;
        if (lane < Tt) {
            dot = 0.f;
            const float* L = d_lhs_t + (long)w * Nn;
            const float* R = d_rhs_t + (long)b * Nn * Tt + lane;
            for (int n = 0; n < Nn; n++) dot += L[n] * R[n * Tt];
        }
        float m = dot;
        #pragma unroll
        for (int o = 16; o; o >>= 1) m = fmaxf(m, __shfl_xor_sync(~0u, m, o));
        float e = (lane < Tt) ? expf(dot - m) : 0.f;
        float su = e;
        #pragma unroll
        for (int o = 16; o; o >>= 1) su += __shfl_xor_sync(~0u, su, o);
        if (lane < Tt) d_att_t[w * Tt + lane] = e / su;
    }
}

// ---------------- apply temporal attention -> bufA ----------------
__global__ void k_apply_t() {
    int warp = (blockIdx.x * blockDim.x + threadIdx.x) >> 5;
    int lane = threadIdx.x & 31;
    if (warp >= BCN) return;
    int b = warp / (Cc * Nn);
    long row = (long)warp * Tt;
    float hv = (lane < Tt) ? d_h[row + lane] : 0.f;
    float acc = 0.f;
    const float* arow = d_att_t + (b * Tt + (lane < Tt ? lane : 0)) * Tt;
    #pragma unroll
    for (int s = 0; s < Tt; s++) {
        float hs = __shfl_sync(~0u, hv, s);
        acc += arow[s] * hs;
    }
    if (lane < Tt) d_bufA[row + lane] = acc;
}

// ---------------- big fused kernel: conv4res | cmix | gres ----------------
__global__ void __launch_bounds__(256, 2)
k_big(const float* __restrict__ resW, const float* __restrict__ resb,
      const float* __restrict__ ccb, const float* __restrict__ x,
      float* __restrict__ out) {
    int b = blockIdx.z;
    int yy = blockIdx.y;
    int p0 = blockIdx.x * 1024 + threadIdx.x * 4;
    __shared__ __align__(16) float sm[5 * Cc * 16];

    if (yy < 4) {
        // ---- conv4res, og = yy ----
        int og = yy;
        float (*Ws)[Cc][16] = (float(*)[Cc][16])sm;
        float (*Rs)[16] = (float(*)[16])(sm + 4 * Cc * 16);
        for (int i = threadIdx.x; i < 16 * Cc; i += 256) {
            int o = i & 15, c = i >> 4;
            #pragma unroll
            for (int k = 0; k < 4; k++)
                Ws[k][c][o] = d_Wc[k * O3 * Cc + (og * 16 + o) * Cc + c];
            Rs[c][o] = resW[(64 + og * 16 + o) * Cc + c];
        }
        __syncthreads();
        if (p0 >= NT) return;
        int t0 = p0 % Tt;
        const float* Zb = d_bufA + (long)b * Cc * NT + p0;
        const float* xb = x + (long)b * Cc * NT + p0;
        u64 acc2[8][4] = {};
        auto cstep = [&](float4 cur, float4 prv, float4 xv, int c) {
            u64 z0 = pk2(prv.y), z1 = pk2(prv.z), z2 = pk2(prv.w);
            u64 z3 = pk2(cur.x), z4 = pk2(cur.y), z5 = pk2(cur.z), z6 = pk2(cur.w);
            u64 xr0 = pk2(xv.x), xr1 = pk2(xv.y), xr2 = pk2(xv.z), xr3 = pk2(xv.w);
            const u64* W0r = (const u64*)Ws[0][c];
            const u64* W1r = (const u64*)Ws[1][c];
            const u64* W2r = (const u64*)Ws[2][c];
            const u64* W3r = (const u64*)Ws[3][c];
            const u64* Rr  = (const u64*)Rs[c];
            #pragma unroll
            for (int o2 = 0; o2 < 8; o2++) {
                u64 w0 = W0r[o2], w1 = W1r[o2], w2 = W2r[o2], w3 = W3r[o2], ar = Rr[o2];
                fma2(acc2[o2][0], w0, z3); fma2(acc2[o2][0], w1, z2);
                fma2(acc2[o2][0], w2, z1); fma2(acc2[o2][0], w3, z0);
                fma2(acc2[o2][0], ar, xr0);
                fma2(acc2[o2][1], w0, z4); fma2(acc2[o2][1], w1, z3);
                fma2(acc2[o2][1], w2, z2); fma2(acc2[o2][1], w3, z1);
                fma2(acc2[o2][1], ar, xr1);
                fma2(acc2[o2][2], w0, z5); fma2(acc2[o2][2], w1, z4);
                fma2(acc2[o2][2], w2, z3); fma2(acc2[o2][2], w3, z2);
                fma2(acc2[o2][2], ar, xr2);
                fma2(acc2[o2][3], w0, z6); fma2(acc2[o2][3], w1, z5);
                fma2(acc2[o2][3], w2, z4); fma2(acc2[o2][3], w3, z3);
                fma2(acc2[o2][3], ar, xr3);
            }
        };
        float4 zero4 = make_float4(0.f, 0.f, 0.f, 0.f);
        bool hasPrev = (t0 > 0);
        for (int c = 0; c < Cc; c += 2) {
            const float* Zc0 = Zb + (long)(c)     * NT;
            const float* Zc1 = Zb + (long)(c + 1) * NT;
            float4 cur0 = *(const float4*)Zc0;
            float4 cur1 = *(const float4*)Zc1;
            float4 prv0 = hasPrev ? *(const float4*)(Zc0 - 4) : zero4;
            float4 prv1 = hasPrev ? *(const float4*)(Zc1 - 4) : zero4;
            float4 xv0 = *(const float4*)(xb + (long)(c)     * NT);
            float4 xv1 = *(const float4*)(xb + (long)(c + 1) * NT);
            cstep(cur0, prv0, xv0, c);
            cstep(cur1, prv1, xv1, c + 1);
        }
        #pragma unroll
        for (int o2 = 0; o2 < 8; o2++) {
            float2 v0 = unpk(acc2[o2][0]), v1 = unpk(acc2[o2][1]);
            float2 v2 = unpk(acc2[o2][2]), v3 = unpk(acc2[o2][3]);
            #pragma unroll
            for (int par = 0; par < 2; par++) {
                int o = og * 16 + o2 * 2 + par;
                float4 v = par ? make_float4(v0.y, v1.y, v2.y, v3.y)
                               : make_float4(v0.x, v1.x, v2.x, v3.x);
                float rb  = resb[64 + o];
                float bhi = d_bhi[o] + rb;
                float blo = d_blo[o] + rb;
                float ba = (t0 == 0) ? blo : bhi;
                v.x = fmaxf(v.x + ba,  0.f); v.y = fmaxf(v.y + ba,  0.f);
                v.z = fmaxf(v.z + bhi, 0.f); v.w = fmaxf(v.w + bhi, 0.f);
                *(float4*)(out + ((long)b * CO + 64 + o) * NT + p0) = v;
            }
        }
    } else {
        int og = yy & 3;
        bool isC = yy < 8;
        float (*As)[16] = (float(*)[16])sm;
        float (*Rs)[16] = (float(*)[16])(sm + Cc * 16);
        const float* Mb = d_M + (long)b * O3 * Cc;
        for (int i = threadIdx.x; i < 16 * Cc; i += 256) {
            int o = i & 15, c = i >> 4;
            if (isC) {
                As[c][o] = Mb[(og * 16 + o) * Cc + c];
                Rs[c][o] = resW[(og * 16 + o) * Cc + c];
            } else {
                As[c][o] = resW[(128 + og * 16 + o) * Cc + c];
            }
        }
        __syncthreads();
        if (p0 >= NT) return;
        const float* Hb = d_h + (long)b * Cc * NT + p0;
        const float* xb = x + (long)b * Cc * NT + p0;
        u64 acc2[8][4] = {};
        if (isC) {
            auto mstep = [&](float4 hv, float4 xv, int c) {
                u64 hp0 = pk2(hv.x), hp1 = pk2(hv.y), hp2 = pk2(hv.z), hp3 = pk2(hv.w);
                u64 xp0 = pk2(xv.x), xp1 = pk2(xv.y), xp2 = pk2(xv.z), xp3 = pk2(xv.w);
                const u64* Mr = (const u64*)As[c];
                const u64* Rr = (const u64*)Rs[c];
                #pragma unroll
                for (int o2 = 0; o2 < 8; o2++) {
                    u64 am = Mr[o2], ar = Rr[o2];
                    fma2(acc2[o2][0], am, hp0); fma2(acc2[o2][0], ar, xp0);
                    fma2(acc2[o2][1], am, hp1); fma2(acc2[o2][1], ar, xp1);
                    fma2(acc2[o2][2], am, hp2); fma2(acc2[o2][2], ar, xp2);
                    fma2(acc2[o2][3], am, hp3); fma2(acc2[o2][3], ar, xp3);
                }
            };
            for (int c = 0; c < Cc; c += 2) {
                float4 h0 = *(const float4*)(Hb + (long)(c)     * NT);
                float4 h1 = *(const float4*)(Hb + (long)(c + 1) * NT);
                float4 x0 = *(const float4*)(xb + (long)(c)     * NT);
                float4 x1 = *(const float4*)(xb + (long)(c + 1) * NT);
                mstep(h0, x0, c);
                mstep(h1, x1, c + 1);
            }
        } else {
            auto gstep = [&](float4 xv, int c) {
                u64 xp0 = pk2(xv.x), xp1 = pk2(xv.y), xp2 = pk2(xv.z), xp3 = pk2(xv.w);
                const u64* Ar = (const u64*)As[c];
                #pragma unroll
                for (int o2 = 0; o2 < 8; o2++) {
                    u64 a2 = Ar[o2];
                    fma2(acc2[o2][0], a2, xp0);
                    fma2(acc2[o2][1], a2, xp1);
                    fma2(acc2[o2][2], a2, xp2);
                    fma2(acc2[o2][3], a2, xp3);
                }
            };
            for (int c = 0; c < Cc; c += 4) {
                float4 x0 = *(const float4*)(xb + (long)(c)     * NT);
                float4 x1 = *(const float4*)(xb + (long)(c + 1) * NT);
                float4 x2 = *(const float4*)(xb + (long)(c + 2) * NT);
                float4 x3 = *(const float4*)(xb + (long)(c + 3) * NT);
                gstep(x0, c); gstep(x1, c + 1); gstep(x2, c + 2); gstep(x3, c + 3);
            }
        }
        #pragma unroll
        for (int o2 = 0; o2 < 8; o2++) {
            float2 v0 = unpk(acc2[o2][0]), v1 = unpk(acc2[o2][1]);
            float2 v2 = unpk(acc2[o2][2]), v3 = unpk(acc2[o2][3]);
            #pragma unroll
            for (int par = 0; par < 2; par++) {
                int o = og * 16 + o2 * 2 + par;
                float4 v = par ? make_float4(v0.y, v1.y, v2.y, v3.y)
                               : make_float4(v0.x, v1.x, v2.x, v3.x);
                if (isC) {
                    float bb = ccb[o] + resb[o];
                    v.x = fmaxf(v.x + bb, 0.f); v.y = fmaxf(v.y + bb, 0.f);
                    v.z = fmaxf(v.z + bb, 0.f); v.w = fmaxf(v.w + bb, 0.f);
                    *(float4*)(out + ((long)b * CO + o) * NT + p0) = v;
                } else {
                    float bb = resb[128 + o];
                    v.x += bb; v.y += bb; v.z += bb; v.w += bb;
                    *(float4*)(out + ((long)b * CO + 128 + o) * NT + p0) = v;
                }
            }
        }
    }
}

// ---------------- graph apply: software-pipelined tiles ----------------
// grid (q-tile 6x256, n-tile 5x64, b); thread: tx=tid&31 (8 q), ty=tid>>5 (8 n)
__global__ void __launch_bounds__(256, 2) k_gapply(float* __restrict__ out) {
    int b = blockIdx.z;
    int q0 = blockIdx.x * 256;
    int n0 = blockIdx.y * 64;
    int tid = threadIdx.x;
    int tx = tid & 31, ty = tid >> 5;
    __shared__ __align__(16) u64 att2[64][16];
    __shared__ __align__(16) float Gs[16][256];
    u64 acc2[8][4] = {};
    const float* Ab = d_att_g + (long)b * Nn * Nn;
    const float* Gb = d_gh + (long)b * Nn * QW;
    const int arow = tid >> 2, ak0 = (tid & 3) * 4;   // att fill coords
    float a_st[4];
    float4 g_st[4];
    auto ldg_tile = [&](int m0) {
        int n = n0 + arow;
        #pragma unroll
        for (int j = 0; j < 4; j++) {
            int m = m0 + ak0 + j;
            a_st[j] = (n < Nn && m < Nn) ? Ab[(long)n * Nn + m] : 0.f;
        }
        #pragma unroll
        for (int j = 0; j < 4; j++) {
            int i2 = tid + j * 256;
            int k = i2 >> 6, qq = (i2 & 63) * 4;
            g_st[j] = make_float4(0.f, 0.f, 0.f, 0.f);
            if (m0 + k < Nn)
                g_st[j] = *(const float4*)(Gb + (long)(m0 + k) * QW + q0 + qq);
        }
    };
    auto sts_tile = [&]() {
        #pragma unroll
        for (int j = 0; j < 4; j++) att2[arow][ak0 + j] = pk2(a_st[j]);
        #pragma unroll
        for (int j = 0; j < 4; j++) {
            int i2 = tid + j * 256;
            int k = i2 >> 6, qq = (i2 & 63) * 4;
            *(float4*)&Gs[k][qq] = g_st[j];
        }
    };
    const int NTILES = (Nn + 15) / 16;   // 20
    ldg_tile(0);
    sts_tile();
    __syncthreads();
    for (int mt = 0; mt < NTILES; mt++) {
        if (mt + 1 < NTILES) ldg_tile((mt + 1) * 16);   // in flight during compute
        #pragma unroll
        for (int k = 0; k < 16; k++) {
            const u64* gp = (const u64*)&Gs[k][tx * 8];
            u64 g0 = gp[0], g1 = gp[1], g2 = gp[2], g3 = gp[3];
            #pragma unroll
            for (int j = 0; j < 8; j++) {
                u64 a = att2[ty * 8 + j][k];
                fma2(acc2[j][0], a, g0);
                fma2(acc2[j][1], a, g1);
                fma2(acc2[j][2], a, g2);
                fma2(acc2[j][3], a, g3);
            }
        }
        __syncthreads();
        if (mt + 1 < NTILES) {
            sts_tile();
            __syncthreads();
        }
    }
    int q = q0 + tx * 8;
    int ch = q / Tt, t0 = q % Tt;
    #pragma unroll
    for (int j = 0; j < 8; j++) {
        int n = n0 + ty * 8 + j;
        if (n >= Nn) continue;
        long base = ((long)b * CO + 128 + ch) * NT + (long)n * Tt + t0;
        float2 a0 = unpk(acc2[j][0]), a1 = unpk(acc2[j][1]);
        float2 a2 = unpk(acc2[j][2]), a3 = unpk(acc2[j][3]);
        float4 r0 = *(const float4*)(out + base);
        float4 r1 = *(const float4*)(out + base + 4);
        float4 w0, w1;
        w0.x = fmaxf(a0.x + r0.x, 0.f); w0.y = fmaxf(a0.y + r0.y, 0.f);
        w0.z = fmaxf(a1.x + r0.z, 0.f); w0.w = fmaxf(a1.y + r0.w, 0.f);
        w1.x = fmaxf(a2.x + r1.x, 0.f); w1.y = fmaxf(a2.y + r1.y, 0.f);
        w1.z = fmaxf(a3.x + r1.z, 0.f); w1.w = fmaxf(a3.y + r1.w, 0.f);
        *(float4*)(out + base) = w0;
        *(float4*)(out + base + 4) = w1;
    }
}

// ================================= launch =================================
extern "C" void kernel_launch(void* const* d_in, const int* in_sizes, int n_in,
                              void* d_out, int out_size) {
    const float* x     = (const float*)d_in[0];
    const int*   adj   = (const int*)  d_in[1];
    const float* ln_g  = (const float*)d_in[2];
    const float* ln_b  = (const float*)d_in[3];
    const float* res_W = (const float*)d_in[4];
    const float* res_b = (const float*)d_in[5];
    const float* ca_W1 = (const float*)d_in[6];
    const float* ca_W2 = (const float*)d_in[7];
    const float* ca_W3 = (const float*)d_in[8];
    const float* cc_W  = (const float*)d_in[9];
    const float* cc_b  = (const float*)d_in[10];
    const float* ta_W1 = (const float*)d_in[11];
    const float* ta_W2 = (const float*)d_in[12];
    const float* ta_W3 = (const float*)d_in[13];
    const float* tc_W0 = (const float*)d_in[14];
    const float* tc_b0 = (const float*)d_in[15];
    const float* tc_W1 = (const float*)d_in[16];
    const float* tc_b1 = (const float*)d_in[17];
    const float* ga_W1 = (const float*)d_in[18];
    const float* ga_W2 = (const float*)d_in[19];
    const float* ga_W3 = (const float*)d_in[20];
    const float* g_W   = (const float*)d_in[21];
    float* out = (float*)d_out;

    int warpBlocks = (BCN + 7) / 8;

    // 1) LayerNorm + T-dots + conv weight combine (tail blocks)
    k_lnw<<<warpBlocks + 65, 256>>>(x, ln_g, ln_b, ca_W1, ga_W1,
                                    tc_W0, tc_b0, tc_W1, tc_b1, warpBlocks);
    // 2) gh = g_W @ h (needs only h)
    k_mixgh<<<dim3(8, 4, Bz), 256>>>(g_W);
    // 3) glue reductions
    k_stage1<<<dim3(921, 4), 256>>>(ca_W3, ta_W1, ta_W3, ga_W3, ca_W2, ga_W2);
    // 4) scoreG | lhs_t | att_c  (ncu slot)
    k_merged2<<<dim3(921, 3), 256>>>(ta_W2);
    // 5) softg | k_M | att_t
    k_merged3<<<dim3(Bz * Nn, 3), 256>>>(adj, cc_W);
    // 6) temporal attention apply -> bufA
    k_apply_t<<<warpBlocks, 256>>>();
    // 7) fused: conv4res | cmix | G-residual
    k_big<<<dim3(8, 12, Bz), 256>>>(res_W, res_b, cc_b, x, out);
    // 8) graph apply + add + relu
    k_gapply<<<dim3(6, 5, Bz), 256>>>(out);

    (void)in_sizes; (void)n_in; (void)out_size;
}

// round 9
// speedup vs baseline: 2.2054x; 1.0578x over previous
#include <cuda_runtime.h>
#include <math.h>

#define Bz 32
#define Cc 64
#define Nn 307
#define Tt 24
#define NT 7368            // Nn*Tt
#define O3 64
#define CO 192
#define QW (O3*Tt)         // 1536 flattened (ch,t)
#define BCN (Bz*Cc*Nn)     // 628736
#define BCNT (Bz*Cc*NT)

typedef unsigned long long u64;

// ---------------- scratch ----------------
__device__ float d_h[BCNT];
__device__ float d_bufA[BCNT];          // apply_t output [b][c][n][t]
__device__ float d_gh[BCNT];            // g_W@h in [b][m][ch][t] layout
__device__ float d_tca[Bz*Cc*Nn];
__device__ float d_tga[Bz*Cc*Nn];
__device__ float d_lhs_c[Bz*Cc*Tt];
__device__ float d_rhs_c[Bz*Cc*Tt];
__device__ float d_tmp_t[Bz*Cc*Tt];
__device__ float d_lhs_t[Bz*Tt*Nn];
__device__ float d_rhs_t[Bz*Nn*Tt];
__device__ float d_lhs_g[Bz*Nn*Tt];
__device__ float d_rhs_g[Bz*Nn*Tt];
__device__ float d_att_c[Bz*Cc*Cc];
__device__ float d_att_t[Bz*Tt*Tt];
__device__ float d_att_g[Bz*Nn*Nn];     // scores -> softmaxed in place
__device__ float d_M[Bz*O3*O3];
__device__ float d_Wc[4*O3*Cc];
__device__ float d_bhi[O3];
__device__ float d_blo[O3];

// -------- packed f32x2 helpers --------
__device__ __forceinline__ void fma2(u64& d, u64 a, u64 b) {
    asm("fma.rn.f32x2 %0, %1, %2, %0;" : "+l"(d) : "l"(a), "l"(b));
}
__device__ __forceinline__ u64 pk2(float x) {
    u64 r; unsigned xi = __float_as_uint(x);
    asm("mov.b64 %0, {%1, %1};" : "=l"(r) : "r"(xi));
    return r;
}
__device__ __forceinline__ float2 unpk(u64 v) {
    unsigned lo, hi;
    asm("mov.b64 {%0, %1}, %2;" : "=r"(lo), "=r"(hi) : "l"(v));
    return make_float2(__uint_as_float(lo), __uint_as_float(hi));
}
// tf32 split: v = hi + lo (both tf32-representable)
__device__ __forceinline__ void tf32_split(float v, float& hf, float& lf) {
    unsigned hb; asm("cvt.rna.tf32.f32 %0, %1;" : "=r"(hb) : "f"(v));
    hf = __uint_as_float(hb);
    float rem = v - hf;
    unsigned lb; asm("cvt.rna.tf32.f32 %0, %1;" : "=r"(lb) : "f"(rem));
    lf = __uint_as_float(lb);
}
__device__ __forceinline__ void mma_tf32(float* d, unsigned a0, unsigned a1,
                                         unsigned a2, unsigned a3,
                                         unsigned b0, unsigned b1) {
    asm volatile(
        "mma.sync.aligned.m16n8k8.row.col.f32.tf32.tf32.f32 "
        "{%0,%1,%2,%3}, {%4,%5,%6,%7}, {%8,%9}, {%0,%1,%2,%3};"
        : "+f"(d[0]), "+f"(d[1]), "+f"(d[2]), "+f"(d[3])
        : "r"(a0), "r"(a1), "r"(a2), "r"(a3), "r"(b0), "r"(b1));
}

// ---------------- LayerNorm + ca/ga T-dots + (tail blocks) conv-weight combine ----------------
__global__ void k_lnw(const float* __restrict__ x, const float* __restrict__ g,
                      const float* __restrict__ be,
                      const float* __restrict__ caW1, const float* __restrict__ gaW1,
                      const float* __restrict__ tcW0, const float* __restrict__ tcb0,
                      const float* __restrict__ tcW1, const float* __restrict__ tcb1,
                      int warpBlocks) {
    if ((int)blockIdx.x >= warpBlocks) {
        int idx = (blockIdx.x - warpBlocks) * 256 + threadIdx.x;
        if (idx < 4 * O3 * Cc) {
            int c = idx & 63, o = (idx >> 6) & 63, k = idx >> 12;
            int a = (k < 2) ? 1 : 0;
            int bsel = (k == 0 || k == 2) ? 1 : 0;
            float s = 0.f;
            for (int j = 0; j < O3; j++)
                s += tcW1[(o * O3 + j) * 2 + a] * tcW0[(j * Cc + c) * 2 + bsel];
            d_Wc[idx] = s;
        } else if (idx < 4 * O3 * Cc + O3) {
            int o = idx - 4 * O3 * Cc;
            float s1 = 0.f, s0 = 0.f;
            for (int j = 0; j < O3; j++) {
                s1 += tcW1[(o * O3 + j) * 2 + 1] * tcb0[j];
                s0 += tcW1[(o * O3 + j) * 2 + 0] * tcb0[j];
            }
            d_blo[o] = s1 + tcb1[o];
            d_bhi[o] = s1 + s0 + tcb1[o];
        }
        return;
    }
    int warp = (blockIdx.x * blockDim.x + threadIdx.x) >> 5;
    int lane = threadIdx.x & 31;
    if (warp >= BCN) return;
    const float* row = x + (long)warp * Tt;
    float v = (lane < Tt) ? row[lane] : 0.f;
    float s = v, s2 = v * v;
    #pragma unroll
    for (int o = 16; o; o >>= 1) {
        s  += __shfl_xor_sync(~0u, s,  o);
        s2 += __shfl_xor_sync(~0u, s2, o);
    }
    float mu  = s * (1.f / Tt);
    float var = s2 * (1.f / Tt) - mu * mu;
    float inv = rsqrtf(var + 1e-5f);
    float hv = 0.f;
    if (lane < Tt) {
        hv = (v - mu) * inv * g[lane] + be[lane];
        d_h[(long)warp * Tt + lane] = hv;
    }
    float dca = (lane < Tt) ? hv * caW1[lane] : 0.f;
    float dga = (lane < Tt) ? hv * gaW1[lane] : 0.f;
    #pragma unroll
    for (int o = 16; o; o >>= 1) {
        dca += __shfl_xor_sync(~0u, dca, o);
        dga += __shfl_xor_sync(~0u, dga, o);
    }
    if (lane == 0) { d_tca[warp] = dca; d_tga[warp] = dga; }
}

// ---------------- gh = g_W @ h, stored [b][n][o][t]; MLP-4 c-loop ----------------
__global__ void __launch_bounds__(256, 2)
k_mixgh(const float* __restrict__ A) {
    int b = blockIdx.z, og = blockIdx.y;
    int p0 = blockIdx.x * 1024 + threadIdx.x * 4;
    __shared__ __align__(16) float As[Cc][16];
    for (int i = threadIdx.x; i < 16 * Cc; i += 256) {
        int o = i & 15, c = i >> 4;
        As[c][o] = A[(og * 16 + o) * Cc + c];
    }
    __syncthreads();
    if (p0 >= NT) return;
    int n = p0 / Tt, t0 = p0 % Tt;
    const float* Xb = d_h + (long)b * Cc * NT + p0;
    u64 acc2[8][4] = {};
    auto step = [&](float4 xv, int c) {
        u64 xp0 = pk2(xv.x), xp1 = pk2(xv.y), xp2 = pk2(xv.z), xp3 = pk2(xv.w);
        const u64* Arow = (const u64*)As[c];
        #pragma unroll
        for (int o2 = 0; o2 < 8; o2++) {
            u64 a2 = Arow[o2];
            fma2(acc2[o2][0], a2, xp0);
            fma2(acc2[o2][1], a2, xp1);
            fma2(acc2[o2][2], a2, xp2);
            fma2(acc2[o2][3], a2, xp3);
        }
    };
    for (int c = 0; c < Cc; c += 4) {
        float4 x0 = *(const float4*)(Xb + (long)(c)     * NT);
        float4 x1 = *(const float4*)(Xb + (long)(c + 1) * NT);
        float4 x2 = *(const float4*)(Xb + (long)(c + 2) * NT);
        float4 x3 = *(const float4*)(Xb + (long)(c + 3) * NT);
        step(x0, c); step(x1, c + 1); step(x2, c + 2); step(x3, c + 3);
    }
    long nbase = ((long)b * Nn + n) * QW;
    #pragma unroll
    for (int o2 = 0; o2 < 8; o2++) {
        float2 v0 = unpk(acc2[o2][0]), v1 = unpk(acc2[o2][1]);
        float2 v2 = unpk(acc2[o2][2]), v3 = unpk(acc2[o2][3]);
        #pragma unroll
        for (int par = 0; par < 2; par++) {
            int o = og * 16 + o2 * 2 + par;
            float4 v = par ? make_float4(v0.y, v1.y, v2.y, v3.y)
                           : make_float4(v0.x, v1.x, v2.x, v3.x);
            *(float4*)(d_gh + nbase + o * Tt + t0) = v;
        }
    }
}

// ---------------- stage1: glue reductions ----------------
__global__ void k_stage1(const float* __restrict__ caW3, const float* __restrict__ taW1,
                         const float* __restrict__ taW3, const float* __restrict__ gaW3,
                         const float* __restrict__ caW2, const float* __restrict__ gaW2) {
    int task = blockIdx.y;
    int idx = blockIdx.x * 256 + threadIdx.x;
    if (task == 0) {
        if (idx >= Bz * Cc * Tt) return;
        int t = idx % Tt, bc = idx / Tt;
        const float* hp = d_h + (long)bc * Nn * Tt + t;
        float a0 = 0.f, a1 = 0.f, b0 = 0.f, b1 = 0.f;
        int n = 0;
        for (; n < 306; n += 2) {
            float h0 = hp[(n)     * Tt];
            float h1 = hp[(n + 1) * Tt];
            a0 += caW3[n] * h0;  b0 += taW1[n] * h0;
            a1 += caW3[n + 1] * h1;  b1 += taW1[n + 1] * h1;
        }
        { float h0 = hp[n * Tt]; a0 += caW3[n] * h0; b0 += taW1[n] * h0; }
        d_rhs_c[idx] = a0 + a1;
        d_tmp_t[idx] = b0 + b1;
    } else if (task == 1) {
        if (idx >= Bz * Nn * Tt) return;
        int t = idx % Tt, n = (idx / Tt) % Nn, b = idx / (Nn * Tt);
        const float* hp = d_h + (((long)b * Cc) * Nn + n) * Tt + t;
        float a0 = 0.f, a1 = 0.f, b0 = 0.f, b1 = 0.f;
        #pragma unroll 4
        for (int c = 0; c < Cc; c += 2) {
            float h0 = hp[(long)(c)     * Nn * Tt];
            float h1 = hp[(long)(c + 1) * Nn * Tt];
            a0 += taW3[c] * h0;  b0 += gaW3[c] * h0;
            a1 += taW3[c + 1] * h1;  b1 += gaW3[c + 1] * h1;
        }
        d_rhs_t[idx] = a0 + a1;
        d_rhs_g[idx] = b0 + b1;
    } else if (task == 2) {
        if (idx >= Bz * Cc * Tt) return;
        int t = idx % Tt, bc = idx / Tt;
        const float* tp = d_tca + (long)bc * Nn;
        float a0 = 0.f, a1 = 0.f, a2 = 0.f, a3 = 0.f;
        int n = 0;
        for (; n < 304; n += 4) {
            a0 += tp[n]     * caW2[(n)     * Tt + t];
            a1 += tp[n + 1] * caW2[(n + 1) * Tt + t];
            a2 += tp[n + 2] * caW2[(n + 2) * Tt + t];
            a3 += tp[n + 3] * caW2[(n + 3) * Tt + t];
        }
        for (; n < Nn; n++) a0 += tp[n] * caW2[n * Tt + t];
        d_lhs_c[idx] = (a0 + a1) + (a2 + a3);
    } else {
        if (idx >= Bz * Nn * Tt) return;
        int t = idx % Tt, bn = idx / Tt;
        int n = bn % Nn, b = bn / Nn;
        const float* tp = d_tga + (long)b * Cc * Nn + n;
        float a0 = 0.f, a1 = 0.f, a2 = 0.f, a3 = 0.f;
        #pragma unroll 4
        for (int c = 0; c < Cc; c += 4) {
            a0 += tp[(c)     * Nn] * gaW2[(c)     * Tt + t];
            a1 += tp[(c + 1) * Nn] * gaW2[(c + 1) * Tt + t];
            a2 += tp[(c + 2) * Nn] * gaW2[(c + 2) * Tt + t];
            a3 += tp[(c + 3) * Nn] * gaW2[(c + 3) * Tt + t];
        }
        d_lhs_g[idx] = (a0 + a1) + (a2 + a3);
    }
}

// ---------------- merged2: y=0 scoreG | y=1 lhs_t | y=2 att_c ----------------
__global__ void k_merged2(const float* __restrict__ taW2) {
    __shared__ __align__(16) char smem_raw[64 * Tt * 8 + Tt * 64 * 4];
    int task = blockIdx.y;
    int tid = threadIdx.x;
    if (task == 0) {
        if (blockIdx.x >= 5 * Bz) return;
        int b = blockIdx.x / 5;
        int n0 = (blockIdx.x % 5) * 64;
        int mq = tid & 15, ny = tid >> 4;
        u64 (*lhs2)[Tt] = (u64(*)[Tt])smem_raw;
        float (*rhsT)[64] = (float(*)[64])(smem_raw + 64 * Tt * 8);
        for (int i = tid; i < 64 * Tt; i += 256) {
            int nl = i / Tt, k = i % Tt;
            float v = (n0 + nl < Nn) ? d_lhs_g[((long)b * Nn + n0 + nl) * Tt + k] : 0.f;
            lhs2[nl][k] = pk2(v);
        }
        for (int m0 = 0; m0 < Nn; m0 += 64) {
            __syncthreads();
            for (int i = tid; i < 64 * Tt; i += 256) {
                int ml = i / Tt, k = i % Tt;
                float v = (m0 + ml < Nn) ? d_rhs_g[((long)b * Nn + m0 + ml) * Tt + k] : 0.f;
                rhsT[k][ml] = v;
            }
            __syncthreads();
            u64 acc2[4][2] = {};
            #pragma unroll
            for (int k = 0; k < Tt; k++) {
                const u64* rp = (const u64*)&rhsT[k][mq * 4];
                u64 r0 = rp[0], r1 = rp[1];
                #pragma unroll
                for (int nl = 0; nl < 4; nl++) {
                    u64 l = lhs2[ny * 4 + nl][k];
                    fma2(acc2[nl][0], l, r0);
                    fma2(acc2[nl][1], l, r1);
                }
            }
            #pragma unroll
            for (int nl = 0; nl < 4; nl++) {
                int n = n0 + ny * 4 + nl;
                if (n >= Nn) continue;
                long row = ((long)b * Nn + n) * Nn;
                #pragma unroll
                for (int mp = 0; mp < 2; mp++) {
                    float2 v = unpk(acc2[nl][mp]);
                    int m = m0 + mq * 4 + mp * 2;
                    if (m < Nn) d_att_g[row + m] = v.x;
                    if (m + 1 < Nn) d_att_g[row + m + 1] = v.y;
                }
            }
        }
    } else if (task == 1) {
        int idx = blockIdx.x * 256 + tid;
        if (idx >= Bz * Tt * Nn) return;
        int n = idx % Nn, bt = idx / Nn;
        int t = bt % Tt, b = bt / Tt;
        const float* tp = d_tmp_t + ((long)b * Cc) * Tt + t;
        float a0 = 0.f, a1 = 0.f, a2 = 0.f, a3 = 0.f;
        #pragma unroll 4
        for (int c = 0; c < Cc; c += 4) {
            a0 += tp[(c)     * Tt] * taW2[(c)     * Nn + n];
            a1 += tp[(c + 1) * Tt] * taW2[(c + 1) * Nn + n];
            a2 += tp[(c + 2) * Tt] * taW2[(c + 2) * Nn + n];
            a3 += tp[(c + 3) * Tt] * taW2[(c + 3) * Nn + n];
        }
        d_lhs_t[idx] = (a0 + a1) + (a2 + a3);
    } else {
        if (blockIdx.x >= (Bz * Cc) / 4) return;
        int unit = tid >> 6, d = tid & 63;
        int bc = blockIdx.x * 4 + unit;
        int b = bc / Cc;
        float* sh = (float*)smem_raw + unit * 64;
        float dot = 0.f;
        const float* L = d_lhs_c + bc * Tt;
        const float* R = d_rhs_c + (b * Cc + d) * Tt;
        #pragma unroll
        for (int t = 0; t < Tt; t++) dot += L[t] * R[t];
        sh[d] = dot;
        __syncthreads();
        float m = -1e38f;
        for (int i = 0; i < O3; i++) m = fmaxf(m, sh[i]);
        float e = expf(dot - m);
        __syncthreads();
        sh[d] = e;
        __syncthreads();
        float s = 0.f;
        for (int i = 0; i < O3; i++) s += sh[i];
        d_att_c[bc * O3 + d] = e / s;
    }
}

// ---------------- merged3: y=0 softg | y=1 k_M | y=2 att_t ----------------
__global__ void k_merged3(const int* __restrict__ adj, const float* __restrict__ ccW) {
    __shared__ float red[256];
    int task = blockIdx.y;
    int tid = threadIdx.x;
    if (task == 0) {
        int bn = blockIdx.x;
        if (bn >= Bz * Nn) return;
        int b = bn / Nn, n = bn % Nn;
        long row = ((long)b * Nn + n) * Nn;
        float sc[2];
        #pragma unroll
        for (int k = 0; k < 2; k++) {
            int m = tid + k * 256;
            sc[k] = -INFINITY;
            if (m < Nn)
                sc[k] = (adj[n * Nn + m] > 0) ? d_att_g[row + m] : -1e30f;
        }
        float lm = fmaxf(sc[0], sc[1]);
        red[tid] = lm; __syncthreads();
        for (int st = 128; st; st >>= 1) {
            if (tid < st) red[tid] = fmaxf(red[tid], red[tid + st]);
            __syncthreads();
        }
        float M = red[0]; __syncthreads();
        float ls = 0.f;
        #pragma unroll
        for (int k = 0; k < 2; k++) {
            int m = tid + k * 256;
            if (m < Nn) { sc[k] = expf(sc[k] - M); ls += sc[k]; }
        }
        red[tid] = ls; __syncthreads();
        for (int st = 128; st; st >>= 1) {
            if (tid < st) red[tid] += red[tid + st];
            __syncthreads();
        }
        float S = red[0];
        #pragma unroll
        for (int k = 0; k < 2; k++) {
            int m = tid + k * 256;
            if (m < Nn) d_att_g[row + m] = sc[k] / S;
        }
    } else if (task == 1) {
        int idx = blockIdx.x * 256 + tid;
        if (idx >= Bz * O3 * O3) return;
        int dd = idx % O3, o = (idx / O3) % O3, b = idx / (O3 * O3);
        const float* ap = d_att_c + ((long)b * Cc) * O3 + dd;
        float a0 = 0.f, a1 = 0.f, a2 = 0.f, a3 = 0.f;
        #pragma unroll 4
        for (int c = 0; c < Cc; c += 4) {
            a0 += ccW[o * Cc + c]     * ap[(c)     * O3];
            a1 += ccW[o * Cc + c + 1] * ap[(c + 1) * O3];
            a2 += ccW[o * Cc + c + 2] * ap[(c + 2) * O3];
            a3 += ccW[o * Cc + c + 3] * ap[(c + 3) * O3];
        }
        d_M[idx] = (a0 + a1) + (a2 + a3);
    } else {
        int w = blockIdx.x * 8 + (tid >> 5);
        if (w >= Bz * Tt) return;
        int lane = tid & 31;
        int b = w / Tt;
        float dot = -INFINITY;
        if (lane < Tt) {
            dot = 0.f;
            const float* L = d_lhs_t + (long)w * Nn;
            const float* R = d_rhs_t + (long)b * Nn * Tt + lane;
            for (int n = 0; n < Nn; n++) dot += L[n] * R[n * Tt];
        }
        float m = dot;
        #pragma unroll
        for (int o = 16; o; o >>= 1) m = fmaxf(m, __shfl_xor_sync(~0u, m, o));
        float e = (lane < Tt) ? expf(dot - m) : 0.f;
        float su = e;
        #pragma unroll
        for (int o = 16; o; o >>= 1) su += __shfl_xor_sync(~0u, su, o);
        if (lane < Tt) d_att_t[w * Tt + lane] = e / su;
    }
}

// ---------------- apply temporal attention -> bufA ----------------
__global__ void k_apply_t() {
    int warp = (blockIdx.x * blockDim.x + threadIdx.x) >> 5;
    int lane = threadIdx.x & 31;
    if (warp >= BCN) return;
    int b = warp / (Cc * Nn);
    long row = (long)warp * Tt;
    float hv = (lane < Tt) ? d_h[row + lane] : 0.f;
    float acc = 0.f;
    const float* arow = d_att_t + (b * Tt + (lane < Tt ? lane : 0)) * Tt;
    #pragma unroll
    for (int s = 0; s < Tt; s++) {
        float hs = __shfl_sync(~0u, hv, s);
        acc += arow[s] * hs;
    }
    if (lane < Tt) d_bufA[row + lane] = acc;
}

// ---------------- big fused kernel: conv4res | cmix | gres (task = blockIdx.x for L2 reuse) ----------------
__global__ void __launch_bounds__(256, 2)
k_big(const float* __restrict__ resW, const float* __restrict__ resb,
      const float* __restrict__ ccb, const float* __restrict__ x,
      float* __restrict__ out) {
    int b = blockIdx.z;
    int yy = blockIdx.x;                     // task varies fastest -> same p-range L2 hot
    int p0 = blockIdx.y * 1024 + threadIdx.x * 4;
    __shared__ __align__(16) float sm[5 * Cc * 16];

    if (yy < 4) {
        int og = yy;
        float (*Ws)[Cc][16] = (float(*)[Cc][16])sm;
        float (*Rs)[16] = (float(*)[16])(sm + 4 * Cc * 16);
        for (int i = threadIdx.x; i < 16 * Cc; i += 256) {
            int o = i & 15, c = i >> 4;
            #pragma unroll
            for (int k = 0; k < 4; k++)
                Ws[k][c][o] = d_Wc[k * O3 * Cc + (og * 16 + o) * Cc + c];
            Rs[c][o] = resW[(64 + og * 16 + o) * Cc + c];
        }
        __syncthreads();
        if (p0 >= NT) return;
        int t0 = p0 % Tt;
        const float* Zb = d_bufA + (long)b * Cc * NT + p0;
        const float* xb = x + (long)b * Cc * NT + p0;
        u64 acc2[8][4] = {};
        auto cstep = [&](float4 cur, float4 prv, float4 xv, int c) {
            u64 z0 = pk2(prv.y), z1 = pk2(prv.z), z2 = pk2(prv.w);
            u64 z3 = pk2(cur.x), z4 = pk2(cur.y), z5 = pk2(cur.z), z6 = pk2(cur.w);
            u64 xr0 = pk2(xv.x), xr1 = pk2(xv.y), xr2 = pk2(xv.z), xr3 = pk2(xv.w);
            const u64* W0r = (const u64*)Ws[0][c];
            const u64* W1r = (const u64*)Ws[1][c];
            const u64* W2r = (const u64*)Ws[2][c];
            const u64* W3r = (const u64*)Ws[3][c];
            const u64* Rr  = (const u64*)Rs[c];
            #pragma unroll
            for (int o2 = 0; o2 < 8; o2++) {
                u64 w0 = W0r[o2], w1 = W1r[o2], w2 = W2r[o2], w3 = W3r[o2], ar = Rr[o2];
                fma2(acc2[o2][0], w0, z3); fma2(acc2[o2][0], w1, z2);
                fma2(acc2[o2][0], w2, z1); fma2(acc2[o2][0], w3, z0);
                fma2(acc2[o2][0], ar, xr0);
                fma2(acc2[o2][1], w0, z4); fma2(acc2[o2][1], w1, z3);
                fma2(acc2[o2][1], w2, z2); fma2(acc2[o2][1], w3, z1);
                fma2(acc2[o2][1], ar, xr1);
                fma2(acc2[o2][2], w0, z5); fma2(acc2[o2][2], w1, z4);
                fma2(acc2[o2][2], w2, z3); fma2(acc2[o2][2], w3, z2);
                fma2(acc2[o2][2], ar, xr2);
                fma2(acc2[o2][3], w0, z6); fma2(acc2[o2][3], w1, z5);
                fma2(acc2[o2][3], w2, z4); fma2(acc2[o2][3], w3, z3);
                fma2(acc2[o2][3], ar, xr3);
            }
        };
        float4 zero4 = make_float4(0.f, 0.f, 0.f, 0.f);
        bool hasPrev = (t0 > 0);
        for (int c = 0; c < Cc; c += 2) {
            const float* Zc0 = Zb + (long)(c)     * NT;
            const float* Zc1 = Zb + (long)(c + 1) * NT;
            float4 cur0 = *(const float4*)Zc0;
            float4 cur1 = *(const float4*)Zc1;
            float4 prv0 = hasPrev ? *(const float4*)(Zc0 - 4) : zero4;
            float4 prv1 = hasPrev ? *(const float4*)(Zc1 - 4) : zero4;
            float4 xv0 = *(const float4*)(xb + (long)(c)     * NT);
            float4 xv1 = *(const float4*)(xb + (long)(c + 1) * NT);
            cstep(cur0, prv0, xv0, c);
            cstep(cur1, prv1, xv1, c + 1);
        }
        #pragma unroll
        for (int o2 = 0; o2 < 8; o2++) {
            float2 v0 = unpk(acc2[o2][0]), v1 = unpk(acc2[o2][1]);
            float2 v2 = unpk(acc2[o2][2]), v3 = unpk(acc2[o2][3]);
            #pragma unroll
            for (int par = 0; par < 2; par++) {
                int o = og * 16 + o2 * 2 + par;
                float4 v = par ? make_float4(v0.y, v1.y, v2.y, v3.y)
                               : make_float4(v0.x, v1.x, v2.x, v3.x);
                float rb  = resb[64 + o];
                float bhi = d_bhi[o] + rb;
                float blo = d_blo[o] + rb;
                float ba = (t0 == 0) ? blo : bhi;
                v.x = fmaxf(v.x + ba,  0.f); v.y = fmaxf(v.y + ba,  0.f);
                v.z = fmaxf(v.z + bhi, 0.f); v.w = fmaxf(v.w + bhi, 0.f);
                *(float4*)(out + ((long)b * CO + 64 + o) * NT + p0) = v;
            }
        }
    } else {
        int og = yy & 3;
        bool isC = yy < 8;
        float (*As)[16] = (float(*)[16])sm;
        float (*Rs)[16] = (float(*)[16])(sm + Cc * 16);
        const float* Mb = d_M + (long)b * O3 * Cc;
        for (int i = threadIdx.x; i < 16 * Cc; i += 256) {
            int o = i & 15, c = i >> 4;
            if (isC) {
                As[c][o] = Mb[(og * 16 + o) * Cc + c];
                Rs[c][o] = resW[(og * 16 + o) * Cc + c];
            } else {
                As[c][o] = resW[(128 + og * 16 + o) * Cc + c];
            }
        }
        __syncthreads();
        if (p0 >= NT) return;
        const float* Hb = d_h + (long)b * Cc * NT + p0;
        const float* xb = x + (long)b * Cc * NT + p0;
        u64 acc2[8][4] = {};
        if (isC) {
            auto mstep = [&](float4 hv, float4 xv, int c) {
                u64 hp0 = pk2(hv.x), hp1 = pk2(hv.y), hp2 = pk2(hv.z), hp3 = pk2(hv.w);
                u64 xp0 = pk2(xv.x), xp1 = pk2(xv.y), xp2 = pk2(xv.z), xp3 = pk2(xv.w);
                const u64* Mr = (const u64*)As[c];
                const u64* Rr = (const u64*)Rs[c];
                #pragma unroll
                for (int o2 = 0; o2 < 8; o2++) {
                    u64 am = Mr[o2], ar = Rr[o2];
                    fma2(acc2[o2][0], am, hp0); fma2(acc2[o2][0], ar, xp0);
                    fma2(acc2[o2][1], am, hp1); fma2(acc2[o2][1], ar, xp1);
                    fma2(acc2[o2][2], am, hp2); fma2(acc2[o2][2], ar, xp2);
                    fma2(acc2[o2][3], am, hp3); fma2(acc2[o2][3], ar, xp3);
                }
            };
            for (int c = 0; c < Cc; c += 2) {
                float4 h0 = *(const float4*)(Hb + (long)(c)     * NT);
                float4 h1 = *(const float4*)(Hb + (long)(c + 1) * NT);
                float4 x0 = *(const float4*)(xb + (long)(c)     * NT);
                float4 x1 = *(const float4*)(xb + (long)(c + 1) * NT);
                mstep(h0, x0, c);
                mstep(h1, x1, c + 1);
            }
        } else {
            auto gstep = [&](float4 xv, int c) {
                u64 xp0 = pk2(xv.x), xp1 = pk2(xv.y), xp2 = pk2(xv.z), xp3 = pk2(xv.w);
                const u64* Ar = (const u64*)As[c];
                #pragma unroll
                for (int o2 = 0; o2 < 8; o2++) {
                    u64 a2 = Ar[o2];
                    fma2(acc2[o2][0], a2, xp0);
                    fma2(acc2[o2][1], a2, xp1);
                    fma2(acc2[o2][2], a2, xp2);
                    fma2(acc2[o2][3], a2, xp3);
                }
            };
            for (int c = 0; c < Cc; c += 4) {
                float4 x0 = *(const float4*)(xb + (long)(c)     * NT);
                float4 x1 = *(const float4*)(xb + (long)(c + 1) * NT);
                float4 x2 = *(const float4*)(xb + (long)(c + 2) * NT);
                float4 x3 = *(const float4*)(xb + (long)(c + 3) * NT);
                gstep(x0, c); gstep(x1, c + 1); gstep(x2, c + 2); gstep(x3, c + 3);
            }
        }
        #pragma unroll
        for (int o2 = 0; o2 < 8; o2++) {
            float2 v0 = unpk(acc2[o2][0]), v1 = unpk(acc2[o2][1]);
            float2 v2 = unpk(acc2[o2][2]), v3 = unpk(acc2[o2][3]);
            #pragma unroll
            for (int par = 0; par < 2; par++) {
                int o = og * 16 + o2 * 2 + par;
                float4 v = par ? make_float4(v0.y, v1.y, v2.y, v3.y)
                               : make_float4(v0.x, v1.x, v2.x, v3.x);
                if (isC) {
                    float bb = ccb[o] + resb[o];
                    v.x = fmaxf(v.x + bb, 0.f); v.y = fmaxf(v.y + bb, 0.f);
                    v.z = fmaxf(v.z + bb, 0.f); v.w = fmaxf(v.w + bb, 0.f);
                    *(float4*)(out + ((long)b * CO + o) * NT + p0) = v;
                } else {
                    float bb = resb[128 + o];
                    v.x += bb; v.y += bb; v.z += bb; v.w += bb;
                    *(float4*)(out + ((long)b * CO + 128 + o) * NT + p0) = v;
                }
            }
        }
    }
}

// ---------------- graph apply: tf32 tensor-core GEMM (3xTF32) + residual + relu ----------------
// Per b: D[n, q] = att[n, m] @ gh[m, q]. Block tile M=64(n) x N=128(q), K-tile 16.
// 8 warps: wm = wid&3 (16 n), wn = wid>>2 (64 q). Warp tile 16x64 = 8 mma(16x8) tiles.
__global__ void __launch_bounds__(256, 2) k_gapply(float* __restrict__ out) {
    int b = blockIdx.z;
    int q0 = blockIdx.x * 128;
    int n0 = blockIdx.y * 64;
    int tid = threadIdx.x;
    int wid = tid >> 5, lane = tid & 31;
    int wm = wid & 3, wn = wid >> 2;
    int g = lane >> 2, t4 = lane & 3;

    __shared__ __align__(16) float Ah[64][20], Al[64][20];      // pad 20: conflict-free
    __shared__ __align__(16) float Gh[16][136], Gl[16][136];    // pad 136: conflict-free

    float d[8][4];
    #pragma unroll
    for (int i = 0; i < 8; i++)
        #pragma unroll
        for (int j = 0; j < 4; j++) d[i][j] = 0.f;

    const float* Ab = d_att_g + (long)b * Nn * Nn;
    const float* Gb = d_gh + (long)b * Nn * QW;

    for (int kt = 0; kt < 20; kt++) {            // 20*16 = 320 >= 307 (zero pad)
        int k0 = kt * 16;
        __syncthreads();
        #pragma unroll
        for (int i = tid; i < 1024; i += 256) {  // A tile 64x16
            int row = i >> 4, kk = i & 15;
            float v = 0.f;
            int n = n0 + row, m = k0 + kk;
            if (n < Nn && m < Nn) v = Ab[(long)n * Nn + m];
            float hf, lf; tf32_split(v, hf, lf);
            Ah[row][kk] = hf; Al[row][kk] = lf;
        }
        #pragma unroll
        for (int i = tid; i < 2048; i += 256) {  // G tile 16x128
            int kk = i >> 7, col = i & 127;
            float v = 0.f;
            int m = k0 + kk;
            if (m < Nn) v = Gb[(long)m * QW + q0 + col];
            float hf, lf; tf32_split(v, hf, lf);
            Gh[kk][col] = hf; Gl[kk][col] = lf;
        }
        __syncthreads();
        #pragma unroll
        for (int ks = 0; ks < 2; ks++) {
            int kb = ks * 8;
            int r0 = wm * 16 + g, r1 = r0 + 8;
            unsigned ah0 = __float_as_uint(Ah[r0][kb + t4]);
            unsigned ah1 = __float_as_uint(Ah[r1][kb + t4]);
            unsigned ah2 = __float_as_uint(Ah[r0][kb + t4 + 4]);
            unsigned ah3 = __float_as_uint(Ah[r1][kb + t4 + 4]);
            unsigned al0 = __float_as_uint(Al[r0][kb + t4]);
            unsigned al1 = __float_as_uint(Al[r1][kb + t4]);
            unsigned al2 = __float_as_uint(Al[r0][kb + t4 + 4]);
            unsigned al3 = __float_as_uint(Al[r1][kb + t4 + 4]);
            #pragma unroll
            for (int tile = 0; tile < 8; tile++) {
                int qc = wn * 64 + tile * 8 + g;
                unsigned bh0 = __float_as_uint(Gh[kb + t4][qc]);
                unsigned bh1 = __float_as_uint(Gh[kb + t4 + 4][qc]);
                unsigned bl0 = __float_as_uint(Gl[kb + t4][qc]);
                unsigned bl1 = __float_as_uint(Gl[kb + t4 + 4][qc]);
                mma_tf32(d[tile], ah0, ah1, ah2, ah3, bh0, bh1);   // hi*hi
                mma_tf32(d[tile], al0, al1, al2, al3, bh0, bh1);   // lo*hi
                mma_tf32(d[tile], ah0, ah1, ah2, ah3, bl0, bl1);   // hi*lo
            }
        }
    }
    // epilogue: D row g / g+8, cols 2*t4, 2*t4+1 within each 16x8 tile
    #pragma unroll
    for (int tile = 0; tile < 8; tile++) {
        int q = q0 + wn * 64 + tile * 8 + 2 * t4;
        int ch = q / Tt, tt = q % Tt;            // pair never crosses ch (8 | 24)
        #pragma unroll
        for (int half = 0; half < 2; half++) {
            int n = n0 + wm * 16 + g + half * 8;
            if (n >= Nn) continue;
            long base = ((long)b * CO + 128 + ch) * NT + (long)n * Tt + tt;
            float2 r = *(const float2*)(out + base);
            float2 w;
            w.x = fmaxf(d[tile][half * 2 + 0] + r.x, 0.f);
            w.y = fmaxf(d[tile][half * 2 + 1] + r.y, 0.f);
            *(float2*)(out + base) = w;
        }
    }
}

// ================================= launch =================================
extern "C" void kernel_launch(void* const* d_in, const int* in_sizes, int n_in,
                              void* d_out, int out_size) {
    const float* x     = (const float*)d_in[0];
    const int*   adj   = (const int*)  d_in[1];
    const float* ln_g  = (const float*)d_in[2];
    const float* ln_b  = (const float*)d_in[3];
    const float* res_W = (const float*)d_in[4];
    const float* res_b = (const float*)d_in[5];
    const float* ca_W1 = (const float*)d_in[6];
    const float* ca_W2 = (const float*)d_in[7];
    const float* ca_W3 = (const float*)d_in[8];
    const float* cc_W  = (const float*)d_in[9];
    const float* cc_b  = (const float*)d_in[10];
    const float* ta_W1 = (const float*)d_in[11];
    const float* ta_W2 = (const float*)d_in[12];
    const float* ta_W3 = (const float*)d_in[13];
    const float* tc_W0 = (const float*)d_in[14];
    const float* tc_b0 = (const float*)d_in[15];
    const float* tc_W1 = (const float*)d_in[16];
    const float* tc_b1 = (const float*)d_in[17];
    const float* ga_W1 = (const float*)d_in[18];
    const float* ga_W2 = (const float*)d_in[19];
    const float* ga_W3 = (const float*)d_in[20];
    const float* g_W   = (const float*)d_in[21];
    float* out = (float*)d_out;

    int warpBlocks = (BCN + 7) / 8;

    // 1) LayerNorm + T-dots + conv weight combine (tail blocks)
    k_lnw<<<warpBlocks + 65, 256>>>(x, ln_g, ln_b, ca_W1, ga_W1,
                                    tc_W0, tc_b0, tc_W1, tc_b1, warpBlocks);
    // 2) gh = g_W @ h
    k_mixgh<<<dim3(8, 4, Bz), 256>>>(g_W);
    // 3) glue reductions
    k_stage1<<<dim3(921, 4), 256>>>(ca_W3, ta_W1, ta_W3, ga_W3, ca_W2, ga_W2);
    // 4) scoreG | lhs_t | att_c
    k_merged2<<<dim3(921, 3), 256>>>(ta_W2);
    // 5) softg | k_M | att_t
    k_merged3<<<dim3(Bz * Nn, 3), 256>>>(adj, cc_W);
    // 6) temporal attention apply -> bufA
    k_apply_t<<<warpBlocks, 256>>>();
    // 7) fused: conv4res | cmix | G-residual (task-major grid for L2 reuse)
    k_big<<<dim3(12, 8, Bz), 256>>>(res_W, res_b, cc_b, x, out);
    // 8) graph apply (tf32 mma, 3xTF32) + add + relu
    k_gapply<<<dim3(12, 5, Bz), 256>>>(out);

    (void)in_sizes; (void)n_in; (void)out_size;
}